// round 1
// baseline (speedup 1.0000x reference)
#include <cuda_runtime.h>
#include <cuda_bf16.h>
#include <math_constants.h>

// Problem constants
#define BB 4
#define NN 1024
#define DD 512
#define HH 8
#define HD 64
#define NSP 32
#define NTMP 16

// Scratch (device globals; no allocations allowed)
__device__ float g_q[BB * HH * NN * HD];   // (b,h,n,d)
__device__ float g_k[BB * HH * NN * HD];
__device__ float g_v[BB * HH * NN * HD];
__device__ float g_y[BB * NN * DD];        // (b,n,h*HD+d)
__device__ float g_mask[BB * NN * NN];     // mask + exp(-0.1*full_dist)
__device__ short g_idx[BB * NN * NN];      // bias table row index
__device__ float g_sbins[NSP];

// ---------------------------------------------------------------------------
// Fill spatial bins: exp(linspace(0, log(257), 32))
// ---------------------------------------------------------------------------
__global__ void init_bins_kernel() {
    int i = threadIdx.x;
    if (i < NSP) {
        double L = log(257.0);
        g_sbins[i] = (float)exp((double)i * (L / 31.0));
    }
}

// ---------------------------------------------------------------------------
// GEMM: C[m,o] = sum_k A[m,k] * W[o,k] + bias[o]
// mode 0: C row-major (M x O) ; mode 1: scatter to (b,h,n,d) layout
// Block: 64x64 output tile, 256 threads, 4x4 microtile, BK=16
// ---------------------------------------------------------------------------
__global__ void gemm_bias_kernel(const float* __restrict__ A,
                                 const float* __restrict__ W,
                                 const float* __restrict__ bias,
                                 float* __restrict__ C,
                                 int M, int K, int O, int mode) {
    __shared__ float As[16][64];
    __shared__ float Ws[16][64];

    int tid = threadIdx.x;
    int tx = tid & 15;        // 0..15  (output cols / 4)
    int ty = tid >> 4;        // 0..15  (output rows / 4)
    int row0 = blockIdx.y * 64;
    int col0 = blockIdx.x * 64;

    int lm  = tid >> 2;       // 0..63 row within tile for loading
    int lk4 = tid & 3;        // float4 index along k

    float acc[4][4];
#pragma unroll
    for (int i = 0; i < 4; i++)
#pragma unroll
        for (int j = 0; j < 4; j++) acc[i][j] = 0.0f;

    for (int k0 = 0; k0 < K; k0 += 16) {
        float4 a4 = *(const float4*)&A[(size_t)(row0 + lm) * K + k0 + lk4 * 4];
        float4 w4 = *(const float4*)&W[(size_t)(col0 + lm) * K + k0 + lk4 * 4];
        As[lk4 * 4 + 0][lm] = a4.x;
        As[lk4 * 4 + 1][lm] = a4.y;
        As[lk4 * 4 + 2][lm] = a4.z;
        As[lk4 * 4 + 3][lm] = a4.w;
        Ws[lk4 * 4 + 0][lm] = w4.x;
        Ws[lk4 * 4 + 1][lm] = w4.y;
        Ws[lk4 * 4 + 2][lm] = w4.z;
        Ws[lk4 * 4 + 3][lm] = w4.w;
        __syncthreads();

#pragma unroll
        for (int kk = 0; kk < 16; kk++) {
            float4 av = *(const float4*)&As[kk][ty * 4];
            float4 wv = *(const float4*)&Ws[kk][tx * 4];
            float a[4] = {av.x, av.y, av.z, av.w};
            float w[4] = {wv.x, wv.y, wv.z, wv.w};
#pragma unroll
            for (int i = 0; i < 4; i++)
#pragma unroll
                for (int j = 0; j < 4; j++) acc[i][j] += a[i] * w[j];
        }
        __syncthreads();
    }

#pragma unroll
    for (int i = 0; i < 4; i++) {
        int m = row0 + ty * 4 + i;
#pragma unroll
        for (int j = 0; j < 4; j++) {
            int o = col0 + tx * 4 + j;
            float val = acc[i][j] + bias[o];
            if (mode == 0) {
                C[(size_t)m * O + o] = val;
            } else {
                int b = m >> 10, n = m & (NN - 1);
                int h = o >> 6, d = o & (HD - 1);
                C[((((size_t)b * HH + h) * NN) + n) * HD + d] = val;
            }
        }
    }
}

// ---------------------------------------------------------------------------
// Precompute per-pair bias-table index + mask value
// ---------------------------------------------------------------------------
__global__ void precompute_kernel(const float* __restrict__ coords) {
    int gid = blockIdx.x * 256 + threadIdx.x;   // 0 .. B*N*N-1 (4M)
    int b = gid >> 20;
    int rem = gid & ((1 << 20) - 1);
    int i = rem >> 10;
    int j = rem & 1023;

    const float* ci = coords + ((size_t)b * NN + i) * 3;
    const float* cj = coords + ((size_t)b * NN + j) * 3;
    float ti = ci[0], yi = ci[1], xi = ci[2];
    float tj = cj[0], yj = cj[1], xj = cj[2];

    float dy = yi - yj, dx = xi - xj, dt = ti - tj;
    float sp2 = dy * dy + dx * dx;
    float sd = sqrtf(fmaxf(sp2, 0.0f));
    float fd = sqrtf(fmaxf(dt * dt + dy * dy + dx * dx, 0.0f));

    // spatial searchsorted 'left': count of bins strictly < sd, clipped to 31
    int c = 0;
#pragma unroll
    for (int s = 0; s < NSP; s++) c += (g_sbins[s] < sd) ? 1 : 0;
    int sidx = min(c, NSP - 1);

    // temporal bins are exact integers -16..16; searchsorted left = ceil(td+16)
    int tc = (int)ceilf(dt + 16.0f);
    tc = max(0, min(2 * NTMP, tc));

    g_idx[gid]  = (short)(sidx + tc * NSP);
    g_mask[gid] = (sd > 256.0f ? -1000.0f : 0.0f) + expf(-0.1f * fd);
}

// ---------------------------------------------------------------------------
// Flash-style attention (fp32 SIMT).
// grid: (N/64, B*H). block: 256 threads.
// Each thread: row r = tid/4, quarter sub = tid%4 -> 16 score cols + 16 out dims.
// ---------------------------------------------------------------------------
#define AT_STRIDE 68   // 64 + 4 pad (float4-aligned, conflict-avoiding)
#define SMEM_ATTN (4 * 64 * AT_STRIDE * sizeof(float))

__global__ void attn_kernel(const float* __restrict__ bias_table) {
    extern __shared__ float sh[];
    float* qs = sh;
    float* ks = qs + 64 * AT_STRIDE;
    float* vs = ks + 64 * AT_STRIDE;
    float* ps = vs + 64 * AT_STRIDE;

    int bh = blockIdx.y;              // 0..31
    int b = bh >> 3, h = bh & 7;
    int i0 = blockIdx.x * 64;
    int tid = threadIdx.x;
    int r = tid >> 2;                 // 0..63 query row within tile
    int sub = tid & 3;                // 0..3

    const float* qbase = g_q + ((size_t)bh * NN + i0) * HD;
    for (int f4 = tid; f4 < 1024; f4 += 256) {
        int row = f4 >> 4, d4 = f4 & 15;
        *(float4*)&qs[row * AT_STRIDE + d4 * 4] = ((const float4*)qbase)[f4];
    }

    float acc[16];
#pragma unroll
    for (int z = 0; z < 16; z++) acc[z] = 0.0f;
    float m_prev = -CUDART_INF_F;
    float l = 0.0f;

    const size_t maskrow = ((size_t)b * NN + (i0 + r)) * NN;

    for (int jt = 0; jt < NN / 64; jt++) {
        int j0 = jt * 64;
        const float* kbase = g_k + ((size_t)bh * NN + j0) * HD;
        const float* vbase = g_v + ((size_t)bh * NN + j0) * HD;
        __syncthreads();   // protect ks/vs from previous iteration's PV readers
        for (int f4 = tid; f4 < 1024; f4 += 256) {
            int row = f4 >> 4, d4 = f4 & 15;
            *(float4*)&ks[row * AT_STRIDE + d4 * 4] = ((const float4*)kbase)[f4];
            *(float4*)&vs[row * AT_STRIDE + d4 * 4] = ((const float4*)vbase)[f4];
        }
        __syncthreads();

        // scores: 16 columns per thread (j = sub + 4*jj)
        float s[16];
        const float4* qrow = (const float4*)&qs[r * AT_STRIDE];
#pragma unroll
        for (int jj = 0; jj < 16; jj++) {
            int j = sub + 4 * jj;
            const float4* krow = (const float4*)&ks[j * AT_STRIDE];
            float dot = 0.0f;
#pragma unroll
            for (int d4 = 0; d4 < 16; d4++) {
                float4 a = qrow[d4];
                float4 k4 = krow[d4];
                dot += a.x * k4.x + a.y * k4.y + a.z * k4.z + a.w * k4.w;
            }
            int gj = j0 + j;
            int bi = (int)g_idx[maskrow + gj];
            float mv = g_mask[maskrow + gj];
            s[jj] = dot * 0.125f + __ldg(&bias_table[bi * HH + h]) + mv;
        }

        // online softmax (row state replicated across the 4 sub-threads)
        float tmax = s[0];
#pragma unroll
        for (int jj = 1; jj < 16; jj++) tmax = fmaxf(tmax, s[jj]);
        tmax = fmaxf(tmax, __shfl_xor_sync(0xffffffffu, tmax, 1));
        tmax = fmaxf(tmax, __shfl_xor_sync(0xffffffffu, tmax, 2));
        float new_m = fmaxf(m_prev, tmax);
        float scale = expf(m_prev - new_m);

        float tsum = 0.0f;
#pragma unroll
        for (int jj = 0; jj < 16; jj++) {
            float p = expf(s[jj] - new_m);
            tsum += p;
            ps[r * AT_STRIDE + sub + 4 * jj] = p;
        }
        tsum += __shfl_xor_sync(0xffffffffu, tsum, 1);
        tsum += __shfl_xor_sync(0xffffffffu, tsum, 2);

        l = l * scale + tsum;
        m_prev = new_m;
#pragma unroll
        for (int z = 0; z < 16; z++) acc[z] *= scale;
        __syncthreads();

        // PV: acc[d] += sum_j p[r][j] * v[j][d], d = sub*16 .. sub*16+15
#pragma unroll 8
        for (int j = 0; j < 64; j++) {
            float p = ps[r * AT_STRIDE + j];
            const float4* vrow = (const float4*)&vs[j * AT_STRIDE + sub * 16];
#pragma unroll
            for (int z4 = 0; z4 < 4; z4++) {
                float4 v4 = vrow[z4];
                acc[z4 * 4 + 0] += p * v4.x;
                acc[z4 * 4 + 1] += p * v4.y;
                acc[z4 * 4 + 2] += p * v4.z;
                acc[z4 * 4 + 3] += p * v4.w;
            }
        }
    }

    float inv = 1.0f / l;
    float* yrow = g_y + ((size_t)b * NN + i0 + r) * DD + h * HD + sub * 16;
#pragma unroll
    for (int z = 0; z < 16; z++) yrow[z] = acc[z] * inv;
}

// ---------------------------------------------------------------------------
// Host launch
// ---------------------------------------------------------------------------
extern "C" void kernel_launch(void* const* d_in, const int* in_sizes, int n_in,
                              void* d_out, int out_size) {
    const float* query = (const float*)d_in[0];
    const float* key   = (const float*)d_in[1];
    const float* value = (const float*)d_in[2];
    const float* coords = (const float*)d_in[3];
    const float* Wq = (const float*)d_in[4];
    const float* bq = (const float*)d_in[5];
    const float* Wk = (const float*)d_in[6];
    const float* bk = (const float*)d_in[7];
    const float* Wv = (const float*)d_in[8];
    const float* bv = (const float*)d_in[9];
    const float* Wo = (const float*)d_in[10];
    const float* bo = (const float*)d_in[11];
    const float* bias_table = (const float*)d_in[12];
    float* out = (float*)d_out;

    float *gq, *gk, *gv, *gy;
    cudaGetSymbolAddress((void**)&gq, g_q);
    cudaGetSymbolAddress((void**)&gk, g_k);
    cudaGetSymbolAddress((void**)&gv, g_v);
    cudaGetSymbolAddress((void**)&gy, g_y);

    cudaFuncSetAttribute(attn_kernel, cudaFuncAttributeMaxDynamicSharedMemorySize,
                         (int)SMEM_ATTN);

    const int M = BB * NN;   // 4096
    dim3 gemm_grid(DD / 64, M / 64);

    init_bins_kernel<<<1, 32>>>();
    gemm_bias_kernel<<<gemm_grid, 256>>>(query, Wq, bq, gq, M, DD, DD, 1);
    gemm_bias_kernel<<<gemm_grid, 256>>>(key,   Wk, bk, gk, M, DD, DD, 1);
    gemm_bias_kernel<<<gemm_grid, 256>>>(value, Wv, bv, gv, M, DD, DD, 1);
    precompute_kernel<<<(BB * NN * NN) / 256, 256>>>(coords);
    attn_kernel<<<dim3(NN / 64, BB * HH), 256, SMEM_ATTN>>>(bias_table);
    gemm_bias_kernel<<<gemm_grid, 256>>>(gy, Wo, bo, out, M, DD, DD, 0);
}

// round 5
// speedup vs baseline: 2.1941x; 2.1941x over previous
#include <cuda_runtime.h>
#include <cuda_bf16.h>
#include <math_constants.h>

// Problem constants
#define BB 4
#define NN 1024
#define DD 512
#define HH 8
#define HD 64
#define NSP 32
#define NTMP 16

// Scratch (device globals; no allocations allowed)
__device__ float g_q[BB * HH * NN * HD];   // (b,h,n,d)
__device__ float g_k[BB * HH * NN * HD];
__device__ float g_v[BB * HH * NN * HD];
__device__ float g_y[BB * NN * DD];        // (b,n,h*HD+d)
__device__ float g_mask[BB * NN * NN];     // mask + exp(-0.1*full_dist)
__device__ short g_idx[BB * NN * NN];      // bias table row index
__device__ float g_sbins[NSP];

// ---------------------------------------------------------------------------
// mma.sync m16n8k8 tf32 wrapper (in-place accumulate) + 3xTF32 split helpers
// ---------------------------------------------------------------------------
__device__ __forceinline__ void mma_tf32(float* d,
                                         unsigned a0, unsigned a1, unsigned a2, unsigned a3,
                                         unsigned b0, unsigned b1) {
    asm volatile(
        "mma.sync.aligned.m16n8k8.row.col.f32.tf32.tf32.f32 "
        "{%0,%1,%2,%3}, {%4,%5,%6,%7}, {%8,%9}, {%0,%1,%2,%3};\n"
        : "+f"(d[0]), "+f"(d[1]), "+f"(d[2]), "+f"(d[3])
        : "r"(a0), "r"(a1), "r"(a2), "r"(a3), "r"(b0), "r"(b1));
}

__device__ __forceinline__ unsigned f2tf(float x) {
    unsigned r;
    asm("cvt.rna.tf32.f32 %0, %1;" : "=r"(r) : "f"(x));
    return r;
}
__device__ __forceinline__ void split_tf32(float x, unsigned& hi, unsigned& lo) {
    hi = f2tf(x);
    lo = f2tf(x - __uint_as_float(hi));
}

// 3xTF32: D += A*B with hi/lo compensation
__device__ __forceinline__ void mma3(float* d,
                                     const unsigned* ah, const unsigned* al,
                                     unsigned bh0, unsigned bh1,
                                     unsigned bl0, unsigned bl1) {
    mma_tf32(d, ah[0], ah[1], ah[2], ah[3], bh0, bh1);
    mma_tf32(d, ah[0], ah[1], ah[2], ah[3], bl0, bl1);
    mma_tf32(d, al[0], al[1], al[2], al[3], bh0, bh1);
}

// ---------------------------------------------------------------------------
// Fill spatial bins: exp(linspace(0, log(257), 32))
// ---------------------------------------------------------------------------
__global__ void init_bins_kernel() {
    int i = threadIdx.x;
    if (i < NSP) {
        double L = log(257.0);
        g_sbins[i] = (float)exp((double)i * (L / 31.0));
    }
}

// ---------------------------------------------------------------------------
// 3xTF32 GEMM: C[m,o] = sum_k A[m,k] * W[o,k] + bias[o]
// mode 0: C row-major (M x O) ; mode 1: scatter to (b,h,n,d) layout
// Tile 128x128, BK=32, 256 threads (8 warps, warp grid 4x2, warp tile 32x64)
// ---------------------------------------------------------------------------
#define GST 36

__global__ void gemm_tf32_kernel(const float* __restrict__ A,
                                 const float* __restrict__ W,
                                 const float* __restrict__ bias,
                                 float* __restrict__ C,
                                 int mode) {
    __shared__ float As[128 * GST];
    __shared__ float Bs[128 * GST];

    const int K = DD, O = DD;
    int tid = threadIdx.x;
    int lane = tid & 31;
    int wid = tid >> 5;
    int warp_m = wid & 3;       // 0..3 -> 32 rows each
    int warp_n = wid >> 2;      // 0..1 -> 64 cols each
    int row0 = blockIdx.y * 128;
    int col0 = blockIdx.x * 128;
    int lg = lane >> 2;         // groupID 0..7
    int lt = lane & 3;          // thread-in-group

    float acc[2][8][4];
#pragma unroll
    for (int mf = 0; mf < 2; mf++)
#pragma unroll
        for (int nf = 0; nf < 8; nf++)
#pragma unroll
            for (int z = 0; z < 4; z++) acc[mf][nf][z] = 0.0f;

    for (int k0 = 0; k0 < K; k0 += 32) {
#pragma unroll
        for (int i = 0; i < 4; i++) {
            int f = tid + 256 * i;      // 0..1023
            int r = f >> 3, c4 = f & 7;
            float4 a4 = *(const float4*)&A[(size_t)(row0 + r) * K + k0 + c4 * 4];
            float4 w4 = *(const float4*)&W[(size_t)(col0 + r) * K + k0 + c4 * 4];
            *(float4*)&As[r * GST + c4 * 4] = a4;
            *(float4*)&Bs[r * GST + c4 * 4] = w4;
        }
        __syncthreads();

#pragma unroll
        for (int kf = 0; kf < 4; kf++) {
            unsigned bh[8][2], bl[8][2];
#pragma unroll
            for (int nf = 0; nf < 8; nf++) {
                int o = warp_n * 64 + nf * 8 + lg;
                split_tf32(Bs[o * GST + kf * 8 + lt],     bh[nf][0], bl[nf][0]);
                split_tf32(Bs[o * GST + kf * 8 + lt + 4], bh[nf][1], bl[nf][1]);
            }
#pragma unroll
            for (int mf = 0; mf < 2; mf++) {
                int m = warp_m * 32 + mf * 16 + lg;
                unsigned ah[4], al[4];
                split_tf32(As[m * GST + kf * 8 + lt],           ah[0], al[0]);
                split_tf32(As[(m + 8) * GST + kf * 8 + lt],     ah[1], al[1]);
                split_tf32(As[m * GST + kf * 8 + lt + 4],       ah[2], al[2]);
                split_tf32(As[(m + 8) * GST + kf * 8 + lt + 4], ah[3], al[3]);
#pragma unroll
                for (int nf = 0; nf < 8; nf++)
                    mma3(acc[mf][nf], ah, al,
                         bh[nf][0], bh[nf][1], bl[nf][0], bl[nf][1]);
            }
        }
        __syncthreads();
    }

    // Epilogue
#pragma unroll
    for (int mf = 0; mf < 2; mf++) {
#pragma unroll
        for (int nf = 0; nf < 8; nf++) {
            int rr = row0 + warp_m * 32 + mf * 16 + lg;
            int cc = col0 + warp_n * 64 + nf * 8 + lt * 2;
            float b0 = bias[cc], b1 = bias[cc + 1];
#pragma unroll
            for (int half = 0; half < 2; half++) {
                int m = rr + half * 8;
                float v0 = acc[mf][nf][half * 2 + 0] + b0;
                float v1 = acc[mf][nf][half * 2 + 1] + b1;
                if (mode == 0) {
                    *(float2*)&C[(size_t)m * O + cc] = make_float2(v0, v1);
                } else {
                    int b = m >> 10, n = m & (NN - 1);
                    int h = cc >> 6, d = cc & (HD - 1);
                    *(float2*)&C[((((size_t)b * HH + h) * NN) + n) * HD + d] =
                        make_float2(v0, v1);
                }
            }
        }
    }
}

// ---------------------------------------------------------------------------
// Precompute per-pair bias-table index + mask value
// ---------------------------------------------------------------------------
__global__ void precompute_kernel(const float* __restrict__ coords) {
    int gid = blockIdx.x * 256 + threadIdx.x;   // 0 .. B*N*N-1 (4M)
    int b = gid >> 20;
    int rem = gid & ((1 << 20) - 1);
    int i = rem >> 10;
    int j = rem & 1023;

    const float* ci = coords + ((size_t)b * NN + i) * 3;
    const float* cj = coords + ((size_t)b * NN + j) * 3;
    float ti = ci[0], yi = ci[1], xi = ci[2];
    float tj = cj[0], yj = cj[1], xj = cj[2];

    float dy = yi - yj, dx = xi - xj, dt = ti - tj;
    float sp2 = dy * dy + dx * dx;
    float sd = sqrtf(fmaxf(sp2, 0.0f));
    float fd = sqrtf(fmaxf(dt * dt + dy * dy + dx * dx, 0.0f));

    // spatial searchsorted 'left': count of bins strictly < sd, clipped to 31
    int c = 0;
#pragma unroll
    for (int s = 0; s < NSP; s++) c += (g_sbins[s] < sd) ? 1 : 0;
    int sidx = min(c, NSP - 1);

    // temporal bins are exact integers -16..16; searchsorted left = ceil(td+16)
    int tc = (int)ceilf(dt + 16.0f);
    tc = max(0, min(2 * NTMP, tc));

    g_idx[gid]  = (short)(sidx + tc * NSP);
    g_mask[gid] = (sd > 256.0f ? -1000.0f : 0.0f) + expf(-0.1f * fd);
}

// ---------------------------------------------------------------------------
// Flash attention with 3xTF32 mma.
// grid: (N/64, B*H). block: 128 threads (4 warps); warp w owns q rows w*16..+16
// smem: qs[64x68] ks[64x68] vs[64x72] ps[64x68]
// ---------------------------------------------------------------------------
#define QS_ST 68
#define KS_ST 68
#define VS_ST 72
#define PS_ST 68
#define SMEM_ATTN ((64 * QS_ST + 64 * KS_ST + 64 * VS_ST + 64 * PS_ST) * sizeof(float))

__global__ __launch_bounds__(128) void attn_kernel(const float* __restrict__ bias_table) {
    extern __shared__ float sh[];
    float* qs = sh;
    float* ks = qs + 64 * QS_ST;
    float* vs = ks + 64 * KS_ST;
    float* ps = vs + 64 * VS_ST;

    int bh = blockIdx.y;              // 0..31
    int b = bh >> 3, h = bh & 7;
    int i0 = blockIdx.x * 64;
    int tid = threadIdx.x;
    int lane = tid & 31;
    int w = tid >> 5;                 // warp 0..3
    int lg = lane >> 2;               // 0..7
    int lt = lane & 3;                // 0..3

    // load q tile (64 x 64) coalesced
    const float* qbase = g_q + ((size_t)bh * NN + i0) * HD;
    for (int f = tid; f < 1024; f += 128) {
        int row = f >> 4, c4 = f & 15;
        *(float4*)&qs[row * QS_ST + c4 * 4] = ((const float4*)qbase)[f];
    }
    __syncthreads();

    // q A-fragments (hi/lo split) in registers for the whole loop
    unsigned qh[8][4], ql[8][4];
    {
        int m = w * 16 + lg;
#pragma unroll
        for (int kf = 0; kf < 8; kf++) {
            split_tf32(qs[m * QS_ST + kf * 8 + lt],           qh[kf][0], ql[kf][0]);
            split_tf32(qs[(m + 8) * QS_ST + kf * 8 + lt],     qh[kf][1], ql[kf][1]);
            split_tf32(qs[m * QS_ST + kf * 8 + lt + 4],       qh[kf][2], ql[kf][2]);
            split_tf32(qs[(m + 8) * QS_ST + kf * 8 + lt + 4], qh[kf][3], ql[kf][3]);
        }
    }

    float o[8][4];
#pragma unroll
    for (int nf = 0; nf < 8; nf++)
#pragma unroll
        for (int z = 0; z < 4; z++) o[nf][z] = 0.0f;
    float m0 = -CUDART_INF_F, m1 = -CUDART_INF_F;
    float l0 = 0.0f, l1 = 0.0f;

    const size_t maskrow0 = ((size_t)b * NN + (i0 + w * 16 + lg)) * NN;
    const size_t maskrow1 = maskrow0 + 8 * (size_t)NN;

    const float* kb_all = g_k + (size_t)bh * NN * HD;
    const float* vb_all = g_v + (size_t)bh * NN * HD;

    for (int jt = 0; jt < NN / 64; jt++) {
        int j0 = jt * 64;
        __syncthreads();   // protect ks/vs from previous iteration readers
        {
            const float4* kb = (const float4*)(kb_all + (size_t)j0 * HD);
            const float4* vb = (const float4*)(vb_all + (size_t)j0 * HD);
            for (int f = tid; f < 1024; f += 128) {
                int row = f >> 4, c4 = f & 15;
                *(float4*)&ks[row * KS_ST + c4 * 4] = kb[f];
                *(float4*)&vs[row * VS_ST + c4 * 4] = vb[f];
            }
        }
        __syncthreads();

        // ---- QK^T: scores s[nf][4] (rows lg, lg+8; cols nf*8 + lt*2 +{0,1})
        float s[8][4];
#pragma unroll
        for (int nf = 0; nf < 8; nf++) {
            s[nf][0] = s[nf][1] = s[nf][2] = s[nf][3] = 0.0f;
            int jr = nf * 8 + lg;
#pragma unroll
            for (int kf = 0; kf < 8; kf++) {
                unsigned bh0, bh1, bl0, bl1;
                split_tf32(ks[jr * KS_ST + kf * 8 + lt],     bh0, bl0);
                split_tf32(ks[jr * KS_ST + kf * 8 + lt + 4], bh1, bl1);
                mma3(s[nf], qh[kf], ql[kf], bh0, bh1, bl0, bl1);
            }
        }

        // ---- bias + mask
#pragma unroll
        for (int nf = 0; nf < 8; nf++) {
            int jc = j0 + nf * 8 + lt * 2;
            float2 mv0 = *(const float2*)&g_mask[maskrow0 + jc];
            float2 mv1 = *(const float2*)&g_mask[maskrow1 + jc];
            unsigned ip0 = *(const unsigned*)&g_idx[maskrow0 + jc];
            unsigned ip1 = *(const unsigned*)&g_idx[maskrow1 + jc];
            int i00 = (int)(ip0 & 0xffff), i01 = (int)(ip0 >> 16);
            int i10 = (int)(ip1 & 0xffff), i11 = (int)(ip1 >> 16);
            s[nf][0] = s[nf][0] * 0.125f + __ldg(&bias_table[i00 * HH + h]) + mv0.x;
            s[nf][1] = s[nf][1] * 0.125f + __ldg(&bias_table[i01 * HH + h]) + mv0.y;
            s[nf][2] = s[nf][2] * 0.125f + __ldg(&bias_table[i10 * HH + h]) + mv1.x;
            s[nf][3] = s[nf][3] * 0.125f + __ldg(&bias_table[i11 * HH + h]) + mv1.y;
        }

        // ---- online softmax (2 rows per thread)
        float t0 = s[0][0], t1 = s[0][2];
#pragma unroll
        for (int nf = 0; nf < 8; nf++) {
            t0 = fmaxf(t0, fmaxf(s[nf][0], s[nf][1]));
            t1 = fmaxf(t1, fmaxf(s[nf][2], s[nf][3]));
        }
        t0 = fmaxf(t0, __shfl_xor_sync(0xffffffffu, t0, 1));
        t0 = fmaxf(t0, __shfl_xor_sync(0xffffffffu, t0, 2));
        t1 = fmaxf(t1, __shfl_xor_sync(0xffffffffu, t1, 1));
        t1 = fmaxf(t1, __shfl_xor_sync(0xffffffffu, t1, 2));
        float nm0 = fmaxf(m0, t0), nm1 = fmaxf(m1, t1);
        float sc0 = __expf(m0 - nm0), sc1 = __expf(m1 - nm1);

        float sum0 = 0.0f, sum1 = 0.0f;
        int pr0 = (w * 16 + lg) * PS_ST;
        int pr1 = pr0 + 8 * PS_ST;
#pragma unroll
        for (int nf = 0; nf < 8; nf++) {
            float p0 = __expf(s[nf][0] - nm0);
            float p1 = __expf(s[nf][1] - nm0);
            float p2 = __expf(s[nf][2] - nm1);
            float p3 = __expf(s[nf][3] - nm1);
            sum0 += p0 + p1;
            sum1 += p2 + p3;
            int jl = nf * 8 + lt * 2;
            *(float2*)&ps[pr0 + jl] = make_float2(p0, p1);
            *(float2*)&ps[pr1 + jl] = make_float2(p2, p3);
        }
        sum0 += __shfl_xor_sync(0xffffffffu, sum0, 1);
        sum0 += __shfl_xor_sync(0xffffffffu, sum0, 2);
        sum1 += __shfl_xor_sync(0xffffffffu, sum1, 1);
        sum1 += __shfl_xor_sync(0xffffffffu, sum1, 2);
        l0 = l0 * sc0 + sum0;
        l1 = l1 * sc1 + sum1;
        m0 = nm0; m1 = nm1;
#pragma unroll
        for (int nf = 0; nf < 8; nf++) {
            o[nf][0] *= sc0; o[nf][1] *= sc0;
            o[nf][2] *= sc1; o[nf][3] *= sc1;
        }
        __syncwarp();

        // ---- PV: o[r][d] += sum_j p[r][j] v[j][d]  (3xTF32)
        int par = (w * 16 + lg) * PS_ST;
#pragma unroll
        for (int kf = 0; kf < 8; kf++) {
            unsigned ph[4], pl[4];
            split_tf32(ps[par + kf * 8 + lt],                 ph[0], pl[0]);
            split_tf32(ps[par + 8 * PS_ST + kf * 8 + lt],     ph[1], pl[1]);
            split_tf32(ps[par + kf * 8 + lt + 4],             ph[2], pl[2]);
            split_tf32(ps[par + 8 * PS_ST + kf * 8 + lt + 4], ph[3], pl[3]);
            int vr0 = (kf * 8 + lt) * VS_ST;
            int vr1 = (kf * 8 + lt + 4) * VS_ST;
#pragma unroll
            for (int nf = 0; nf < 8; nf++) {
                unsigned bh0, bh1, bl0, bl1;
                split_tf32(vs[vr0 + nf * 8 + lg], bh0, bl0);
                split_tf32(vs[vr1 + nf * 8 + lg], bh1, bl1);
                mma3(o[nf], ph, pl, bh0, bh1, bl0, bl1);
            }
        }
    }

    float inv0 = 1.0f / l0;
    float inv1 = 1.0f / l1;
    int r0 = i0 + w * 16 + lg;
#pragma unroll
    for (int nf = 0; nf < 8; nf++) {
        int cc = h * HD + nf * 8 + lt * 2;
        *(float2*)&g_y[(size_t)(b * NN + r0) * DD + cc] =
            make_float2(o[nf][0] * inv0, o[nf][1] * inv0);
        *(float2*)&g_y[(size_t)(b * NN + r0 + 8) * DD + cc] =
            make_float2(o[nf][2] * inv1, o[nf][3] * inv1);
    }
}

// ---------------------------------------------------------------------------
// Host launch
// ---------------------------------------------------------------------------
extern "C" void kernel_launch(void* const* d_in, const int* in_sizes, int n_in,
                              void* d_out, int out_size) {
    const float* query = (const float*)d_in[0];
    const float* key   = (const float*)d_in[1];
    const float* value = (const float*)d_in[2];
    const float* coords = (const float*)d_in[3];
    const float* Wq = (const float*)d_in[4];
    const float* bq = (const float*)d_in[5];
    const float* Wk = (const float*)d_in[6];
    const float* bk = (const float*)d_in[7];
    const float* Wv = (const float*)d_in[8];
    const float* bv = (const float*)d_in[9];
    const float* Wo = (const float*)d_in[10];
    const float* bo = (const float*)d_in[11];
    const float* bias_table = (const float*)d_in[12];
    float* out = (float*)d_out;

    float *gq, *gk, *gv, *gy;
    cudaGetSymbolAddress((void**)&gq, g_q);
    cudaGetSymbolAddress((void**)&gk, g_k);
    cudaGetSymbolAddress((void**)&gv, g_v);
    cudaGetSymbolAddress((void**)&gy, g_y);

    cudaFuncSetAttribute(attn_kernel, cudaFuncAttributeMaxDynamicSharedMemorySize,
                         (int)SMEM_ATTN);

    dim3 gemm_grid(DD / 128, (BB * NN) / 128);   // (4, 32)

    init_bins_kernel<<<1, 32>>>();
    gemm_tf32_kernel<<<gemm_grid, 256>>>(query, Wq, bq, gq, 1);
    gemm_tf32_kernel<<<gemm_grid, 256>>>(key,   Wk, bk, gk, 1);
    gemm_tf32_kernel<<<gemm_grid, 256>>>(value, Wv, bv, gv, 1);
    precompute_kernel<<<(BB * NN * NN) / 256, 256>>>(coords);
    attn_kernel<<<dim3(NN / 64, BB * HH), 128, SMEM_ATTN>>>(bias_table);
    gemm_tf32_kernel<<<gemm_grid, 256>>>(gy, Wo, bo, out, 0);
}

// round 6
// speedup vs baseline: 3.4351x; 1.5656x over previous
#include <cuda_runtime.h>
#include <cuda_bf16.h>
#include <math_constants.h>

// Problem constants
#define BB 4
#define NN 1024
#define DD 512
#define HH 8
#define HD 64
#define NSP 32
#define NTMP 16

// Scratch (device globals; no allocations allowed)
__device__ float g_q[BB * HH * NN * HD];   // (b,h,n,d)
__device__ float g_k[BB * HH * NN * HD];
__device__ float g_v[BB * HH * NN * HD];
__device__ float g_y[BB * NN * DD];        // (b,n,h*HD+d)
__device__ float g_mask[BB * NN * NN];     // mask + exp(-0.1*full_dist)
__device__ short g_idx[BB * NN * NN];      // bias table row index
__device__ float g_sbins[NSP];

// ---------------------------------------------------------------------------
// bf16 m16n8k16 mma + 3xBF16 split helpers
// ---------------------------------------------------------------------------
__device__ __forceinline__ void mma_bf16(float* d,
                                         unsigned a0, unsigned a1, unsigned a2, unsigned a3,
                                         unsigned b0, unsigned b1) {
    asm volatile(
        "mma.sync.aligned.m16n8k16.row.col.f32.bf16.bf16.f32 "
        "{%0,%1,%2,%3}, {%4,%5,%6,%7}, {%8,%9}, {%0,%1,%2,%3};\n"
        : "+f"(d[0]), "+f"(d[1]), "+f"(d[2]), "+f"(d[3])
        : "r"(a0), "r"(a1), "r"(a2), "r"(a3), "r"(b0), "r"(b1));
}

// D += Ah*Bh + Ah*Bl + Al*Bh   (drop Al*Bl ~ 2^-18)
__device__ __forceinline__ void mma3b(float* d,
                                      const unsigned* ah, const unsigned* al,
                                      unsigned bh0, unsigned bh1,
                                      unsigned bl0, unsigned bl1) {
    mma_bf16(d, ah[0], ah[1], ah[2], ah[3], bh0, bh1);
    mma_bf16(d, ah[0], ah[1], ah[2], ah[3], bl0, bl1);
    mma_bf16(d, al[0], al[1], al[2], al[3], bh0, bh1);
}

// split two floats into packed-bf16 hi word + lo word (x0 -> low half)
__device__ __forceinline__ void split2(float x0, float x1, unsigned& hi, unsigned& lo) {
    __nv_bfloat162 h = __floats2bfloat162_rn(x0, x1);
    float2 hf = __bfloat1622float2(h);
    __nv_bfloat162 l = __floats2bfloat162_rn(x0 - hf.x, x1 - hf.y);
    hi = *(unsigned*)&h;
    lo = *(unsigned*)&l;
}

__device__ __forceinline__ unsigned smem_u32(const void* p) {
    return (unsigned)__cvta_generic_to_shared(p);
}

// ldmatrix x4 transposed b16 (for V fragments)
__device__ __forceinline__ void ldsm_x4_trans(unsigned& r0, unsigned& r1,
                                              unsigned& r2, unsigned& r3,
                                              unsigned addr) {
    asm volatile(
        "ldmatrix.sync.aligned.m8n8.x4.trans.shared.b16 {%0,%1,%2,%3}, [%4];"
        : "=r"(r0), "=r"(r1), "=r"(r2), "=r"(r3) : "r"(addr));
}

// ---------------------------------------------------------------------------
// Fill spatial bins: exp(linspace(0, log(257), 32))
// ---------------------------------------------------------------------------
__global__ void init_bins_kernel() {
    int i = threadIdx.x;
    if (i < NSP) {
        double L = log(257.0);
        g_sbins[i] = (float)exp((double)i * (L / 31.0));
    }
}

// ---------------------------------------------------------------------------
// 3xBF16 GEMM: C[m,o] = sum_k A[m,k] * W[o,k] + bias[o]
// mode 0: C row-major; mode 1: scatter to (b,h,n,d)
// Tile 128x128, BK=32, 256 threads (8 warps, 4x2, warp tile 32x64)
// smem planes: bf16 hi/lo, row stride 40 bf16 = 20 words (conflict-free frags)
// ---------------------------------------------------------------------------
#define BKW 20

struct QKVArgs {
    const float* A0; const float* A1; const float* A2;
    const float* W0; const float* W1; const float* W2;
    const float* b0; const float* b1; const float* b2;
    float* C0; float* C1; float* C2;
};

__global__ __launch_bounds__(256) void gemm_bf16_kernel(QKVArgs args, int mode) {
    __shared__ unsigned Ah[128 * BKW], Al[128 * BKW];
    __shared__ unsigned Bh[128 * BKW], Bl[128 * BKW];

    int z = blockIdx.z;
    const float* A    = (z == 0) ? args.A0 : (z == 1) ? args.A1 : args.A2;
    const float* W    = (z == 0) ? args.W0 : (z == 1) ? args.W1 : args.W2;
    const float* bias = (z == 0) ? args.b0 : (z == 1) ? args.b1 : args.b2;
    float* C          = (z == 0) ? args.C0 : (z == 1) ? args.C1 : args.C2;

    const int K = DD, O = DD;
    int tid = threadIdx.x;
    int lane = tid & 31;
    int wid = tid >> 5;
    int warp_m = wid & 3;
    int warp_n = wid >> 2;
    int row0 = blockIdx.y * 128;
    int col0 = blockIdx.x * 128;
    int lg = lane >> 2;
    int lt = lane & 3;

    float acc[2][8][4];
#pragma unroll
    for (int mf = 0; mf < 2; mf++)
#pragma unroll
        for (int nf = 0; nf < 8; nf++)
#pragma unroll
            for (int zz = 0; zz < 4; zz++) acc[mf][nf][zz] = 0.0f;

    for (int k0 = 0; k0 < K; k0 += 32) {
#pragma unroll
        for (int i = 0; i < 4; i++) {
            int f = tid + 256 * i;      // 0..1023
            int r = f >> 3, c4 = f & 7;
            float4 a4 = *(const float4*)&A[(size_t)(row0 + r) * K + k0 + c4 * 4];
            float4 w4 = *(const float4*)&W[(size_t)(col0 + r) * K + k0 + c4 * 4];
            unsigned h0, l0, h1, l1;
            split2(a4.x, a4.y, h0, l0); split2(a4.z, a4.w, h1, l1);
            Ah[r * BKW + c4 * 2] = h0; Ah[r * BKW + c4 * 2 + 1] = h1;
            Al[r * BKW + c4 * 2] = l0; Al[r * BKW + c4 * 2 + 1] = l1;
            split2(w4.x, w4.y, h0, l0); split2(w4.z, w4.w, h1, l1);
            Bh[r * BKW + c4 * 2] = h0; Bh[r * BKW + c4 * 2 + 1] = h1;
            Bl[r * BKW + c4 * 2] = l0; Bl[r * BKW + c4 * 2 + 1] = l1;
        }
        __syncthreads();

#pragma unroll
        for (int kf = 0; kf < 2; kf++) {
            unsigned bh[8][2], bl[8][2];
#pragma unroll
            for (int nf = 0; nf < 8; nf++) {
                int o = warp_n * 64 + nf * 8 + lg;
                int wb = o * BKW + kf * 8 + lt;
                bh[nf][0] = Bh[wb]; bh[nf][1] = Bh[wb + 4];
                bl[nf][0] = Bl[wb]; bl[nf][1] = Bl[wb + 4];
            }
#pragma unroll
            for (int mf = 0; mf < 2; mf++) {
                int m = warp_m * 32 + mf * 16 + lg;
                int wa = m * BKW + kf * 8 + lt;
                unsigned ah[4], al[4];
                ah[0] = Ah[wa];           ah[1] = Ah[wa + 8 * BKW];
                ah[2] = Ah[wa + 4];       ah[3] = Ah[wa + 8 * BKW + 4];
                al[0] = Al[wa];           al[1] = Al[wa + 8 * BKW];
                al[2] = Al[wa + 4];       al[3] = Al[wa + 8 * BKW + 4];
#pragma unroll
                for (int nf = 0; nf < 8; nf++)
                    mma3b(acc[mf][nf], ah, al,
                          bh[nf][0], bh[nf][1], bl[nf][0], bl[nf][1]);
            }
        }
        __syncthreads();
    }

    // Epilogue
#pragma unroll
    for (int mf = 0; mf < 2; mf++) {
#pragma unroll
        for (int nf = 0; nf < 8; nf++) {
            int rr = row0 + warp_m * 32 + mf * 16 + lg;
            int cc = col0 + warp_n * 64 + nf * 8 + lt * 2;
            float b0 = bias[cc], b1 = bias[cc + 1];
#pragma unroll
            for (int half = 0; half < 2; half++) {
                int m = rr + half * 8;
                float v0 = acc[mf][nf][half * 2 + 0] + b0;
                float v1 = acc[mf][nf][half * 2 + 1] + b1;
                if (mode == 0) {
                    *(float2*)&C[(size_t)m * O + cc] = make_float2(v0, v1);
                } else {
                    int b = m >> 10, n = m & (NN - 1);
                    int h = cc >> 6, d = cc & (HD - 1);
                    *(float2*)&C[((((size_t)b * HH + h) * NN) + n) * HD + d] =
                        make_float2(v0, v1);
                }
            }
        }
    }
}

// ---------------------------------------------------------------------------
// Precompute per-pair bias-table index + mask value
// ---------------------------------------------------------------------------
__global__ void precompute_kernel(const float* __restrict__ coords) {
    int gid = blockIdx.x * 256 + threadIdx.x;   // 0 .. B*N*N-1 (4M)
    int b = gid >> 20;
    int rem = gid & ((1 << 20) - 1);
    int i = rem >> 10;
    int j = rem & 1023;

    const float* ci = coords + ((size_t)b * NN + i) * 3;
    const float* cj = coords + ((size_t)b * NN + j) * 3;
    float ti = ci[0], yi = ci[1], xi = ci[2];
    float tj = cj[0], yj = cj[1], xj = cj[2];

    float dy = yi - yj, dx = xi - xj, dt = ti - tj;
    float sp2 = dy * dy + dx * dx;
    float sd = sqrtf(fmaxf(sp2, 0.0f));
    float fd = sqrtf(fmaxf(dt * dt + dy * dy + dx * dx, 0.0f));

    int c = 0;
#pragma unroll
    for (int s = 0; s < NSP; s++) c += (g_sbins[s] < sd) ? 1 : 0;
    int sidx = min(c, NSP - 1);

    int tc = (int)ceilf(dt + 16.0f);
    tc = max(0, min(2 * NTMP, tc));

    g_idx[gid]  = (short)(sidx + tc * NSP);
    g_mask[gid] = (sd > 256.0f ? -1000.0f : 0.0f) + expf(-0.1f * fd);
}

// ---------------------------------------------------------------------------
// Flash attention with 3xBF16 mma.
// grid: (N/64, B*H). block: 128 threads (4 warps); warp w owns q rows w*16..+16
// smem: 8 bf16 planes [64 rows][72 bf16 = 36 words]: qh,ql,kh,kl,vh,vl,ph,pl
// ---------------------------------------------------------------------------
#define PW 36                              // words per plane row
#define PLANE (64 * PW)                    // words per plane
#define SMEM_ATTN (8 * PLANE * 4)          // 73728 bytes

__global__ __launch_bounds__(128) void attn_kernel(const float* __restrict__ bias_table) {
    extern __shared__ unsigned sh[];
    unsigned* qh = sh;
    unsigned* ql = qh + PLANE;
    unsigned* kh = ql + PLANE;
    unsigned* kl = kh + PLANE;
    unsigned* vh = kl + PLANE;
    unsigned* vl = vh + PLANE;
    unsigned* ph = vl + PLANE;
    unsigned* pl = ph + PLANE;

    int bh_ = blockIdx.y;             // 0..31
    int b = bh_ >> 3, h = bh_ & 7;
    int i0 = blockIdx.x * 64;
    int tid = threadIdx.x;
    int lane = tid & 31;
    int w = tid >> 5;
    int lg = lane >> 2;
    int lt = lane & 3;

    // load + split q tile (64 x 64)
    const float* qbase = g_q + ((size_t)bh_ * NN + i0) * HD;
#pragma unroll
    for (int it = 0; it < 8; it++) {
        int f = tid + 128 * it;
        int row = f >> 4, c4 = f & 15;
        float4 a4 = ((const float4*)qbase)[f];
        unsigned h0, l0, h1, l1;
        split2(a4.x, a4.y, h0, l0); split2(a4.z, a4.w, h1, l1);
        qh[row * PW + c4 * 2] = h0; qh[row * PW + c4 * 2 + 1] = h1;
        ql[row * PW + c4 * 2] = l0; ql[row * PW + c4 * 2 + 1] = l1;
    }
    __syncthreads();

    // q A-fragments held in registers for whole loop (4 k16-steps)
    unsigned qhf[4][4], qlf[4][4];
    {
        int m = w * 16 + lg;
#pragma unroll
        for (int kf = 0; kf < 4; kf++) {
            int wa = m * PW + kf * 8 + lt;
            qhf[kf][0] = qh[wa];         qhf[kf][1] = qh[wa + 8 * PW];
            qhf[kf][2] = qh[wa + 4];     qhf[kf][3] = qh[wa + 8 * PW + 4];
            qlf[kf][0] = ql[wa];         qlf[kf][1] = ql[wa + 8 * PW];
            qlf[kf][2] = ql[wa + 4];     qlf[kf][3] = ql[wa + 8 * PW + 4];
        }
    }

    float o[8][4];
#pragma unroll
    for (int nf = 0; nf < 8; nf++)
#pragma unroll
        for (int zz = 0; zz < 4; zz++) o[nf][zz] = 0.0f;
    float m0 = -CUDART_INF_F, m1 = -CUDART_INF_F;
    float l0s = 0.0f, l1s = 0.0f;

    const size_t maskrow0 = ((size_t)b * NN + (i0 + w * 16 + lg)) * NN;
    const size_t maskrow1 = maskrow0 + 8 * (size_t)NN;

    const float* kb_all = g_k + (size_t)bh_ * NN * HD;
    const float* vb_all = g_v + (size_t)bh_ * NN * HD;

    for (int jt = 0; jt < NN / 64; jt++) {
        int j0 = jt * 64;
        __syncthreads();
        {
            const float4* kb = (const float4*)(kb_all + (size_t)j0 * HD);
            const float4* vb = (const float4*)(vb_all + (size_t)j0 * HD);
#pragma unroll
            for (int it = 0; it < 8; it++) {
                int f = tid + 128 * it;
                int row = f >> 4, c4 = f & 15;
                float4 a4 = kb[f];
                unsigned h0, l0, h1, l1;
                split2(a4.x, a4.y, h0, l0); split2(a4.z, a4.w, h1, l1);
                kh[row * PW + c4 * 2] = h0; kh[row * PW + c4 * 2 + 1] = h1;
                kl[row * PW + c4 * 2] = l0; kl[row * PW + c4 * 2 + 1] = l1;
                float4 v4 = vb[f];
                split2(v4.x, v4.y, h0, l0); split2(v4.z, v4.w, h1, l1);
                vh[row * PW + c4 * 2] = h0; vh[row * PW + c4 * 2 + 1] = h1;
                vl[row * PW + c4 * 2] = l0; vl[row * PW + c4 * 2 + 1] = l1;
            }
        }
        __syncthreads();

        // ---- QK^T (3xBF16): s[nf] covers cols nf*8 + lt*2 + {0,1}, rows lg, lg+8
        float s[8][4];
#pragma unroll
        for (int nf = 0; nf < 8; nf++) {
            s[nf][0] = s[nf][1] = s[nf][2] = s[nf][3] = 0.0f;
            int jr = nf * 8 + lg;
#pragma unroll
            for (int kf = 0; kf < 4; kf++) {
                int wb = jr * PW + kf * 8 + lt;
                unsigned bh0 = kh[wb], bh1 = kh[wb + 4];
                unsigned bl0 = kl[wb], bl1 = kl[wb + 4];
                mma3b(s[nf], qhf[kf], qlf[kf], bh0, bh1, bl0, bl1);
            }
        }

        // ---- bias + mask
#pragma unroll
        for (int nf = 0; nf < 8; nf++) {
            int jc = j0 + nf * 8 + lt * 2;
            float2 mv0 = *(const float2*)&g_mask[maskrow0 + jc];
            float2 mv1 = *(const float2*)&g_mask[maskrow1 + jc];
            unsigned ip0 = *(const unsigned*)&g_idx[maskrow0 + jc];
            unsigned ip1 = *(const unsigned*)&g_idx[maskrow1 + jc];
            int i00 = (int)(ip0 & 0xffff), i01 = (int)(ip0 >> 16);
            int i10 = (int)(ip1 & 0xffff), i11 = (int)(ip1 >> 16);
            s[nf][0] = s[nf][0] * 0.125f + __ldg(&bias_table[i00 * HH + h]) + mv0.x;
            s[nf][1] = s[nf][1] * 0.125f + __ldg(&bias_table[i01 * HH + h]) + mv0.y;
            s[nf][2] = s[nf][2] * 0.125f + __ldg(&bias_table[i10 * HH + h]) + mv1.x;
            s[nf][3] = s[nf][3] * 0.125f + __ldg(&bias_table[i11 * HH + h]) + mv1.y;
        }

        // ---- online softmax (2 rows per thread)
        float t0 = s[0][0], t1 = s[0][2];
#pragma unroll
        for (int nf = 0; nf < 8; nf++) {
            t0 = fmaxf(t0, fmaxf(s[nf][0], s[nf][1]));
            t1 = fmaxf(t1, fmaxf(s[nf][2], s[nf][3]));
        }
        t0 = fmaxf(t0, __shfl_xor_sync(0xffffffffu, t0, 1));
        t0 = fmaxf(t0, __shfl_xor_sync(0xffffffffu, t0, 2));
        t1 = fmaxf(t1, __shfl_xor_sync(0xffffffffu, t1, 1));
        t1 = fmaxf(t1, __shfl_xor_sync(0xffffffffu, t1, 2));
        float nm0 = fmaxf(m0, t0), nm1 = fmaxf(m1, t1);
        float sc0 = __expf(m0 - nm0), sc1 = __expf(m1 - nm1);

        float sum0 = 0.0f, sum1 = 0.0f;
        int pr0 = (w * 16 + lg) * PW;
        int pr1 = pr0 + 8 * PW;
#pragma unroll
        for (int nf = 0; nf < 8; nf++) {
            float p0 = __expf(s[nf][0] - nm0);
            float p1 = __expf(s[nf][1] - nm0);
            float p2 = __expf(s[nf][2] - nm1);
            float p3 = __expf(s[nf][3] - nm1);
            sum0 += p0 + p1;
            sum1 += p2 + p3;
            unsigned hw, lw;
            int wi = nf * 4 + lt;
            split2(p0, p1, hw, lw);
            ph[pr0 + wi] = hw; pl[pr0 + wi] = lw;
            split2(p2, p3, hw, lw);
            ph[pr1 + wi] = hw; pl[pr1 + wi] = lw;
        }
        sum0 += __shfl_xor_sync(0xffffffffu, sum0, 1);
        sum0 += __shfl_xor_sync(0xffffffffu, sum0, 2);
        sum1 += __shfl_xor_sync(0xffffffffu, sum1, 1);
        sum1 += __shfl_xor_sync(0xffffffffu, sum1, 2);
        l0s = l0s * sc0 + sum0;
        l1s = l1s * sc1 + sum1;
        m0 = nm0; m1 = nm1;
#pragma unroll
        for (int nf = 0; nf < 8; nf++) {
            o[nf][0] *= sc0; o[nf][1] *= sc0;
            o[nf][2] *= sc1; o[nf][3] *= sc1;
        }
        __syncwarp();

        // ---- PV (3xBF16): o[r][d] += sum_j P[r][j] V[j][d]
        int par = (w * 16 + lg) * PW;
#pragma unroll
        for (int kf = 0; kf < 4; kf++) {
            int wa = par + kf * 8 + lt;
            unsigned phf[4], plf[4];
            phf[0] = ph[wa];       phf[1] = ph[wa + 8 * PW];
            phf[2] = ph[wa + 4];   phf[3] = ph[wa + 8 * PW + 4];
            plf[0] = pl[wa];       plf[1] = pl[wa + 8 * PW];
            plf[2] = pl[wa + 4];   plf[3] = pl[wa + 8 * PW + 4];
            // ldmatrix lane address: rows j0v + (lane&15), col-block +8 for lanes>=16
            int vrow = kf * 16 + (lane & 15);
#pragma unroll
            for (int nf2 = 0; nf2 < 4; nf2++) {
                unsigned woff = (unsigned)(vrow * PW + nf2 * 8 + ((lane >> 4) << 2)) * 4u;
                unsigned h0, h1, h2, h3, l0_, l1_, l2_, l3_;
                ldsm_x4_trans(h0, h1, h2, h3, smem_u32(vh) + woff);
                ldsm_x4_trans(l0_, l1_, l2_, l3_, smem_u32(vl) + woff);
                mma3b(o[2 * nf2],     phf, plf, h0, h1, l0_, l1_);
                mma3b(o[2 * nf2 + 1], phf, plf, h2, h3, l2_, l3_);
            }
        }
    }

    float inv0 = 1.0f / l0s;
    float inv1 = 1.0f / l1s;
    int r0 = i0 + w * 16 + lg;
#pragma unroll
    for (int nf = 0; nf < 8; nf++) {
        int cc = h * HD + nf * 8 + lt * 2;
        *(float2*)&g_y[(size_t)(b * NN + r0) * DD + cc] =
            make_float2(o[nf][0] * inv0, o[nf][1] * inv0);
        *(float2*)&g_y[(size_t)(b * NN + r0 + 8) * DD + cc] =
            make_float2(o[nf][2] * inv1, o[nf][3] * inv1);
    }
}

// ---------------------------------------------------------------------------
// Host launch
// ---------------------------------------------------------------------------
extern "C" void kernel_launch(void* const* d_in, const int* in_sizes, int n_in,
                              void* d_out, int out_size) {
    const float* query = (const float*)d_in[0];
    const float* key   = (const float*)d_in[1];
    const float* value = (const float*)d_in[2];
    const float* coords = (const float*)d_in[3];
    const float* Wq = (const float*)d_in[4];
    const float* bq = (const float*)d_in[5];
    const float* Wk = (const float*)d_in[6];
    const float* bk = (const float*)d_in[7];
    const float* Wv = (const float*)d_in[8];
    const float* bv = (const float*)d_in[9];
    const float* Wo = (const float*)d_in[10];
    const float* bo = (const float*)d_in[11];
    const float* bias_table = (const float*)d_in[12];
    float* out = (float*)d_out;

    float *gq, *gk, *gv, *gy;
    cudaGetSymbolAddress((void**)&gq, g_q);
    cudaGetSymbolAddress((void**)&gk, g_k);
    cudaGetSymbolAddress((void**)&gv, g_v);
    cudaGetSymbolAddress((void**)&gy, g_y);

    cudaFuncSetAttribute(attn_kernel, cudaFuncAttributeMaxDynamicSharedMemorySize,
                         (int)SMEM_ATTN);

    init_bins_kernel<<<1, 32>>>();

    // Fused QKV projections (grid.z selects input/weight set)
    QKVArgs qa;
    qa.A0 = query; qa.A1 = key; qa.A2 = value;
    qa.W0 = Wq;    qa.W1 = Wk;  qa.W2 = Wv;
    qa.b0 = bq;    qa.b1 = bk;  qa.b2 = bv;
    qa.C0 = gq;    qa.C1 = gk;  qa.C2 = gv;
    gemm_bf16_kernel<<<dim3(DD / 128, (BB * NN) / 128, 3), 256>>>(qa, 1);

    precompute_kernel<<<(BB * NN * NN) / 256, 256>>>(coords);
    attn_kernel<<<dim3(NN / 64, BB * HH), 128, SMEM_ATTN>>>(bias_table);

    // Output projection
    QKVArgs oa;
    oa.A0 = gy; oa.A1 = gy; oa.A2 = gy;
    oa.W0 = Wo; oa.W1 = Wo; oa.W2 = Wo;
    oa.b0 = bo; oa.b1 = bo; oa.b2 = bo;
    oa.C0 = out; oa.C1 = out; oa.C2 = out;
    gemm_bf16_kernel<<<dim3(DD / 128, (BB * NN) / 128, 1), 256>>>(oa, 0);
}

// round 7
// speedup vs baseline: 3.8337x; 1.1160x over previous
#include <cuda_runtime.h>
#include <cuda_bf16.h>
#include <math_constants.h>

// Problem constants
#define BB 4
#define NN 1024
#define DD 512
#define HH 8
#define HD 64
#define NSP 32
#define NTMP 16

// Scratch (device globals; no allocations allowed)
__device__ __nv_bfloat16 g_qbh[BB * HH * NN * HD];  // Q bf16 hi plane (b,h,n,d)
__device__ __nv_bfloat16 g_qbl[BB * HH * NN * HD];  // Q bf16 lo plane
__device__ __nv_bfloat16 g_kbh[BB * HH * NN * HD];
__device__ __nv_bfloat16 g_kbl[BB * HH * NN * HD];
__device__ __nv_bfloat16 g_vbh[BB * HH * NN * HD];
__device__ __nv_bfloat16 g_vbl[BB * HH * NN * HD];
__device__ float g_y[BB * NN * DD];        // attention out (b,n,h*HD+d)
__device__ float g_mask[BB * NN * NN];     // mask + exp(-0.1*full_dist)
__device__ short g_idx[BB * NN * NN];      // bias table row index
__device__ float g_sbins[NSP];

// ---------------------------------------------------------------------------
// bf16 m16n8k16 mma + 3xBF16 split helpers
// ---------------------------------------------------------------------------
__device__ __forceinline__ void mma_bf16(float* d,
                                         unsigned a0, unsigned a1, unsigned a2, unsigned a3,
                                         unsigned b0, unsigned b1) {
    asm volatile(
        "mma.sync.aligned.m16n8k16.row.col.f32.bf16.bf16.f32 "
        "{%0,%1,%2,%3}, {%4,%5,%6,%7}, {%8,%9}, {%0,%1,%2,%3};\n"
        : "+f"(d[0]), "+f"(d[1]), "+f"(d[2]), "+f"(d[3])
        : "r"(a0), "r"(a1), "r"(a2), "r"(a3), "r"(b0), "r"(b1));
}

// D += Ah*Bh + Ah*Bl + Al*Bh   (drop Al*Bl ~ 2^-18)
__device__ __forceinline__ void mma3b(float* d,
                                      const unsigned* ah, const unsigned* al,
                                      unsigned bh0, unsigned bh1,
                                      unsigned bl0, unsigned bl1) {
    mma_bf16(d, ah[0], ah[1], ah[2], ah[3], bh0, bh1);
    mma_bf16(d, ah[0], ah[1], ah[2], ah[3], bl0, bl1);
    mma_bf16(d, al[0], al[1], al[2], al[3], bh0, bh1);
}

// split two floats into packed-bf16 hi word + lo word (x0 -> low half)
__device__ __forceinline__ void split2(float x0, float x1, unsigned& hi, unsigned& lo) {
    __nv_bfloat162 h = __floats2bfloat162_rn(x0, x1);
    float2 hf = __bfloat1622float2(h);
    __nv_bfloat162 l = __floats2bfloat162_rn(x0 - hf.x, x1 - hf.y);
    hi = *(unsigned*)&h;
    lo = *(unsigned*)&l;
}

__device__ __forceinline__ unsigned smem_u32(const void* p) {
    return (unsigned)__cvta_generic_to_shared(p);
}

__device__ __forceinline__ void ldsm_x4(unsigned& r0, unsigned& r1,
                                        unsigned& r2, unsigned& r3, unsigned addr) {
    asm volatile(
        "ldmatrix.sync.aligned.m8n8.x4.shared.b16 {%0,%1,%2,%3}, [%4];"
        : "=r"(r0), "=r"(r1), "=r"(r2), "=r"(r3) : "r"(addr));
}

__device__ __forceinline__ void ldsm_x4_trans(unsigned& r0, unsigned& r1,
                                              unsigned& r2, unsigned& r3,
                                              unsigned addr) {
    asm volatile(
        "ldmatrix.sync.aligned.m8n8.x4.trans.shared.b16 {%0,%1,%2,%3}, [%4];"
        : "=r"(r0), "=r"(r1), "=r"(r2), "=r"(r3) : "r"(addr));
}

// ---------------------------------------------------------------------------
// Fill spatial bins: exp(linspace(0, log(257), 32))
// ---------------------------------------------------------------------------
__global__ void init_bins_kernel() {
    int i = threadIdx.x;
    if (i < NSP) {
        double L = log(257.0);
        g_sbins[i] = (float)exp((double)i * (L / 31.0));
    }
}

// ---------------------------------------------------------------------------
// 3xBF16 GEMM: C[m,o] = sum_k A[m,k] * W[o,k] + bias[o]
// mode 0: C row-major fp32; mode 1: scatter bf16 hi/lo planes in (b,h,n,d)
// Tile 128x128, BK=32, 256 threads (8 warps, 4x2, warp tile 32x64)
// ---------------------------------------------------------------------------
#define BKW 20

struct QKVArgs {
    const float* A0; const float* A1; const float* A2;
    const float* W0; const float* W1; const float* W2;
    const float* b0; const float* b1; const float* b2;
    __nv_bfloat16* Ch0; __nv_bfloat16* Cl0;
    __nv_bfloat16* Ch1; __nv_bfloat16* Cl1;
    __nv_bfloat16* Ch2; __nv_bfloat16* Cl2;
    float* C0;
};

__global__ __launch_bounds__(256) void gemm_bf16_kernel(QKVArgs args, int mode) {
    __shared__ unsigned Ah[128 * BKW], Al[128 * BKW];
    __shared__ unsigned Bh[128 * BKW], Bl[128 * BKW];

    int z = blockIdx.z;
    const float* A    = (z == 0) ? args.A0 : (z == 1) ? args.A1 : args.A2;
    const float* W    = (z == 0) ? args.W0 : (z == 1) ? args.W1 : args.W2;
    const float* bias = (z == 0) ? args.b0 : (z == 1) ? args.b1 : args.b2;
    __nv_bfloat16* Ch = (z == 0) ? args.Ch0 : (z == 1) ? args.Ch1 : args.Ch2;
    __nv_bfloat16* Cl = (z == 0) ? args.Cl0 : (z == 1) ? args.Cl1 : args.Cl2;

    const int K = DD, O = DD;
    int tid = threadIdx.x;
    int lane = tid & 31;
    int wid = tid >> 5;
    int warp_m = wid & 3;
    int warp_n = wid >> 2;
    int row0 = blockIdx.y * 128;
    int col0 = blockIdx.x * 128;
    int lg = lane >> 2;
    int lt = lane & 3;

    float acc[2][8][4];
#pragma unroll
    for (int mf = 0; mf < 2; mf++)
#pragma unroll
        for (int nf = 0; nf < 8; nf++)
#pragma unroll
            for (int zz = 0; zz < 4; zz++) acc[mf][nf][zz] = 0.0f;

    for (int k0 = 0; k0 < K; k0 += 32) {
#pragma unroll
        for (int i = 0; i < 4; i++) {
            int f = tid + 256 * i;      // 0..1023
            int r = f >> 3, c4 = f & 7;
            float4 a4 = *(const float4*)&A[(size_t)(row0 + r) * K + k0 + c4 * 4];
            float4 w4 = *(const float4*)&W[(size_t)(col0 + r) * K + k0 + c4 * 4];
            unsigned h0, l0, h1, l1;
            split2(a4.x, a4.y, h0, l0); split2(a4.z, a4.w, h1, l1);
            Ah[r * BKW + c4 * 2] = h0; Ah[r * BKW + c4 * 2 + 1] = h1;
            Al[r * BKW + c4 * 2] = l0; Al[r * BKW + c4 * 2 + 1] = l1;
            split2(w4.x, w4.y, h0, l0); split2(w4.z, w4.w, h1, l1);
            Bh[r * BKW + c4 * 2] = h0; Bh[r * BKW + c4 * 2 + 1] = h1;
            Bl[r * BKW + c4 * 2] = l0; Bl[r * BKW + c4 * 2 + 1] = l1;
        }
        __syncthreads();

#pragma unroll
        for (int kf = 0; kf < 2; kf++) {
            unsigned bh[8][2], bl[8][2];
#pragma unroll
            for (int nf = 0; nf < 8; nf++) {
                int o = warp_n * 64 + nf * 8 + lg;
                int wb = o * BKW + kf * 8 + lt;
                bh[nf][0] = Bh[wb]; bh[nf][1] = Bh[wb + 4];
                bl[nf][0] = Bl[wb]; bl[nf][1] = Bl[wb + 4];
            }
#pragma unroll
            for (int mf = 0; mf < 2; mf++) {
                int m = warp_m * 32 + mf * 16 + lg;
                int wa = m * BKW + kf * 8 + lt;
                unsigned ah[4], al[4];
                ah[0] = Ah[wa];           ah[1] = Ah[wa + 8 * BKW];
                ah[2] = Ah[wa + 4];       ah[3] = Ah[wa + 8 * BKW + 4];
                al[0] = Al[wa];           al[1] = Al[wa + 8 * BKW];
                al[2] = Al[wa + 4];       al[3] = Al[wa + 8 * BKW + 4];
#pragma unroll
                for (int nf = 0; nf < 8; nf++)
                    mma3b(acc[mf][nf], ah, al,
                          bh[nf][0], bh[nf][1], bl[nf][0], bl[nf][1]);
            }
        }
        __syncthreads();
    }

    // Epilogue
#pragma unroll
    for (int mf = 0; mf < 2; mf++) {
#pragma unroll
        for (int nf = 0; nf < 8; nf++) {
            int rr = row0 + warp_m * 32 + mf * 16 + lg;
            int cc = col0 + warp_n * 64 + nf * 8 + lt * 2;
            float b0 = bias[cc], b1 = bias[cc + 1];
#pragma unroll
            for (int half = 0; half < 2; half++) {
                int m = rr + half * 8;
                float v0 = acc[mf][nf][half * 2 + 0] + b0;
                float v1 = acc[mf][nf][half * 2 + 1] + b1;
                if (mode == 0) {
                    *(float2*)&args.C0[(size_t)m * O + cc] = make_float2(v0, v1);
                } else {
                    int b = m >> 10, n = m & (NN - 1);
                    int h = cc >> 6, d = cc & (HD - 1);
                    size_t widx = (((((size_t)b * HH + h) * NN) + n) * HD + d) >> 1;
                    unsigned hw, lw;
                    split2(v0, v1, hw, lw);
                    ((unsigned*)Ch)[widx] = hw;
                    ((unsigned*)Cl)[widx] = lw;
                }
            }
        }
    }
}

// ---------------------------------------------------------------------------
// Precompute per-pair bias-table index + mask value
// ---------------------------------------------------------------------------
__global__ void precompute_kernel(const float* __restrict__ coords) {
    int gid = blockIdx.x * 256 + threadIdx.x;   // 0 .. B*N*N-1 (4M)
    int b = gid >> 20;
    int rem = gid & ((1 << 20) - 1);
    int i = rem >> 10;
    int j = rem & 1023;

    const float* ci = coords + ((size_t)b * NN + i) * 3;
    const float* cj = coords + ((size_t)b * NN + j) * 3;
    float ti = ci[0], yi = ci[1], xi = ci[2];
    float tj = cj[0], yj = cj[1], xj = cj[2];

    float dy = yi - yj, dx = xi - xj, dt = ti - tj;
    float sp2 = dy * dy + dx * dx;
    float sd = sqrtf(fmaxf(sp2, 0.0f));
    float fd = sqrtf(fmaxf(dt * dt + dy * dy + dx * dx, 0.0f));

    int c = 0;
#pragma unroll
    for (int s = 0; s < NSP; s++) c += (g_sbins[s] < sd) ? 1 : 0;
    int sidx = min(c, NSP - 1);

    int tc = (int)ceilf(dt + 16.0f);
    tc = max(0, min(2 * NTMP, tc));

    g_idx[gid]  = (short)(sidx + tc * NSP);
    g_mask[gid] = (sd > 256.0f ? -1000.0f : 0.0f) + expf(-0.1f * fd);
}

// ---------------------------------------------------------------------------
// Flash attention, 3xBF16, pre-split operands, P kept in registers.
// grid: (N/128, B*H). block: 256 threads (8 warps); warp w owns q rows w*16..+16
// smem: kh,kl,vh,vl planes [64 j rows][32 data words + 4 pad]
// ---------------------------------------------------------------------------
#define PW 36
#define PLANE (64 * PW)

__global__ __launch_bounds__(256) void attn_kernel(const float* __restrict__ bias_table) {
    __shared__ unsigned kh[PLANE], kl[PLANE], vh[PLANE], vl[PLANE];

    int bh_ = blockIdx.y;             // 0..31
    int b = bh_ >> 3, h = bh_ & 7;
    int i0 = blockIdx.x * 128;
    int tid = threadIdx.x;
    int lane = tid & 31;
    int w = tid >> 5;                 // 0..7
    int lg = lane >> 2;
    int lt = lane & 3;
    int m = w * 16 + lg;              // q row within tile (first of pair)

    // Q A-fragments loaded straight from global bf16 planes (one-time)
    unsigned qhf[4][4], qlf[4][4];
    {
        const unsigned* qhp = (const unsigned*)g_qbh + ((size_t)bh_ * NN + i0) * (HD / 2);
        const unsigned* qlp = (const unsigned*)g_qbl + ((size_t)bh_ * NN + i0) * (HD / 2);
#pragma unroll
        for (int kf = 0; kf < 4; kf++) {
            int base = m * (HD / 2) + kf * 8 + lt;
            qhf[kf][0] = qhp[base];
            qhf[kf][1] = qhp[base + 8 * (HD / 2)];
            qhf[kf][2] = qhp[base + 4];
            qhf[kf][3] = qhp[base + 8 * (HD / 2) + 4];
            qlf[kf][0] = qlp[base];
            qlf[kf][1] = qlp[base + 8 * (HD / 2)];
            qlf[kf][2] = qlp[base + 4];
            qlf[kf][3] = qlp[base + 8 * (HD / 2) + 4];
        }
    }

    float o[8][4];
#pragma unroll
    for (int nf = 0; nf < 8; nf++)
#pragma unroll
        for (int zz = 0; zz < 4; zz++) o[nf][zz] = 0.0f;
    float m0 = -CUDART_INF_F, m1 = -CUDART_INF_F;
    float l0s = 0.0f, l1s = 0.0f;

    const size_t maskrow0 = ((size_t)b * NN + (i0 + m)) * NN;
    const size_t maskrow1 = maskrow0 + 8 * (size_t)NN;

    const unsigned* kbh = (const unsigned*)g_kbh + (size_t)bh_ * NN * (HD / 2);
    const unsigned* kbl = (const unsigned*)g_kbl + (size_t)bh_ * NN * (HD / 2);
    const unsigned* vbh = (const unsigned*)g_vbh + (size_t)bh_ * NN * (HD / 2);
    const unsigned* vbl = (const unsigned*)g_vbl + (size_t)bh_ * NN * (HD / 2);

    // ldmatrix source addresses (byte) fixed per thread
    const unsigned k_row = (lane & 7) + ((lane >> 4) << 3);
    const unsigned k_colw = ((lane >> 3) & 1) << 2;
    const unsigned v_row = lane & 15;
    const unsigned v_colw = (lane >> 4) << 2;
    const unsigned kh_base = smem_u32(kh), kl_base = smem_u32(kl);
    const unsigned vh_base = smem_u32(vh), vl_base = smem_u32(vl);

    for (int jt = 0; jt < NN / 64; jt++) {
        int j0 = jt * 64;
        __syncthreads();
        // copy 64x64 bf16 hi/lo K,V tiles (pure copy, uint4)
#pragma unroll
        for (int it = 0; it < 2; it++) {
            int f = tid + 256 * it;       // 0..511
            int row = f >> 3, c4 = f & 7;
            size_t goff = (size_t)(j0 + row) * (HD / 2);
            uint4 t0 = ((const uint4*)(kbh + goff))[c4];
            uint4 t1 = ((const uint4*)(kbl + goff))[c4];
            uint4 t2 = ((const uint4*)(vbh + goff))[c4];
            uint4 t3 = ((const uint4*)(vbl + goff))[c4];
            *(uint4*)&kh[row * PW + c4 * 4] = t0;
            *(uint4*)&kl[row * PW + c4 * 4] = t1;
            *(uint4*)&vh[row * PW + c4 * 4] = t2;
            *(uint4*)&vl[row * PW + c4 * 4] = t3;
        }
        __syncthreads();

        // ---- QK^T (3xBF16), K B-frags via ldmatrix.x4 (two n-blocks at once)
        float s[8][4];
#pragma unroll
        for (int nf = 0; nf < 8; nf++)
            s[nf][0] = s[nf][1] = s[nf][2] = s[nf][3] = 0.0f;
#pragma unroll
        for (int kf = 0; kf < 4; kf++) {
#pragma unroll
            for (int np = 0; np < 4; np++) {   // n-pair: rows np*16 .. +15
                unsigned woff = ((np * 16 + k_row) * PW + kf * 8 + k_colw) * 4u;
                unsigned h0, h1, h2, h3, l0_, l1_, l2_, l3_;
                ldsm_x4(h0, h1, h2, h3, kh_base + woff);
                ldsm_x4(l0_, l1_, l2_, l3_, kl_base + woff);
                mma3b(s[2 * np],     qhf[kf], qlf[kf], h0, h1, l0_, l1_);
                mma3b(s[2 * np + 1], qhf[kf], qlf[kf], h2, h3, l2_, l3_);
            }
        }

        // ---- bias + mask
#pragma unroll
        for (int nf = 0; nf < 8; nf++) {
            int jc = j0 + nf * 8 + lt * 2;
            float2 mv0 = *(const float2*)&g_mask[maskrow0 + jc];
            float2 mv1 = *(const float2*)&g_mask[maskrow1 + jc];
            unsigned ip0 = *(const unsigned*)&g_idx[maskrow0 + jc];
            unsigned ip1 = *(const unsigned*)&g_idx[maskrow1 + jc];
            int i00 = (int)(ip0 & 0xffff), i01 = (int)(ip0 >> 16);
            int i10 = (int)(ip1 & 0xffff), i11 = (int)(ip1 >> 16);
            s[nf][0] = s[nf][0] * 0.125f + __ldg(&bias_table[i00 * HH + h]) + mv0.x;
            s[nf][1] = s[nf][1] * 0.125f + __ldg(&bias_table[i01 * HH + h]) + mv0.y;
            s[nf][2] = s[nf][2] * 0.125f + __ldg(&bias_table[i10 * HH + h]) + mv1.x;
            s[nf][3] = s[nf][3] * 0.125f + __ldg(&bias_table[i11 * HH + h]) + mv1.y;
        }

        // ---- online softmax (2 rows per thread)
        float t0 = s[0][0], t1 = s[0][2];
#pragma unroll
        for (int nf = 0; nf < 8; nf++) {
            t0 = fmaxf(t0, fmaxf(s[nf][0], s[nf][1]));
            t1 = fmaxf(t1, fmaxf(s[nf][2], s[nf][3]));
        }
        t0 = fmaxf(t0, __shfl_xor_sync(0xffffffffu, t0, 1));
        t0 = fmaxf(t0, __shfl_xor_sync(0xffffffffu, t0, 2));
        t1 = fmaxf(t1, __shfl_xor_sync(0xffffffffu, t1, 1));
        t1 = fmaxf(t1, __shfl_xor_sync(0xffffffffu, t1, 2));
        float nm0 = fmaxf(m0, t0), nm1 = fmaxf(m1, t1);
        float sc0 = __expf(m0 - nm0), sc1 = __expf(m1 - nm1);

        float sum0 = 0.0f, sum1 = 0.0f;
#pragma unroll
        for (int nf = 0; nf < 8; nf++) {
            s[nf][0] = __expf(s[nf][0] - nm0);
            s[nf][1] = __expf(s[nf][1] - nm0);
            s[nf][2] = __expf(s[nf][2] - nm1);
            s[nf][3] = __expf(s[nf][3] - nm1);
            sum0 += s[nf][0] + s[nf][1];
            sum1 += s[nf][2] + s[nf][3];
        }
        sum0 += __shfl_xor_sync(0xffffffffu, sum0, 1);
        sum0 += __shfl_xor_sync(0xffffffffu, sum0, 2);
        sum1 += __shfl_xor_sync(0xffffffffu, sum1, 1);
        sum1 += __shfl_xor_sync(0xffffffffu, sum1, 2);
        l0s = l0s * sc0 + sum0;
        l1s = l1s * sc1 + sum1;
        m0 = nm0; m1 = nm1;
#pragma unroll
        for (int nf = 0; nf < 8; nf++) {
            o[nf][0] *= sc0; o[nf][1] *= sc0;
            o[nf][2] *= sc1; o[nf][3] *= sc1;
        }

        // ---- PV (3xBF16): P A-fragments packed directly from registers
#pragma unroll
        for (int kf = 0; kf < 4; kf++) {
            unsigned phf[4], plf[4];
            split2(s[2 * kf][0],     s[2 * kf][1],     phf[0], plf[0]);
            split2(s[2 * kf][2],     s[2 * kf][3],     phf[1], plf[1]);
            split2(s[2 * kf + 1][0], s[2 * kf + 1][1], phf[2], plf[2]);
            split2(s[2 * kf + 1][2], s[2 * kf + 1][3], phf[3], plf[3]);
            unsigned vrow = kf * 16 + v_row;
#pragma unroll
            for (int nf2 = 0; nf2 < 4; nf2++) {
                unsigned woff = (vrow * PW + nf2 * 8 + v_colw) * 4u;
                unsigned h0, h1, h2, h3, l0_, l1_, l2_, l3_;
                ldsm_x4_trans(h0, h1, h2, h3, vh_base + woff);
                ldsm_x4_trans(l0_, l1_, l2_, l3_, vl_base + woff);
                mma3b(o[2 * nf2],     phf, plf, h0, h1, l0_, l1_);
                mma3b(o[2 * nf2 + 1], phf, plf, h2, h3, l2_, l3_);
            }
        }
    }

    float inv0 = 1.0f / l0s;
    float inv1 = 1.0f / l1s;
    int r0 = i0 + m;
#pragma unroll
    for (int nf = 0; nf < 8; nf++) {
        int cc = h * HD + nf * 8 + lt * 2;
        *(float2*)&g_y[(size_t)(b * NN + r0) * DD + cc] =
            make_float2(o[nf][0] * inv0, o[nf][1] * inv0);
        *(float2*)&g_y[(size_t)(b * NN + r0 + 8) * DD + cc] =
            make_float2(o[nf][2] * inv1, o[nf][3] * inv1);
    }
}

// ---------------------------------------------------------------------------
// Host launch
// ---------------------------------------------------------------------------
extern "C" void kernel_launch(void* const* d_in, const int* in_sizes, int n_in,
                              void* d_out, int out_size) {
    const float* query = (const float*)d_in[0];
    const float* key   = (const float*)d_in[1];
    const float* value = (const float*)d_in[2];
    const float* coords = (const float*)d_in[3];
    const float* Wq = (const float*)d_in[4];
    const float* bq = (const float*)d_in[5];
    const float* Wk = (const float*)d_in[6];
    const float* bk = (const float*)d_in[7];
    const float* Wv = (const float*)d_in[8];
    const float* bv = (const float*)d_in[9];
    const float* Wo = (const float*)d_in[10];
    const float* bo = (const float*)d_in[11];
    const float* bias_table = (const float*)d_in[12];
    float* out = (float*)d_out;

    __nv_bfloat16 *qbh, *qbl, *kbh, *kbl, *vbh, *vbl;
    float* gy;
    cudaGetSymbolAddress((void**)&qbh, g_qbh);
    cudaGetSymbolAddress((void**)&qbl, g_qbl);
    cudaGetSymbolAddress((void**)&kbh, g_kbh);
    cudaGetSymbolAddress((void**)&kbl, g_kbl);
    cudaGetSymbolAddress((void**)&vbh, g_vbh);
    cudaGetSymbolAddress((void**)&vbl, g_vbl);
    cudaGetSymbolAddress((void**)&gy, g_y);

    init_bins_kernel<<<1, 32>>>();

    // Fused QKV projections -> bf16 hi/lo planes
    QKVArgs qa;
    qa.A0 = query; qa.A1 = key; qa.A2 = value;
    qa.W0 = Wq;    qa.W1 = Wk;  qa.W2 = Wv;
    qa.b0 = bq;    qa.b1 = bk;  qa.b2 = bv;
    qa.Ch0 = qbh;  qa.Cl0 = qbl;
    qa.Ch1 = kbh;  qa.Cl1 = kbl;
    qa.Ch2 = vbh;  qa.Cl2 = vbl;
    qa.C0 = nullptr;
    gemm_bf16_kernel<<<dim3(DD / 128, (BB * NN) / 128, 3), 256>>>(qa, 1);

    precompute_kernel<<<(BB * NN * NN) / 256, 256>>>(coords);
    attn_kernel<<<dim3(NN / 128, BB * HH), 256>>>(bias_table);

    // Output projection (fp32 in, fp32 out)
    QKVArgs oa;
    oa.A0 = gy; oa.A1 = gy; oa.A2 = gy;
    oa.W0 = Wo; oa.W1 = Wo; oa.W2 = Wo;
    oa.b0 = bo; oa.b1 = bo; oa.b2 = bo;
    oa.Ch0 = nullptr; oa.Cl0 = nullptr;
    oa.Ch1 = nullptr; oa.Cl1 = nullptr;
    oa.Ch2 = nullptr; oa.Cl2 = nullptr;
    oa.C0 = out;
    gemm_bf16_kernel<<<dim3(DD / 128, (BB * NN) / 128, 1), 256>>>(oa, 0);
}

// round 8
// speedup vs baseline: 4.1704x; 1.0878x over previous
#include <cuda_runtime.h>
#include <cuda_bf16.h>
#include <cuda_fp16.h>
#include <math_constants.h>

// Problem constants
#define BB 4
#define NN 1024
#define DD 512
#define HH 8
#define HD 64
#define NSP 32
#define NTMP 16

// Scratch (device globals; no allocations allowed)
__device__ __nv_bfloat16 g_qbh[BB * HH * NN * HD];  // Q bf16 hi plane (b,h,n,d)
__device__ __nv_bfloat16 g_qbl[BB * HH * NN * HD];  // Q bf16 lo plane
__device__ __nv_bfloat16 g_kbh[BB * HH * NN * HD];
__device__ __nv_bfloat16 g_kbl[BB * HH * NN * HD];
__device__ __nv_bfloat16 g_vbh[BB * HH * NN * HD];
__device__ __nv_bfloat16 g_vbl[BB * HH * NN * HD];
__device__ float g_y[BB * NN * DD];        // attention out (b,n,h*HD+d)
__device__ unsigned g_mi[BB * NN * NN];    // packed: fp16(mask) << 16 | idx
__device__ float g_sbins[NSP];

// ---------------------------------------------------------------------------
// bf16 m16n8k16 mma + 3xBF16 split helpers
// ---------------------------------------------------------------------------
__device__ __forceinline__ void mma_bf16(float* d,
                                         unsigned a0, unsigned a1, unsigned a2, unsigned a3,
                                         unsigned b0, unsigned b1) {
    asm volatile(
        "mma.sync.aligned.m16n8k16.row.col.f32.bf16.bf16.f32 "
        "{%0,%1,%2,%3}, {%4,%5,%6,%7}, {%8,%9}, {%0,%1,%2,%3};\n"
        : "+f"(d[0]), "+f"(d[1]), "+f"(d[2]), "+f"(d[3])
        : "r"(a0), "r"(a1), "r"(a2), "r"(a3), "r"(b0), "r"(b1));
}

// D += Ah*Bh + Ah*Bl + Al*Bh   (drop Al*Bl ~ 2^-18)
__device__ __forceinline__ void mma3b(float* d,
                                      const unsigned* ah, const unsigned* al,
                                      unsigned bh0, unsigned bh1,
                                      unsigned bl0, unsigned bl1) {
    mma_bf16(d, ah[0], ah[1], ah[2], ah[3], bh0, bh1);
    mma_bf16(d, ah[0], ah[1], ah[2], ah[3], bl0, bl1);
    mma_bf16(d, al[0], al[1], al[2], al[3], bh0, bh1);
}

// split two floats into packed-bf16 hi word + lo word (x0 -> low half)
__device__ __forceinline__ void split2(float x0, float x1, unsigned& hi, unsigned& lo) {
    __nv_bfloat162 h = __floats2bfloat162_rn(x0, x1);
    float2 hf = __bfloat1622float2(h);
    __nv_bfloat162 l = __floats2bfloat162_rn(x0 - hf.x, x1 - hf.y);
    hi = *(unsigned*)&h;
    lo = *(unsigned*)&l;
}

__device__ __forceinline__ unsigned smem_u32(const void* p) {
    return (unsigned)__cvta_generic_to_shared(p);
}

__device__ __forceinline__ void ldsm_x4(unsigned& r0, unsigned& r1,
                                        unsigned& r2, unsigned& r3, unsigned addr) {
    asm volatile(
        "ldmatrix.sync.aligned.m8n8.x4.shared.b16 {%0,%1,%2,%3}, [%4];"
        : "=r"(r0), "=r"(r1), "=r"(r2), "=r"(r3) : "r"(addr));
}

__device__ __forceinline__ void ldsm_x4_trans(unsigned& r0, unsigned& r1,
                                              unsigned& r2, unsigned& r3,
                                              unsigned addr) {
    asm volatile(
        "ldmatrix.sync.aligned.m8n8.x4.trans.shared.b16 {%0,%1,%2,%3}, [%4];"
        : "=r"(r0), "=r"(r1), "=r"(r2), "=r"(r3) : "r"(addr));
}

// decode packed mask+idx -> additive term using smem bias column
__device__ __forceinline__ float mi_term(unsigned wv, const float* bias_sm) {
    float mv = __half2float(__ushort_as_half((unsigned short)(wv >> 16)));
    return bias_sm[wv & 0xffffu] + mv;
}

// ---------------------------------------------------------------------------
// Fill spatial bins: exp(linspace(0, log(257), 32))
// ---------------------------------------------------------------------------
__global__ void init_bins_kernel() {
    int i = threadIdx.x;
    if (i < NSP) {
        double L = log(257.0);
        g_sbins[i] = (float)exp((double)i * (L / 31.0));
    }
}

// ---------------------------------------------------------------------------
// 3xBF16 GEMM: C[m,o] = sum_k A[m,k] * W[o,k] + bias[o]
// mode 0: C row-major fp32; mode 1: scatter bf16 hi/lo planes in (b,h,n,d)
// Tile 128x128, BK=32, 256 threads (8 warps, 4x2, warp tile 32x64)
// ---------------------------------------------------------------------------
#define BKW 20

struct QKVArgs {
    const float* A0; const float* A1; const float* A2;
    const float* W0; const float* W1; const float* W2;
    const float* b0; const float* b1; const float* b2;
    __nv_bfloat16* Ch0; __nv_bfloat16* Cl0;
    __nv_bfloat16* Ch1; __nv_bfloat16* Cl1;
    __nv_bfloat16* Ch2; __nv_bfloat16* Cl2;
    float* C0;
};

__global__ __launch_bounds__(256) void gemm_bf16_kernel(QKVArgs args, int mode) {
    __shared__ unsigned Ah[128 * BKW], Al[128 * BKW];
    __shared__ unsigned Bh[128 * BKW], Bl[128 * BKW];

    int z = blockIdx.z;
    const float* A    = (z == 0) ? args.A0 : (z == 1) ? args.A1 : args.A2;
    const float* W    = (z == 0) ? args.W0 : (z == 1) ? args.W1 : args.W2;
    const float* bias = (z == 0) ? args.b0 : (z == 1) ? args.b1 : args.b2;
    __nv_bfloat16* Ch = (z == 0) ? args.Ch0 : (z == 1) ? args.Ch1 : args.Ch2;
    __nv_bfloat16* Cl = (z == 0) ? args.Cl0 : (z == 1) ? args.Cl1 : args.Cl2;

    const int K = DD, O = DD;
    int tid = threadIdx.x;
    int lane = tid & 31;
    int wid = tid >> 5;
    int warp_m = wid & 3;
    int warp_n = wid >> 2;
    int row0 = blockIdx.y * 128;
    int col0 = blockIdx.x * 128;
    int lg = lane >> 2;
    int lt = lane & 3;

    float acc[2][8][4];
#pragma unroll
    for (int mf = 0; mf < 2; mf++)
#pragma unroll
        for (int nf = 0; nf < 8; nf++)
#pragma unroll
            for (int zz = 0; zz < 4; zz++) acc[mf][nf][zz] = 0.0f;

    for (int k0 = 0; k0 < K; k0 += 32) {
#pragma unroll
        for (int i = 0; i < 4; i++) {
            int f = tid + 256 * i;      // 0..1023
            int r = f >> 3, c4 = f & 7;
            float4 a4 = *(const float4*)&A[(size_t)(row0 + r) * K + k0 + c4 * 4];
            float4 w4 = *(const float4*)&W[(size_t)(col0 + r) * K + k0 + c4 * 4];
            unsigned h0, l0, h1, l1;
            split2(a4.x, a4.y, h0, l0); split2(a4.z, a4.w, h1, l1);
            Ah[r * BKW + c4 * 2] = h0; Ah[r * BKW + c4 * 2 + 1] = h1;
            Al[r * BKW + c4 * 2] = l0; Al[r * BKW + c4 * 2 + 1] = l1;
            split2(w4.x, w4.y, h0, l0); split2(w4.z, w4.w, h1, l1);
            Bh[r * BKW + c4 * 2] = h0; Bh[r * BKW + c4 * 2 + 1] = h1;
            Bl[r * BKW + c4 * 2] = l0; Bl[r * BKW + c4 * 2 + 1] = l1;
        }
        __syncthreads();

#pragma unroll
        for (int kf = 0; kf < 2; kf++) {
            unsigned bh[8][2], bl[8][2];
#pragma unroll
            for (int nf = 0; nf < 8; nf++) {
                int o = warp_n * 64 + nf * 8 + lg;
                int wb = o * BKW + kf * 8 + lt;
                bh[nf][0] = Bh[wb]; bh[nf][1] = Bh[wb + 4];
                bl[nf][0] = Bl[wb]; bl[nf][1] = Bl[wb + 4];
            }
#pragma unroll
            for (int mf = 0; mf < 2; mf++) {
                int m = warp_m * 32 + mf * 16 + lg;
                int wa = m * BKW + kf * 8 + lt;
                unsigned ah[4], al[4];
                ah[0] = Ah[wa];           ah[1] = Ah[wa + 8 * BKW];
                ah[2] = Ah[wa + 4];       ah[3] = Ah[wa + 8 * BKW + 4];
                al[0] = Al[wa];           al[1] = Al[wa + 8 * BKW];
                al[2] = Al[wa + 4];       al[3] = Al[wa + 8 * BKW + 4];
#pragma unroll
                for (int nf = 0; nf < 8; nf++)
                    mma3b(acc[mf][nf], ah, al,
                          bh[nf][0], bh[nf][1], bl[nf][0], bl[nf][1]);
            }
        }
        __syncthreads();
    }

    // Epilogue
#pragma unroll
    for (int mf = 0; mf < 2; mf++) {
#pragma unroll
        for (int nf = 0; nf < 8; nf++) {
            int rr = row0 + warp_m * 32 + mf * 16 + lg;
            int cc = col0 + warp_n * 64 + nf * 8 + lt * 2;
            float b0 = bias[cc], b1 = bias[cc + 1];
#pragma unroll
            for (int half = 0; half < 2; half++) {
                int m = rr + half * 8;
                float v0 = acc[mf][nf][half * 2 + 0] + b0;
                float v1 = acc[mf][nf][half * 2 + 1] + b1;
                if (mode == 0) {
                    *(float2*)&args.C0[(size_t)m * O + cc] = make_float2(v0, v1);
                } else {
                    int b = m >> 10, n = m & (NN - 1);
                    int h = cc >> 6, d = cc & (HD - 1);
                    size_t widx = (((((size_t)b * HH + h) * NN) + n) * HD + d) >> 1;
                    unsigned hw, lw;
                    split2(v0, v1, hw, lw);
                    ((unsigned*)Ch)[widx] = hw;
                    ((unsigned*)Cl)[widx] = lw;
                }
            }
        }
    }
}

// ---------------------------------------------------------------------------
// Precompute per-pair packed (fp16 mask | u16 idx)
// ---------------------------------------------------------------------------
__global__ void precompute_kernel(const float* __restrict__ coords) {
    int gid = blockIdx.x * 256 + threadIdx.x;   // 0 .. B*N*N-1 (4M)
    int b = gid >> 20;
    int rem = gid & ((1 << 20) - 1);
    int i = rem >> 10;
    int j = rem & 1023;

    const float* ci = coords + ((size_t)b * NN + i) * 3;
    const float* cj = coords + ((size_t)b * NN + j) * 3;
    float ti = ci[0], yi = ci[1], xi = ci[2];
    float tj = cj[0], yj = cj[1], xj = cj[2];

    float dy = yi - yj, dx = xi - xj, dt = ti - tj;
    float sp2 = dy * dy + dx * dx;
    float sd = sqrtf(fmaxf(sp2, 0.0f));
    float fd = sqrtf(fmaxf(dt * dt + dy * dy + dx * dx, 0.0f));

    int c = 0;
#pragma unroll
    for (int s = 0; s < NSP; s++) c += (g_sbins[s] < sd) ? 1 : 0;
    int sidx = min(c, NSP - 1);

    int tc = (int)ceilf(dt + 16.0f);
    tc = max(0, min(2 * NTMP, tc));

    float maskval = (sd > 256.0f ? -1000.0f : 0.0f) + expf(-0.1f * fd);
    unsigned short hb = __half_as_ushort(__float2half_rn(maskval));
    g_mi[gid] = ((unsigned)hb << 16) | (unsigned)(sidx + tc * NSP);
}

// ---------------------------------------------------------------------------
// Flash attention, 3xBF16, pre-split operands, P in registers,
// packed mask+idx, bias column cached in smem.
// grid: (N/128, B*H). block: 256 threads (8 warps); warp w owns q rows w*16..+16
// ---------------------------------------------------------------------------
#define PW 36
#define PLANE (64 * PW)
#define NBIAS ((2 * NTMP + 1) * NSP)   // 1056

__global__ __launch_bounds__(256) void attn_kernel(const float* __restrict__ bias_table) {
    __shared__ unsigned kh[PLANE], kl[PLANE], vh[PLANE], vl[PLANE];
    __shared__ float bias_sm[NBIAS];

    int bh_ = blockIdx.y;             // 0..31
    int b = bh_ >> 3, h = bh_ & 7;
    int i0 = blockIdx.x * 128;
    int tid = threadIdx.x;
    int lane = tid & 31;
    int w = tid >> 5;                 // 0..7
    int lg = lane >> 2;
    int lt = lane & 3;
    int m = w * 16 + lg;              // q row within tile (first of pair)

    // bias column for this head into smem
    for (int i = tid; i < NBIAS; i += 256)
        bias_sm[i] = bias_table[i * HH + h];

    // Q A-fragments loaded straight from global bf16 planes (one-time)
    unsigned qhf[4][4], qlf[4][4];
    {
        const unsigned* qhp = (const unsigned*)g_qbh + ((size_t)bh_ * NN + i0) * (HD / 2);
        const unsigned* qlp = (const unsigned*)g_qbl + ((size_t)bh_ * NN + i0) * (HD / 2);
#pragma unroll
        for (int kf = 0; kf < 4; kf++) {
            int base = m * (HD / 2) + kf * 8 + lt;
            qhf[kf][0] = qhp[base];
            qhf[kf][1] = qhp[base + 8 * (HD / 2)];
            qhf[kf][2] = qhp[base + 4];
            qhf[kf][3] = qhp[base + 8 * (HD / 2) + 4];
            qlf[kf][0] = qlp[base];
            qlf[kf][1] = qlp[base + 8 * (HD / 2)];
            qlf[kf][2] = qlp[base + 4];
            qlf[kf][3] = qlp[base + 8 * (HD / 2) + 4];
        }
    }

    float o[8][4];
#pragma unroll
    for (int nf = 0; nf < 8; nf++)
#pragma unroll
        for (int zz = 0; zz < 4; zz++) o[nf][zz] = 0.0f;
    float m0 = -CUDART_INF_F, m1 = -CUDART_INF_F;
    float l0s = 0.0f, l1s = 0.0f;

    const size_t mirow0 = ((size_t)b * NN + (i0 + m)) * NN;
    const size_t mirow1 = mirow0 + 8 * (size_t)NN;

    const unsigned* kbh = (const unsigned*)g_kbh + (size_t)bh_ * NN * (HD / 2);
    const unsigned* kbl = (const unsigned*)g_kbl + (size_t)bh_ * NN * (HD / 2);
    const unsigned* vbh = (const unsigned*)g_vbh + (size_t)bh_ * NN * (HD / 2);
    const unsigned* vbl = (const unsigned*)g_vbl + (size_t)bh_ * NN * (HD / 2);

    const unsigned k_row = (lane & 7) + ((lane >> 4) << 3);
    const unsigned k_colw = ((lane >> 3) & 1) << 2;
    const unsigned v_row = lane & 15;
    const unsigned v_colw = (lane >> 4) << 2;
    const unsigned kh_base = smem_u32(kh), kl_base = smem_u32(kl);
    const unsigned vh_base = smem_u32(vh), vl_base = smem_u32(vl);

    for (int jt = 0; jt < NN / 64; jt++) {
        int j0 = jt * 64;
        __syncthreads();
        // copy 64x64 bf16 hi/lo K,V tiles (pure copy, uint4)
#pragma unroll
        for (int it = 0; it < 2; it++) {
            int f = tid + 256 * it;       // 0..511
            int row = f >> 3, c4 = f & 7;
            size_t goff = (size_t)(j0 + row) * (HD / 2);
            uint4 t0 = ((const uint4*)(kbh + goff))[c4];
            uint4 t1 = ((const uint4*)(kbl + goff))[c4];
            uint4 t2 = ((const uint4*)(vbh + goff))[c4];
            uint4 t3 = ((const uint4*)(vbl + goff))[c4];
            *(uint4*)&kh[row * PW + c4 * 4] = t0;
            *(uint4*)&kl[row * PW + c4 * 4] = t1;
            *(uint4*)&vh[row * PW + c4 * 4] = t2;
            *(uint4*)&vl[row * PW + c4 * 4] = t3;
        }
        __syncthreads();

        // ---- QK^T (3xBF16), K B-frags via ldmatrix.x4
        float s[8][4];
#pragma unroll
        for (int nf = 0; nf < 8; nf++)
            s[nf][0] = s[nf][1] = s[nf][2] = s[nf][3] = 0.0f;
#pragma unroll
        for (int kf = 0; kf < 4; kf++) {
#pragma unroll
            for (int np = 0; np < 4; np++) {
                unsigned woff = ((np * 16 + k_row) * PW + kf * 8 + k_colw) * 4u;
                unsigned h0, h1, h2, h3, l0_, l1_, l2_, l3_;
                ldsm_x4(h0, h1, h2, h3, kh_base + woff);
                ldsm_x4(l0_, l1_, l2_, l3_, kl_base + woff);
                mma3b(s[2 * np],     qhf[kf], qlf[kf], h0, h1, l0_, l1_);
                mma3b(s[2 * np + 1], qhf[kf], qlf[kf], h2, h3, l2_, l3_);
            }
        }

        // ---- bias + mask (packed loads + smem bias)
#pragma unroll
        for (int nf = 0; nf < 8; nf++) {
            int jc = j0 + nf * 8 + lt * 2;
            uint2 w0 = *(const uint2*)&g_mi[mirow0 + jc];
            uint2 w1 = *(const uint2*)&g_mi[mirow1 + jc];
            s[nf][0] = s[nf][0] * 0.125f + mi_term(w0.x, bias_sm);
            s[nf][1] = s[nf][1] * 0.125f + mi_term(w0.y, bias_sm);
            s[nf][2] = s[nf][2] * 0.125f + mi_term(w1.x, bias_sm);
            s[nf][3] = s[nf][3] * 0.125f + mi_term(w1.y, bias_sm);
        }

        // ---- online softmax (2 rows per thread)
        float t0 = s[0][0], t1 = s[0][2];
#pragma unroll
        for (int nf = 0; nf < 8; nf++) {
            t0 = fmaxf(t0, fmaxf(s[nf][0], s[nf][1]));
            t1 = fmaxf(t1, fmaxf(s[nf][2], s[nf][3]));
        }
        t0 = fmaxf(t0, __shfl_xor_sync(0xffffffffu, t0, 1));
        t0 = fmaxf(t0, __shfl_xor_sync(0xffffffffu, t0, 2));
        t1 = fmaxf(t1, __shfl_xor_sync(0xffffffffu, t1, 1));
        t1 = fmaxf(t1, __shfl_xor_sync(0xffffffffu, t1, 2));
        float nm0 = fmaxf(m0, t0), nm1 = fmaxf(m1, t1);
        float sc0 = __expf(m0 - nm0), sc1 = __expf(m1 - nm1);

        float sum0 = 0.0f, sum1 = 0.0f;
#pragma unroll
        for (int nf = 0; nf < 8; nf++) {
            s[nf][0] = __expf(s[nf][0] - nm0);
            s[nf][1] = __expf(s[nf][1] - nm0);
            s[nf][2] = __expf(s[nf][2] - nm1);
            s[nf][3] = __expf(s[nf][3] - nm1);
            sum0 += s[nf][0] + s[nf][1];
            sum1 += s[nf][2] + s[nf][3];
        }
        sum0 += __shfl_xor_sync(0xffffffffu, sum0, 1);
        sum0 += __shfl_xor_sync(0xffffffffu, sum0, 2);
        sum1 += __shfl_xor_sync(0xffffffffu, sum1, 1);
        sum1 += __shfl_xor_sync(0xffffffffu, sum1, 2);
        l0s = l0s * sc0 + sum0;
        l1s = l1s * sc1 + sum1;
        m0 = nm0; m1 = nm1;
#pragma unroll
        for (int nf = 0; nf < 8; nf++) {
            o[nf][0] *= sc0; o[nf][1] *= sc0;
            o[nf][2] *= sc1; o[nf][3] *= sc1;
        }

        // ---- PV (3xBF16): P A-fragments packed directly from registers
#pragma unroll
        for (int kf = 0; kf < 4; kf++) {
            unsigned phf[4], plf[4];
            split2(s[2 * kf][0],     s[2 * kf][1],     phf[0], plf[0]);
            split2(s[2 * kf][2],     s[2 * kf][3],     phf[1], plf[1]);
            split2(s[2 * kf + 1][0], s[2 * kf + 1][1], phf[2], plf[2]);
            split2(s[2 * kf + 1][2], s[2 * kf + 1][3], phf[3], plf[3]);
            unsigned vrow = kf * 16 + v_row;
#pragma unroll
            for (int nf2 = 0; nf2 < 4; nf2++) {
                unsigned woff = (vrow * PW + nf2 * 8 + v_colw) * 4u;
                unsigned h0, h1, h2, h3, l0_, l1_, l2_, l3_;
                ldsm_x4_trans(h0, h1, h2, h3, vh_base + woff);
                ldsm_x4_trans(l0_, l1_, l2_, l3_, vl_base + woff);
                mma3b(o[2 * nf2],     phf, plf, h0, h1, l0_, l1_);
                mma3b(o[2 * nf2 + 1], phf, plf, h2, h3, l2_, l3_);
            }
        }
    }

    float inv0 = 1.0f / l0s;
    float inv1 = 1.0f / l1s;
    int r0 = i0 + m;
#pragma unroll
    for (int nf = 0; nf < 8; nf++) {
        int cc = h * HD + nf * 8 + lt * 2;
        *(float2*)&g_y[(size_t)(b * NN + r0) * DD + cc] =
            make_float2(o[nf][0] * inv0, o[nf][1] * inv0);
        *(float2*)&g_y[(size_t)(b * NN + r0 + 8) * DD + cc] =
            make_float2(o[nf][2] * inv1, o[nf][3] * inv1);
    }
}

// ---------------------------------------------------------------------------
// Host launch
// ---------------------------------------------------------------------------
extern "C" void kernel_launch(void* const* d_in, const int* in_sizes, int n_in,
                              void* d_out, int out_size) {
    const float* query = (const float*)d_in[0];
    const float* key   = (const float*)d_in[1];
    const float* value = (const float*)d_in[2];
    const float* coords = (const float*)d_in[3];
    const float* Wq = (const float*)d_in[4];
    const float* bq = (const float*)d_in[5];
    const float* Wk = (const float*)d_in[6];
    const float* bk = (const float*)d_in[7];
    const float* Wv = (const float*)d_in[8];
    const float* bv = (const float*)d_in[9];
    const float* Wo = (const float*)d_in[10];
    const float* bo = (const float*)d_in[11];
    const float* bias_table = (const float*)d_in[12];
    float* out = (float*)d_out;

    __nv_bfloat16 *qbh, *qbl, *kbh, *kbl, *vbh, *vbl;
    float* gy;
    cudaGetSymbolAddress((void**)&qbh, g_qbh);
    cudaGetSymbolAddress((void**)&qbl, g_qbl);
    cudaGetSymbolAddress((void**)&kbh, g_kbh);
    cudaGetSymbolAddress((void**)&kbl, g_kbl);
    cudaGetSymbolAddress((void**)&vbh, g_vbh);
    cudaGetSymbolAddress((void**)&vbl, g_vbl);
    cudaGetSymbolAddress((void**)&gy, g_y);

    init_bins_kernel<<<1, 32>>>();

    // Fused QKV projections -> bf16 hi/lo planes
    QKVArgs qa;
    qa.A0 = query; qa.A1 = key; qa.A2 = value;
    qa.W0 = Wq;    qa.W1 = Wk;  qa.W2 = Wv;
    qa.b0 = bq;    qa.b1 = bk;  qa.b2 = bv;
    qa.Ch0 = qbh;  qa.Cl0 = qbl;
    qa.Ch1 = kbh;  qa.Cl1 = kbl;
    qa.Ch2 = vbh;  qa.Cl2 = vbl;
    qa.C0 = nullptr;
    gemm_bf16_kernel<<<dim3(DD / 128, (BB * NN) / 128, 3), 256>>>(qa, 1);

    precompute_kernel<<<(BB * NN * NN) / 256, 256>>>(coords);
    attn_kernel<<<dim3(NN / 128, BB * HH), 256>>>(bias_table);

    // Output projection (fp32 in, fp32 out)
    QKVArgs oa;
    oa.A0 = gy; oa.A1 = gy; oa.A2 = gy;
    oa.W0 = Wo; oa.W1 = Wo; oa.W2 = Wo;
    oa.b0 = bo; oa.b1 = bo; oa.b2 = bo;
    oa.Ch0 = nullptr; oa.Cl0 = nullptr;
    oa.Ch1 = nullptr; oa.Cl1 = nullptr;
    oa.Ch2 = nullptr; oa.Cl2 = nullptr;
    oa.C0 = out;
    gemm_bf16_kernel<<<dim3(DD / 128, (BB * NN) / 128, 1), 256>>>(oa, 0);
}

// round 10
// speedup vs baseline: 4.5101x; 1.0815x over previous
#include <cuda_runtime.h>
#include <cuda_bf16.h>
#include <cuda_fp16.h>
#include <math_constants.h>

// Problem constants
#define BB 4
#define NN 1024
#define DD 512
#define HH 8
#define HD 64
#define NSP 32
#define NTMP 16

// Scratch (device globals; no allocations allowed)
__device__ __nv_bfloat16 g_qbh[BB * HH * NN * HD];  // Q bf16 hi plane (b,h,n,d)
__device__ __nv_bfloat16 g_qbl[BB * HH * NN * HD];  // Q bf16 lo plane
__device__ __nv_bfloat16 g_kbh[BB * HH * NN * HD];
__device__ __nv_bfloat16 g_kbl[BB * HH * NN * HD];
__device__ __nv_bfloat16 g_vbh[BB * HH * NN * HD];
__device__ __nv_bfloat16 g_vbl[BB * HH * NN * HD];
__device__ float g_y[BB * NN * DD];        // attention out (b,n,h*HD+d)
__device__ unsigned g_mi[BB * NN * NN];    // packed: fp16(mask) << 16 | idx
__device__ float g_sbins[NSP];

// ---------------------------------------------------------------------------
// bf16 m16n8k16 mma + 3xBF16 split helpers
// ---------------------------------------------------------------------------
__device__ __forceinline__ void mma_bf16(float* d,
                                         unsigned a0, unsigned a1, unsigned a2, unsigned a3,
                                         unsigned b0, unsigned b1) {
    asm volatile(
        "mma.sync.aligned.m16n8k16.row.col.f32.bf16.bf16.f32 "
        "{%0,%1,%2,%3}, {%4,%5,%6,%7}, {%8,%9}, {%0,%1,%2,%3};\n"
        : "+f"(d[0]), "+f"(d[1]), "+f"(d[2]), "+f"(d[3])
        : "r"(a0), "r"(a1), "r"(a2), "r"(a3), "r"(b0), "r"(b1));
}

// D += Ah*Bh + Ah*Bl + Al*Bh   (drop Al*Bl ~ 2^-18)
__device__ __forceinline__ void mma3b(float* d,
                                      const unsigned* ah, const unsigned* al,
                                      unsigned bh0, unsigned bh1,
                                      unsigned bl0, unsigned bl1) {
    mma_bf16(d, ah[0], ah[1], ah[2], ah[3], bh0, bh1);
    mma_bf16(d, ah[0], ah[1], ah[2], ah[3], bl0, bl1);
    mma_bf16(d, al[0], al[1], al[2], al[3], bh0, bh1);
}

// split two floats into packed-bf16 hi word + lo word (x0 -> low half)
__device__ __forceinline__ void split2(float x0, float x1, unsigned& hi, unsigned& lo) {
    __nv_bfloat162 h = __floats2bfloat162_rn(x0, x1);
    float2 hf = __bfloat1622float2(h);
    __nv_bfloat162 l = __floats2bfloat162_rn(x0 - hf.x, x1 - hf.y);
    hi = *(unsigned*)&h;
    lo = *(unsigned*)&l;
}

__device__ __forceinline__ unsigned smem_u32(const void* p) {
    return (unsigned)__cvta_generic_to_shared(p);
}

__device__ __forceinline__ void ldsm_x4(unsigned& r0, unsigned& r1,
                                        unsigned& r2, unsigned& r3, unsigned addr) {
    asm volatile(
        "ldmatrix.sync.aligned.m8n8.x4.shared.b16 {%0,%1,%2,%3}, [%4];"
        : "=r"(r0), "=r"(r1), "=r"(r2), "=r"(r3) : "r"(addr));
}

__device__ __forceinline__ void ldsm_x4_trans(unsigned& r0, unsigned& r1,
                                              unsigned& r2, unsigned& r3,
                                              unsigned addr) {
    asm volatile(
        "ldmatrix.sync.aligned.m8n8.x4.trans.shared.b16 {%0,%1,%2,%3}, [%4];"
        : "=r"(r0), "=r"(r1), "=r"(r2), "=r"(r3) : "r"(addr));
}

// decode packed mask+idx -> additive term using smem bias column
__device__ __forceinline__ float mi_term(unsigned wv, const float* bias_sm) {
    float mv = __half2float(__ushort_as_half((unsigned short)(wv >> 16)));
    return bias_sm[wv & 0xffffu] + mv;
}

// ---------------------------------------------------------------------------
// Fill spatial bins: exp(linspace(0, log(257), 32))
// ---------------------------------------------------------------------------
__global__ void init_bins_kernel() {
    int i = threadIdx.x;
    if (i < NSP) {
        double L = log(257.0);
        g_sbins[i] = (float)exp((double)i * (L / 31.0));
    }
}

// ---------------------------------------------------------------------------
// 3xBF16 GEMM: C[m,o] = sum_k A[m,k] * W[o,k] + bias[o]
// mode 0: C row-major fp32; mode 1: scatter bf16 hi/lo planes in (b,h,n,d)
// Tile 128x128, BK=32, 256 threads (8 warps, 4x2, warp tile 32x64)
// ---------------------------------------------------------------------------
#define BKW 20

struct QKVArgs {
    const float* A0; const float* A1; const float* A2;
    const float* W0; const float* W1; const float* W2;
    const float* b0; const float* b1; const float* b2;
    __nv_bfloat16* Ch0; __nv_bfloat16* Cl0;
    __nv_bfloat16* Ch1; __nv_bfloat16* Cl1;
    __nv_bfloat16* Ch2; __nv_bfloat16* Cl2;
    float* C0;
};

__global__ __launch_bounds__(256) void gemm_bf16_kernel(QKVArgs args, int mode) {
    __shared__ unsigned Ah[128 * BKW], Al[128 * BKW];
    __shared__ unsigned Bh[128 * BKW], Bl[128 * BKW];

    int z = blockIdx.z;
    const float* A    = (z == 0) ? args.A0 : (z == 1) ? args.A1 : args.A2;
    const float* W    = (z == 0) ? args.W0 : (z == 1) ? args.W1 : args.W2;
    const float* bias = (z == 0) ? args.b0 : (z == 1) ? args.b1 : args.b2;
    __nv_bfloat16* Ch = (z == 0) ? args.Ch0 : (z == 1) ? args.Ch1 : args.Ch2;
    __nv_bfloat16* Cl = (z == 0) ? args.Cl0 : (z == 1) ? args.Cl1 : args.Cl2;

    const int K = DD, O = DD;
    int tid = threadIdx.x;
    int lane = tid & 31;
    int wid = tid >> 5;
    int warp_m = wid & 3;
    int warp_n = wid >> 2;
    int row0 = blockIdx.y * 128;
    int col0 = blockIdx.x * 128;
    int lg = lane >> 2;
    int lt = lane & 3;

    float acc[2][8][4];
#pragma unroll
    for (int mf = 0; mf < 2; mf++)
#pragma unroll
        for (int nf = 0; nf < 8; nf++)
#pragma unroll
            for (int zz = 0; zz < 4; zz++) acc[mf][nf][zz] = 0.0f;

    for (int k0 = 0; k0 < K; k0 += 32) {
#pragma unroll
        for (int i = 0; i < 4; i++) {
            int f = tid + 256 * i;      // 0..1023
            int r = f >> 3, c4 = f & 7;
            float4 a4 = *(const float4*)&A[(size_t)(row0 + r) * K + k0 + c4 * 4];
            float4 w4 = *(const float4*)&W[(size_t)(col0 + r) * K + k0 + c4 * 4];
            unsigned h0, l0, h1, l1;
            split2(a4.x, a4.y, h0, l0); split2(a4.z, a4.w, h1, l1);
            Ah[r * BKW + c4 * 2] = h0; Ah[r * BKW + c4 * 2 + 1] = h1;
            Al[r * BKW + c4 * 2] = l0; Al[r * BKW + c4 * 2 + 1] = l1;
            split2(w4.x, w4.y, h0, l0); split2(w4.z, w4.w, h1, l1);
            Bh[r * BKW + c4 * 2] = h0; Bh[r * BKW + c4 * 2 + 1] = h1;
            Bl[r * BKW + c4 * 2] = l0; Bl[r * BKW + c4 * 2 + 1] = l1;
        }
        __syncthreads();

#pragma unroll
        for (int kf = 0; kf < 2; kf++) {
            unsigned bh[8][2], bl[8][2];
#pragma unroll
            for (int nf = 0; nf < 8; nf++) {
                int o = warp_n * 64 + nf * 8 + lg;
                int wb = o * BKW + kf * 8 + lt;
                bh[nf][0] = Bh[wb]; bh[nf][1] = Bh[wb + 4];
                bl[nf][0] = Bl[wb]; bl[nf][1] = Bl[wb + 4];
            }
#pragma unroll
            for (int mf = 0; mf < 2; mf++) {
                int m = warp_m * 32 + mf * 16 + lg;
                int wa = m * BKW + kf * 8 + lt;
                unsigned ah[4], al[4];
                ah[0] = Ah[wa];           ah[1] = Ah[wa + 8 * BKW];
                ah[2] = Ah[wa + 4];       ah[3] = Ah[wa + 8 * BKW + 4];
                al[0] = Al[wa];           al[1] = Al[wa + 8 * BKW];
                al[2] = Al[wa + 4];       al[3] = Al[wa + 8 * BKW + 4];
#pragma unroll
                for (int nf = 0; nf < 8; nf++)
                    mma3b(acc[mf][nf], ah, al,
                          bh[nf][0], bh[nf][1], bl[nf][0], bl[nf][1]);
            }
        }
        __syncthreads();
    }

    // Epilogue
#pragma unroll
    for (int mf = 0; mf < 2; mf++) {
#pragma unroll
        for (int nf = 0; nf < 8; nf++) {
            int rr = row0 + warp_m * 32 + mf * 16 + lg;
            int cc = col0 + warp_n * 64 + nf * 8 + lt * 2;
            float b0 = bias[cc], b1 = bias[cc + 1];
#pragma unroll
            for (int half = 0; half < 2; half++) {
                int m = rr + half * 8;
                float v0 = acc[mf][nf][half * 2 + 0] + b0;
                float v1 = acc[mf][nf][half * 2 + 1] + b1;
                if (mode == 0) {
                    *(float2*)&args.C0[(size_t)m * O + cc] = make_float2(v0, v1);
                } else {
                    int b = m >> 10, n = m & (NN - 1);
                    int h = cc >> 6, d = cc & (HD - 1);
                    size_t widx = (((((size_t)b * HH + h) * NN) + n) * HD + d) >> 1;
                    unsigned hw, lw;
                    split2(v0, v1, hw, lw);
                    ((unsigned*)Ch)[widx] = hw;
                    ((unsigned*)Cl)[widx] = lw;
                }
            }
        }
    }
}

// ---------------------------------------------------------------------------
// Precompute per-pair packed (fp16 mask | u16 idx)
// ---------------------------------------------------------------------------
__global__ void precompute_kernel(const float* __restrict__ coords) {
    int gid = blockIdx.x * 256 + threadIdx.x;   // 0 .. B*N*N-1 (4M)
    int b = gid >> 20;
    int rem = gid & ((1 << 20) - 1);
    int i = rem >> 10;
    int j = rem & 1023;

    const float* ci = coords + ((size_t)b * NN + i) * 3;
    const float* cj = coords + ((size_t)b * NN + j) * 3;
    float ti = ci[0], yi = ci[1], xi = ci[2];
    float tj = cj[0], yj = cj[1], xj = cj[2];

    float dy = yi - yj, dx = xi - xj, dt = ti - tj;
    float sp2 = dy * dy + dx * dx;
    float sd = sqrtf(fmaxf(sp2, 0.0f));
    float fd = sqrtf(fmaxf(dt * dt + dy * dy + dx * dx, 0.0f));

    int c = 0;
#pragma unroll
    for (int s = 0; s < NSP; s++) c += (g_sbins[s] < sd) ? 1 : 0;
    int sidx = min(c, NSP - 1);

    int tc = (int)ceilf(dt + 16.0f);
    tc = max(0, min(2 * NTMP, tc));

    float maskval = (sd > 256.0f ? -1000.0f : 0.0f) + expf(-0.1f * fd);
    unsigned short hb = __half_as_ushort(__float2half_rn(maskval));
    g_mi[gid] = ((unsigned)hb << 16) | (unsigned)(sidx + tc * NSP);
}

// ---------------------------------------------------------------------------
// Flash attention, 3xBF16 QK and PV, pre-split operands, P in registers,
// packed mask+idx, bias column cached in smem. 2 CTAs/SM.
// grid: (N/128, B*H). block: 256 threads (8 warps); warp w owns q rows w*16..+16
// ---------------------------------------------------------------------------
#define PW 36
#define PLANE (64 * PW)
#define NBIAS ((2 * NTMP + 1) * NSP)   // 1056

__global__ void __launch_bounds__(256, 2) attn_kernel(const float* __restrict__ bias_table) {
    __shared__ unsigned kh[PLANE], kl[PLANE], vh[PLANE], vl[PLANE];
    __shared__ float bias_sm[NBIAS];

    int bh_ = blockIdx.y;             // 0..31
    int b = bh_ >> 3, h = bh_ & 7;
    int i0 = blockIdx.x * 128;
    int tid = threadIdx.x;
    int lane = tid & 31;
    int w = tid >> 5;                 // 0..7
    int lg = lane >> 2;
    int lt = lane & 3;
    int m = w * 16 + lg;              // q row within tile (first of pair)

    // bias column for this head into smem
    for (int i = tid; i < NBIAS; i += 256)
        bias_sm[i] = bias_table[i * HH + h];

    // Q A-fragments loaded straight from global bf16 planes (one-time)
    unsigned qhf[4][4], qlf[4][4];
    {
        const unsigned* qhp = (const unsigned*)g_qbh + ((size_t)bh_ * NN + i0) * (HD / 2);
        const unsigned* qlp = (const unsigned*)g_qbl + ((size_t)bh_ * NN + i0) * (HD / 2);
#pragma unroll
        for (int kf = 0; kf < 4; kf++) {
            int base = m * (HD / 2) + kf * 8 + lt;
            qhf[kf][0] = qhp[base];
            qhf[kf][1] = qhp[base + 8 * (HD / 2)];
            qhf[kf][2] = qhp[base + 4];
            qhf[kf][3] = qhp[base + 8 * (HD / 2) + 4];
            qlf[kf][0] = qlp[base];
            qlf[kf][1] = qlp[base + 8 * (HD / 2)];
            qlf[kf][2] = qlp[base + 4];
            qlf[kf][3] = qlp[base + 8 * (HD / 2) + 4];
        }
    }

    float o[8][4];
#pragma unroll
    for (int nf = 0; nf < 8; nf++)
#pragma unroll
        for (int zz = 0; zz < 4; zz++) o[nf][zz] = 0.0f;
    float m0 = -CUDART_INF_F, m1 = -CUDART_INF_F;
    float l0s = 0.0f, l1s = 0.0f;

    const size_t mirow0 = ((size_t)b * NN + (i0 + m)) * NN;
    const size_t mirow1 = mirow0 + 8 * (size_t)NN;

    const unsigned* kbh = (const unsigned*)g_kbh + (size_t)bh_ * NN * (HD / 2);
    const unsigned* kbl = (const unsigned*)g_kbl + (size_t)bh_ * NN * (HD / 2);
    const unsigned* vbh = (const unsigned*)g_vbh + (size_t)bh_ * NN * (HD / 2);
    const unsigned* vbl = (const unsigned*)g_vbl + (size_t)bh_ * NN * (HD / 2);

    const unsigned k_row = (lane & 7) + ((lane >> 4) << 3);
    const unsigned k_colw = ((lane >> 3) & 1) << 2;
    const unsigned v_row = lane & 15;
    const unsigned v_colw = (lane >> 4) << 2;
    const unsigned kh_base = smem_u32(kh), kl_base = smem_u32(kl);
    const unsigned vh_base = smem_u32(vh), vl_base = smem_u32(vl);

    for (int jt = 0; jt < NN / 64; jt++) {
        int j0 = jt * 64;
        __syncthreads();
        // copy 64x64 bf16 hi/lo K,V tiles (pure copy, uint4)
#pragma unroll
        for (int it = 0; it < 2; it++) {
            int f = tid + 256 * it;       // 0..511
            int row = f >> 3, c4 = f & 7;
            size_t goff = (size_t)(j0 + row) * (HD / 2);
            uint4 t0 = ((const uint4*)(kbh + goff))[c4];
            uint4 t1 = ((const uint4*)(kbl + goff))[c4];
            uint4 t2 = ((const uint4*)(vbh + goff))[c4];
            uint4 t3 = ((const uint4*)(vbl + goff))[c4];
            *(uint4*)&kh[row * PW + c4 * 4] = t0;
            *(uint4*)&kl[row * PW + c4 * 4] = t1;
            *(uint4*)&vh[row * PW + c4 * 4] = t2;
            *(uint4*)&vl[row * PW + c4 * 4] = t3;
        }
        __syncthreads();

        // ---- QK^T (3xBF16), K B-frags via ldmatrix.x4
        float s[8][4];
#pragma unroll
        for (int nf = 0; nf < 8; nf++)
            s[nf][0] = s[nf][1] = s[nf][2] = s[nf][3] = 0.0f;
#pragma unroll
        for (int kf = 0; kf < 4; kf++) {
#pragma unroll
            for (int np = 0; np < 4; np++) {
                unsigned woff = ((np * 16 + k_row) * PW + kf * 8 + k_colw) * 4u;
                unsigned h0, h1, h2, h3, l0_, l1_, l2_, l3_;
                ldsm_x4(h0, h1, h2, h3, kh_base + woff);
                ldsm_x4(l0_, l1_, l2_, l3_, kl_base + woff);
                mma3b(s[2 * np],     qhf[kf], qlf[kf], h0, h1, l0_, l1_);
                mma3b(s[2 * np + 1], qhf[kf], qlf[kf], h2, h3, l2_, l3_);
            }
        }

        // ---- bias + mask (packed loads + smem bias)
#pragma unroll
        for (int nf = 0; nf < 8; nf++) {
            int jc = j0 + nf * 8 + lt * 2;
            uint2 w0 = *(const uint2*)&g_mi[mirow0 + jc];
            uint2 w1 = *(const uint2*)&g_mi[mirow1 + jc];
            s[nf][0] = s[nf][0] * 0.125f + mi_term(w0.x, bias_sm);
            s[nf][1] = s[nf][1] * 0.125f + mi_term(w0.y, bias_sm);
            s[nf][2] = s[nf][2] * 0.125f + mi_term(w1.x, bias_sm);
            s[nf][3] = s[nf][3] * 0.125f + mi_term(w1.y, bias_sm);
        }

        // ---- online softmax (2 rows per thread)
        float t0 = s[0][0], t1 = s[0][2];
#pragma unroll
        for (int nf = 0; nf < 8; nf++) {
            t0 = fmaxf(t0, fmaxf(s[nf][0], s[nf][1]));
            t1 = fmaxf(t1, fmaxf(s[nf][2], s[nf][3]));
        }
        t0 = fmaxf(t0, __shfl_xor_sync(0xffffffffu, t0, 1));
        t0 = fmaxf(t0, __shfl_xor_sync(0xffffffffu, t0, 2));
        t1 = fmaxf(t1, __shfl_xor_sync(0xffffffffu, t1, 1));
        t1 = fmaxf(t1, __shfl_xor_sync(0xffffffffu, t1, 2));
        float nm0 = fmaxf(m0, t0), nm1 = fmaxf(m1, t1);
        float sc0 = __expf(m0 - nm0), sc1 = __expf(m1 - nm1);

        float sum0 = 0.0f, sum1 = 0.0f;
#pragma unroll
        for (int nf = 0; nf < 8; nf++) {
            s[nf][0] = __expf(s[nf][0] - nm0);
            s[nf][1] = __expf(s[nf][1] - nm0);
            s[nf][2] = __expf(s[nf][2] - nm1);
            s[nf][3] = __expf(s[nf][3] - nm1);
            sum0 += s[nf][0] + s[nf][1];
            sum1 += s[nf][2] + s[nf][3];
        }
        sum0 += __shfl_xor_sync(0xffffffffu, sum0, 1);
        sum0 += __shfl_xor_sync(0xffffffffu, sum0, 2);
        sum1 += __shfl_xor_sync(0xffffffffu, sum1, 1);
        sum1 += __shfl_xor_sync(0xffffffffu, sum1, 2);
        l0s = l0s * sc0 + sum0;
        l1s = l1s * sc1 + sum1;
        m0 = nm0; m1 = nm1;
#pragma unroll
        for (int nf = 0; nf < 8; nf++) {
            o[nf][0] *= sc0; o[nf][1] *= sc0;
            o[nf][2] *= sc1; o[nf][3] *= sc1;
        }

        // ---- PV (3xBF16): P A-fragments split hi/lo from registers
#pragma unroll
        for (int kf = 0; kf < 4; kf++) {
            unsigned phf[4], plf[4];
            split2(s[2 * kf][0],     s[2 * kf][1],     phf[0], plf[0]);
            split2(s[2 * kf][2],     s[2 * kf][3],     phf[1], plf[1]);
            split2(s[2 * kf + 1][0], s[2 * kf + 1][1], phf[2], plf[2]);
            split2(s[2 * kf + 1][2], s[2 * kf + 1][3], phf[3], plf[3]);
            unsigned vrow = kf * 16 + v_row;
#pragma unroll
            for (int nf2 = 0; nf2 < 4; nf2++) {
                unsigned woff = (vrow * PW + nf2 * 8 + v_colw) * 4u;
                unsigned h0, h1, h2, h3, l0_, l1_, l2_, l3_;
                ldsm_x4_trans(h0, h1, h2, h3, vh_base + woff);
                ldsm_x4_trans(l0_, l1_, l2_, l3_, vl_base + woff);
                mma3b(o[2 * nf2],     phf, plf, h0, h1, l0_, l1_);
                mma3b(o[2 * nf2 + 1], phf, plf, h2, h3, l2_, l3_);
            }
        }
    }

    float inv0 = 1.0f / l0s;
    float inv1 = 1.0f / l1s;
    int r0 = i0 + m;
#pragma unroll
    for (int nf = 0; nf < 8; nf++) {
        int cc = h * HD + nf * 8 + lt * 2;
        *(float2*)&g_y[(size_t)(b * NN + r0) * DD + cc] =
            make_float2(o[nf][0] * inv0, o[nf][1] * inv0);
        *(float2*)&g_y[(size_t)(b * NN + r0 + 8) * DD + cc] =
            make_float2(o[nf][2] * inv1, o[nf][3] * inv1);
    }
}

// ---------------------------------------------------------------------------
// Host launch
// ---------------------------------------------------------------------------
extern "C" void kernel_launch(void* const* d_in, const int* in_sizes, int n_in,
                              void* d_out, int out_size) {
    const float* query = (const float*)d_in[0];
    const float* key   = (const float*)d_in[1];
    const float* value = (const float*)d_in[2];
    const float* coords = (const float*)d_in[3];
    const float* Wq = (const float*)d_in[4];
    const float* bq = (const float*)d_in[5];
    const float* Wk = (const float*)d_in[6];
    const float* bk = (const float*)d_in[7];
    const float* Wv = (const float*)d_in[8];
    const float* bv = (const float*)d_in[9];
    const float* Wo = (const float*)d_in[10];
    const float* bo = (const float*)d_in[11];
    const float* bias_table = (const float*)d_in[12];
    float* out = (float*)d_out;

    __nv_bfloat16 *qbh, *qbl, *kbh, *kbl, *vbh, *vbl;
    float* gy;
    cudaGetSymbolAddress((void**)&qbh, g_qbh);
    cudaGetSymbolAddress((void**)&qbl, g_qbl);
    cudaGetSymbolAddress((void**)&kbh, g_kbh);
    cudaGetSymbolAddress((void**)&kbl, g_kbl);
    cudaGetSymbolAddress((void**)&vbh, g_vbh);
    cudaGetSymbolAddress((void**)&vbl, g_vbl);
    cudaGetSymbolAddress((void**)&gy, g_y);

    init_bins_kernel<<<1, 32>>>();

    // Fused QKV projections -> bf16 hi/lo planes
    QKVArgs qa;
    qa.A0 = query; qa.A1 = key; qa.A2 = value;
    qa.W0 = Wq;    qa.W1 = Wk;  qa.W2 = Wv;
    qa.b0 = bq;    qa.b1 = bk;  qa.b2 = bv;
    qa.Ch0 = qbh;  qa.Cl0 = qbl;
    qa.Ch1 = kbh;  qa.Cl1 = kbl;
    qa.Ch2 = vbh;  qa.Cl2 = vbl;
    qa.C0 = nullptr;
    gemm_bf16_kernel<<<dim3(DD / 128, (BB * NN) / 128, 3), 256>>>(qa, 1);

    precompute_kernel<<<(BB * NN * NN) / 256, 256>>>(coords);
    attn_kernel<<<dim3(NN / 128, BB * HH), 256>>>(bias_table);

    // Output projection (fp32 in, fp32 out)
    QKVArgs oa;
    oa.A0 = gy; oa.A1 = gy; oa.A2 = gy;
    oa.W0 = Wo; oa.W1 = Wo; oa.W2 = Wo;
    oa.b0 = bo; oa.b1 = bo; oa.b2 = bo;
    oa.Ch0 = nullptr; oa.Cl0 = nullptr;
    oa.Ch1 = nullptr; oa.Cl1 = nullptr;
    oa.Ch2 = nullptr; oa.Cl2 = nullptr;
    oa.C0 = out;
    gemm_bf16_kernel<<<dim3(DD / 128, (BB * NN) / 128, 1), 256>>>(oa, 0);
}

// round 12
// speedup vs baseline: 4.5960x; 1.0191x over previous
#include <cuda_runtime.h>
#include <cuda_bf16.h>
#include <cuda_fp16.h>
#include <math_constants.h>

// Problem constants
#define BB 4
#define NN 1024
#define DD 512
#define HH 8
#define HD 64
#define NSP 32
#define NTMP 16

// Scratch (device globals; no allocations allowed)
__device__ __nv_bfloat16 g_qbh[BB * HH * NN * HD];  // Q bf16 hi plane (b,h,n,d)
__device__ __nv_bfloat16 g_qbl[BB * HH * NN * HD];  // Q bf16 lo plane
__device__ __nv_bfloat16 g_kbh[BB * HH * NN * HD];
__device__ __nv_bfloat16 g_kbl[BB * HH * NN * HD];
__device__ __nv_bfloat16 g_vbh[BB * HH * NN * HD];
__device__ __nv_bfloat16 g_vbl[BB * HH * NN * HD];
__device__ float g_y[BB * NN * DD];        // attention out (b,n,h*HD+d)
__device__ unsigned g_mi[BB * NN * NN];    // packed: fp16(mask) << 16 | idx
__device__ float g_sbins[NSP];

// ---------------------------------------------------------------------------
// bf16 m16n8k16 mma + 3xBF16 split helpers
// ---------------------------------------------------------------------------
__device__ __forceinline__ void mma_bf16(float* d,
                                         unsigned a0, unsigned a1, unsigned a2, unsigned a3,
                                         unsigned b0, unsigned b1) {
    asm volatile(
        "mma.sync.aligned.m16n8k16.row.col.f32.bf16.bf16.f32 "
        "{%0,%1,%2,%3}, {%4,%5,%6,%7}, {%8,%9}, {%0,%1,%2,%3};\n"
        : "+f"(d[0]), "+f"(d[1]), "+f"(d[2]), "+f"(d[3])
        : "r"(a0), "r"(a1), "r"(a2), "r"(a3), "r"(b0), "r"(b1));
}

// D += Ah*Bh + Ah*Bl + Al*Bh   (drop Al*Bl ~ 2^-18)
__device__ __forceinline__ void mma3b(float* d,
                                      const unsigned* ah, const unsigned* al,
                                      unsigned bh0, unsigned bh1,
                                      unsigned bl0, unsigned bl1) {
    mma_bf16(d, ah[0], ah[1], ah[2], ah[3], bh0, bh1);
    mma_bf16(d, ah[0], ah[1], ah[2], ah[3], bl0, bl1);
    mma_bf16(d, al[0], al[1], al[2], al[3], bh0, bh1);
}

// split two floats into packed-bf16 hi word + lo word (x0 -> low half)
__device__ __forceinline__ void split2(float x0, float x1, unsigned& hi, unsigned& lo) {
    __nv_bfloat162 h = __floats2bfloat162_rn(x0, x1);
    float2 hf = __bfloat1622float2(h);
    __nv_bfloat162 l = __floats2bfloat162_rn(x0 - hf.x, x1 - hf.y);
    hi = *(unsigned*)&h;
    lo = *(unsigned*)&l;
}

__device__ __forceinline__ unsigned smem_u32(const void* p) {
    return (unsigned)__cvta_generic_to_shared(p);
}

__device__ __forceinline__ void cp_async16(unsigned dst, const void* src) {
    asm volatile("cp.async.cg.shared.global [%0], [%1], 16;\n"
                 :: "r"(dst), "l"(src));
}
__device__ __forceinline__ void cp_async_commit() {
    asm volatile("cp.async.commit_group;\n" ::: "memory");
}
__device__ __forceinline__ void cp_async_wait0() {
    asm volatile("cp.async.wait_group 0;\n" ::: "memory");
}

__device__ __forceinline__ void ldsm_x4(unsigned& r0, unsigned& r1,
                                        unsigned& r2, unsigned& r3, unsigned addr) {
    asm volatile(
        "ldmatrix.sync.aligned.m8n8.x4.shared.b16 {%0,%1,%2,%3}, [%4];"
        : "=r"(r0), "=r"(r1), "=r"(r2), "=r"(r3) : "r"(addr));
}

__device__ __forceinline__ void ldsm_x4_trans(unsigned& r0, unsigned& r1,
                                              unsigned& r2, unsigned& r3,
                                              unsigned addr) {
    asm volatile(
        "ldmatrix.sync.aligned.m8n8.x4.trans.shared.b16 {%0,%1,%2,%3}, [%4];"
        : "=r"(r0), "=r"(r1), "=r"(r2), "=r"(r3) : "r"(addr));
}

// decode packed mask+idx -> additive term using smem bias column
__device__ __forceinline__ float mi_term(unsigned wv, const float* bias_sm) {
    float mv = __half2float(__ushort_as_half((unsigned short)(wv >> 16)));
    return bias_sm[wv & 0xffffu] + mv;
}

// ---------------------------------------------------------------------------
// Fill spatial bins: exp(linspace(0, log(257), 32))
// ---------------------------------------------------------------------------
__global__ void init_bins_kernel() {
    int i = threadIdx.x;
    if (i < NSP) {
        double L = log(257.0);
        g_sbins[i] = (float)exp((double)i * (L / 31.0));
    }
}

// ---------------------------------------------------------------------------
// 3xBF16 GEMM: C[m,o] = sum_k A[m,k] * W[o,k] + bias[o]
// mode 0: C row-major fp32; mode 1: scatter bf16 hi/lo planes in (b,h,n,d)
// Tile 128x128, BK=32, 256 threads (8 warps, 4x2, warp tile 32x64), 2 CTAs/SM
// ---------------------------------------------------------------------------
#define BKW 20

struct QKVArgs {
    const float* A0; const float* A1; const float* A2;
    const float* W0; const float* W1; const float* W2;
    const float* b0; const float* b1; const float* b2;
    __nv_bfloat16* Ch0; __nv_bfloat16* Cl0;
    __nv_bfloat16* Ch1; __nv_bfloat16* Cl1;
    __nv_bfloat16* Ch2; __nv_bfloat16* Cl2;
    float* C0;
};

__global__ void __launch_bounds__(256, 2) gemm_bf16_kernel(QKVArgs args, int mode) {
    __shared__ unsigned Ah[128 * BKW], Al[128 * BKW];
    __shared__ unsigned Bh[128 * BKW], Bl[128 * BKW];

    int z = blockIdx.z;
    const float* A    = (z == 0) ? args.A0 : (z == 1) ? args.A1 : args.A2;
    const float* W    = (z == 0) ? args.W0 : (z == 1) ? args.W1 : args.W2;
    const float* bias = (z == 0) ? args.b0 : (z == 1) ? args.b1 : args.b2;
    __nv_bfloat16* Ch = (z == 0) ? args.Ch0 : (z == 1) ? args.Ch1 : args.Ch2;
    __nv_bfloat16* Cl = (z == 0) ? args.Cl0 : (z == 1) ? args.Cl1 : args.Cl2;

    const int K = DD, O = DD;
    int tid = threadIdx.x;
    int lane = tid & 31;
    int wid = tid >> 5;
    int warp_m = wid & 3;
    int warp_n = wid >> 2;
    int row0 = blockIdx.y * 128;
    int col0 = blockIdx.x * 128;
    int lg = lane >> 2;
    int lt = lane & 3;

    float acc[2][8][4];
#pragma unroll
    for (int mf = 0; mf < 2; mf++)
#pragma unroll
        for (int nf = 0; nf < 8; nf++)
#pragma unroll
            for (int zz = 0; zz < 4; zz++) acc[mf][nf][zz] = 0.0f;

    for (int k0 = 0; k0 < K; k0 += 32) {
#pragma unroll
        for (int i = 0; i < 4; i++) {
            int f = tid + 256 * i;      // 0..1023
            int r = f >> 3, c4 = f & 7;
            float4 a4 = *(const float4*)&A[(size_t)(row0 + r) * K + k0 + c4 * 4];
            float4 w4 = *(const float4*)&W[(size_t)(col0 + r) * K + k0 + c4 * 4];
            unsigned h0, l0, h1, l1;
            split2(a4.x, a4.y, h0, l0); split2(a4.z, a4.w, h1, l1);
            Ah[r * BKW + c4 * 2] = h0; Ah[r * BKW + c4 * 2 + 1] = h1;
            Al[r * BKW + c4 * 2] = l0; Al[r * BKW + c4 * 2 + 1] = l1;
            split2(w4.x, w4.y, h0, l0); split2(w4.z, w4.w, h1, l1);
            Bh[r * BKW + c4 * 2] = h0; Bh[r * BKW + c4 * 2 + 1] = h1;
            Bl[r * BKW + c4 * 2] = l0; Bl[r * BKW + c4 * 2 + 1] = l1;
        }
        __syncthreads();

#pragma unroll
        for (int kf = 0; kf < 2; kf++) {
            unsigned bh[8][2], bl[8][2];
#pragma unroll
            for (int nf = 0; nf < 8; nf++) {
                int o = warp_n * 64 + nf * 8 + lg;
                int wb = o * BKW + kf * 8 + lt;
                bh[nf][0] = Bh[wb]; bh[nf][1] = Bh[wb + 4];
                bl[nf][0] = Bl[wb]; bl[nf][1] = Bl[wb + 4];
            }
#pragma unroll
            for (int mf = 0; mf < 2; mf++) {
                int m = warp_m * 32 + mf * 16 + lg;
                int wa = m * BKW + kf * 8 + lt;
                unsigned ah[4], al[4];
                ah[0] = Ah[wa];           ah[1] = Ah[wa + 8 * BKW];
                ah[2] = Ah[wa + 4];       ah[3] = Ah[wa + 8 * BKW + 4];
                al[0] = Al[wa];           al[1] = Al[wa + 8 * BKW];
                al[2] = Al[wa + 4];       al[3] = Al[wa + 8 * BKW + 4];
#pragma unroll
                for (int nf = 0; nf < 8; nf++)
                    mma3b(acc[mf][nf], ah, al,
                          bh[nf][0], bh[nf][1], bl[nf][0], bl[nf][1]);
            }
        }
        __syncthreads();
    }

    // Epilogue
#pragma unroll
    for (int mf = 0; mf < 2; mf++) {
#pragma unroll
        for (int nf = 0; nf < 8; nf++) {
            int rr = row0 + warp_m * 32 + mf * 16 + lg;
            int cc = col0 + warp_n * 64 + nf * 8 + lt * 2;
            float b0 = bias[cc], b1 = bias[cc + 1];
#pragma unroll
            for (int half = 0; half < 2; half++) {
                int m = rr + half * 8;
                float v0 = acc[mf][nf][half * 2 + 0] + b0;
                float v1 = acc[mf][nf][half * 2 + 1] + b1;
                if (mode == 0) {
                    *(float2*)&args.C0[(size_t)m * O + cc] = make_float2(v0, v1);
                } else {
                    int b = m >> 10, n = m & (NN - 1);
                    int h = cc >> 6, d = cc & (HD - 1);
                    size_t widx = (((((size_t)b * HH + h) * NN) + n) * HD + d) >> 1;
                    unsigned hw, lw;
                    split2(v0, v1, hw, lw);
                    ((unsigned*)Ch)[widx] = hw;
                    ((unsigned*)Cl)[widx] = lw;
                }
            }
        }
    }
}

// ---------------------------------------------------------------------------
// Precompute per-pair packed (fp16 mask | u16 idx)
// ---------------------------------------------------------------------------
__global__ void precompute_kernel(const float* __restrict__ coords) {
    int gid = blockIdx.x * 256 + threadIdx.x;   // 0 .. B*N*N-1 (4M)
    int b = gid >> 20;
    int rem = gid & ((1 << 20) - 1);
    int i = rem >> 10;
    int j = rem & 1023;

    const float* ci = coords + ((size_t)b * NN + i) * 3;
    const float* cj = coords + ((size_t)b * NN + j) * 3;
    float ti = ci[0], yi = ci[1], xi = ci[2];
    float tj = cj[0], yj = cj[1], xj = cj[2];

    float dy = yi - yj, dx = xi - xj, dt = ti - tj;
    float sp2 = dy * dy + dx * dx;
    float sd = sqrtf(fmaxf(sp2, 0.0f));
    float fd = sqrtf(fmaxf(dt * dt + dy * dy + dx * dx, 0.0f));

    int c = 0;
#pragma unroll
    for (int s = 0; s < NSP; s++) c += (g_sbins[s] < sd) ? 1 : 0;
    int sidx = min(c, NSP - 1);

    int tc = (int)ceilf(dt + 16.0f);
    tc = max(0, min(2 * NTMP, tc));

    float maskval = (sd > 256.0f ? -1000.0f : 0.0f) + expf(-0.1f * fd);
    unsigned short hb = __half_as_ushort(__float2half_rn(maskval));
    g_mi[gid] = ((unsigned)hb << 16) | (unsigned)(sidx + tc * NSP);
}

// ---------------------------------------------------------------------------
// Flash attention, 3xBF16 QK and PV, cp.async double-buffered K/V tiles,
// P in registers, packed mask+idx, bias column in smem. 2 CTAs/SM.
// grid: (N/128, B*H). block: 256 threads (8 warps); warp w owns q rows w*16..+16
// dynamic smem: 2 stages x 4 planes x [64 rows][36 words]
// ---------------------------------------------------------------------------
#define PW 36
#define PLANE (64 * PW)
#define STAGE_WORDS (4 * PLANE)
#define SMEM_DYN (2 * STAGE_WORDS * 4)     // 73728 bytes
#define NBIAS ((2 * NTMP + 1) * NSP)       // 1056

__global__ void __launch_bounds__(256, 2) attn_kernel(const float* __restrict__ bias_table) {
    extern __shared__ unsigned dynsm[];
    __shared__ float bias_sm[NBIAS];

    int bh_ = blockIdx.y;             // 0..31
    int b = bh_ >> 3, h = bh_ & 7;
    int i0 = blockIdx.x * 128;
    int tid = threadIdx.x;
    int lane = tid & 31;
    int w = tid >> 5;                 // 0..7
    int lg = lane >> 2;
    int lt = lane & 3;
    int m = w * 16 + lg;              // q row within tile (first of pair)

    // bias column for this head into smem
    for (int i = tid; i < NBIAS; i += 256)
        bias_sm[i] = bias_table[i * HH + h];

    const unsigned* kbh = (const unsigned*)g_kbh + (size_t)bh_ * NN * (HD / 2);
    const unsigned* kbl = (const unsigned*)g_kbl + (size_t)bh_ * NN * (HD / 2);
    const unsigned* vbh = (const unsigned*)g_vbh + (size_t)bh_ * NN * (HD / 2);
    const unsigned* vbl = (const unsigned*)g_vbl + (size_t)bh_ * NN * (HD / 2);
    const unsigned dyn_base = smem_u32(dynsm);

    // per-thread cp.async source/dest offsets (2 chunks x 4 planes)
    int cp_row0 = tid >> 3, cp_c4 = tid & 7;
    int cp_row1 = cp_row0 + 32;

    // Q A-fragments loaded straight from global bf16 planes (one-time)
    unsigned qhf[4][4], qlf[4][4];
    {
        const unsigned* qhp = (const unsigned*)g_qbh + ((size_t)bh_ * NN + i0) * (HD / 2);
        const unsigned* qlp = (const unsigned*)g_qbl + ((size_t)bh_ * NN + i0) * (HD / 2);
#pragma unroll
        for (int kf = 0; kf < 4; kf++) {
            int base = m * (HD / 2) + kf * 8 + lt;
            qhf[kf][0] = qhp[base];
            qhf[kf][1] = qhp[base + 8 * (HD / 2)];
            qhf[kf][2] = qhp[base + 4];
            qhf[kf][3] = qhp[base + 8 * (HD / 2) + 4];
            qlf[kf][0] = qlp[base];
            qlf[kf][1] = qlp[base + 8 * (HD / 2)];
            qlf[kf][2] = qlp[base + 4];
            qlf[kf][3] = qlp[base + 8 * (HD / 2) + 4];
        }
    }

    float o[8][4];
#pragma unroll
    for (int nf = 0; nf < 8; nf++)
#pragma unroll
        for (int zz = 0; zz < 4; zz++) o[nf][zz] = 0.0f;
    float m0 = -CUDART_INF_F, m1 = -CUDART_INF_F;
    float l0s = 0.0f, l1s = 0.0f;

    const size_t mirow0 = ((size_t)b * NN + (i0 + m)) * NN;
    const size_t mirow1 = mirow0 + 8 * (size_t)NN;

    const unsigned k_row = (lane & 7) + ((lane >> 4) << 3);
    const unsigned k_colw = ((lane >> 3) & 1) << 2;
    const unsigned v_row = lane & 15;
    const unsigned v_colw = (lane >> 4) << 2;

    // async copy of one 64-row K/V tile group into a stage
    auto copy_tile = [&](int stage, int j0) {
        unsigned sb = dyn_base + (unsigned)stage * STAGE_WORDS * 4;
        size_t g0 = (size_t)(j0 + cp_row0) * (HD / 2) + cp_c4 * 4;
        size_t g1 = (size_t)(j0 + cp_row1) * (HD / 2) + cp_c4 * 4;
        unsigned d0 = (cp_row0 * PW + cp_c4 * 4) * 4u;
        unsigned d1 = (cp_row1 * PW + cp_c4 * 4) * 4u;
        cp_async16(sb + d0, kbh + g0);
        cp_async16(sb + d1, kbh + g1);
        cp_async16(sb + PLANE * 4 + d0, kbl + g0);
        cp_async16(sb + PLANE * 4 + d1, kbl + g1);
        cp_async16(sb + 2 * PLANE * 4 + d0, vbh + g0);
        cp_async16(sb + 2 * PLANE * 4 + d1, vbh + g1);
        cp_async16(sb + 3 * PLANE * 4 + d0, vbl + g0);
        cp_async16(sb + 3 * PLANE * 4 + d1, vbl + g1);
    };

    // prologue: prefetch tile 0 into stage 0
    copy_tile(0, 0);
    cp_async_commit();

    for (int jt = 0; jt < NN / 64; jt++) {
        int cur = jt & 1;
        cp_async_wait0();
        __syncthreads();   // stage cur ready; all warps done with stage cur^1
        if (jt + 1 < NN / 64) {
            copy_tile(cur ^ 1, (jt + 1) * 64);
            cp_async_commit();
        }

        unsigned sb = dyn_base + (unsigned)cur * STAGE_WORDS * 4;
        unsigned kh_base = sb;
        unsigned kl_base = sb + PLANE * 4;
        unsigned vh_base = sb + 2 * PLANE * 4;
        unsigned vl_base = sb + 3 * PLANE * 4;
        int j0 = jt * 64;

        // ---- QK^T (3xBF16), K B-frags via ldmatrix.x4
        float s[8][4];
#pragma unroll
        for (int nf = 0; nf < 8; nf++)
            s[nf][0] = s[nf][1] = s[nf][2] = s[nf][3] = 0.0f;
#pragma unroll
        for (int kf = 0; kf < 4; kf++) {
#pragma unroll
            for (int np = 0; np < 4; np++) {
                unsigned woff = ((np * 16 + k_row) * PW + kf * 8 + k_colw) * 4u;
                unsigned h0, h1, h2, h3, l0_, l1_, l2_, l3_;
                ldsm_x4(h0, h1, h2, h3, kh_base + woff);
                ldsm_x4(l0_, l1_, l2_, l3_, kl_base + woff);
                mma3b(s[2 * np],     qhf[kf], qlf[kf], h0, h1, l0_, l1_);
                mma3b(s[2 * np + 1], qhf[kf], qlf[kf], h2, h3, l2_, l3_);
            }
        }

        // ---- bias + mask (packed loads + smem bias)
#pragma unroll
        for (int nf = 0; nf < 8; nf++) {
            int jc = j0 + nf * 8 + lt * 2;
            uint2 w0 = *(const uint2*)&g_mi[mirow0 + jc];
            uint2 w1 = *(const uint2*)&g_mi[mirow1 + jc];
            s[nf][0] = s[nf][0] * 0.125f + mi_term(w0.x, bias_sm);
            s[nf][1] = s[nf][1] * 0.125f + mi_term(w0.y, bias_sm);
            s[nf][2] = s[nf][2] * 0.125f + mi_term(w1.x, bias_sm);
            s[nf][3] = s[nf][3] * 0.125f + mi_term(w1.y, bias_sm);
        }

        // ---- online softmax (2 rows per thread)
        float t0 = s[0][0], t1 = s[0][2];
#pragma unroll
        for (int nf = 0; nf < 8; nf++) {
            t0 = fmaxf(t0, fmaxf(s[nf][0], s[nf][1]));
            t1 = fmaxf(t1, fmaxf(s[nf][2], s[nf][3]));
        }
        t0 = fmaxf(t0, __shfl_xor_sync(0xffffffffu, t0, 1));
        t0 = fmaxf(t0, __shfl_xor_sync(0xffffffffu, t0, 2));
        t1 = fmaxf(t1, __shfl_xor_sync(0xffffffffu, t1, 1));
        t1 = fmaxf(t1, __shfl_xor_sync(0xffffffffu, t1, 2));
        float nm0 = fmaxf(m0, t0), nm1 = fmaxf(m1, t1);
        float sc0 = __expf(m0 - nm0), sc1 = __expf(m1 - nm1);

        float sum0 = 0.0f, sum1 = 0.0f;
#pragma unroll
        for (int nf = 0; nf < 8; nf++) {
            s[nf][0] = __expf(s[nf][0] - nm0);
            s[nf][1] = __expf(s[nf][1] - nm0);
            s[nf][2] = __expf(s[nf][2] - nm1);
            s[nf][3] = __expf(s[nf][3] - nm1);
            sum0 += s[nf][0] + s[nf][1];
            sum1 += s[nf][2] + s[nf][3];
        }
        sum0 += __shfl_xor_sync(0xffffffffu, sum0, 1);
        sum0 += __shfl_xor_sync(0xffffffffu, sum0, 2);
        sum1 += __shfl_xor_sync(0xffffffffu, sum1, 1);
        sum1 += __shfl_xor_sync(0xffffffffu, sum1, 2);
        l0s = l0s * sc0 + sum0;
        l1s = l1s * sc1 + sum1;
        m0 = nm0; m1 = nm1;
#pragma unroll
        for (int nf = 0; nf < 8; nf++) {
            o[nf][0] *= sc0; o[nf][1] *= sc0;
            o[nf][2] *= sc1; o[nf][3] *= sc1;
        }

        // ---- PV (3xBF16): P A-fragments split hi/lo from registers
#pragma unroll
        for (int kf = 0; kf < 4; kf++) {
            unsigned phf[4], plf[4];
            split2(s[2 * kf][0],     s[2 * kf][1],     phf[0], plf[0]);
            split2(s[2 * kf][2],     s[2 * kf][3],     phf[1], plf[1]);
            split2(s[2 * kf + 1][0], s[2 * kf + 1][1], phf[2], plf[2]);
            split2(s[2 * kf + 1][2], s[2 * kf + 1][3], phf[3], plf[3]);
            unsigned vrow = kf * 16 + v_row;
#pragma unroll
            for (int nf2 = 0; nf2 < 4; nf2++) {
                unsigned woff = (vrow * PW + nf2 * 8 + v_colw) * 4u;
                unsigned h0, h1, h2, h3, l0_, l1_, l2_, l3_;
                ldsm_x4_trans(h0, h1, h2, h3, vh_base + woff);
                ldsm_x4_trans(l0_, l1_, l2_, l3_, vl_base + woff);
                mma3b(o[2 * nf2],     phf, plf, h0, h1, l0_, l1_);
                mma3b(o[2 * nf2 + 1], phf, plf, h2, h3, l2_, l3_);
            }
        }
    }

    float inv0 = 1.0f / l0s;
    float inv1 = 1.0f / l1s;
    int r0 = i0 + m;
#pragma unroll
    for (int nf = 0; nf < 8; nf++) {
        int cc = h * HD + nf * 8 + lt * 2;
        *(float2*)&g_y[(size_t)(b * NN + r0) * DD + cc] =
            make_float2(o[nf][0] * inv0, o[nf][1] * inv0);
        *(float2*)&g_y[(size_t)(b * NN + r0 + 8) * DD + cc] =
            make_float2(o[nf][2] * inv1, o[nf][3] * inv1);
    }
}

// ---------------------------------------------------------------------------
// Host launch
// ---------------------------------------------------------------------------
extern "C" void kernel_launch(void* const* d_in, const int* in_sizes, int n_in,
                              void* d_out, int out_size) {
    const float* query = (const float*)d_in[0];
    const float* key   = (const float*)d_in[1];
    const float* value = (const float*)d_in[2];
    const float* coords = (const float*)d_in[3];
    const float* Wq = (const float*)d_in[4];
    const float* bq = (const float*)d_in[5];
    const float* Wk = (const float*)d_in[6];
    const float* bk = (const float*)d_in[7];
    const float* Wv = (const float*)d_in[8];
    const float* bv = (const float*)d_in[9];
    const float* Wo = (const float*)d_in[10];
    const float* bo = (const float*)d_in[11];
    const float* bias_table = (const float*)d_in[12];
    float* out = (float*)d_out;

    __nv_bfloat16 *qbh, *qbl, *kbh, *kbl, *vbh, *vbl;
    float* gy;
    cudaGetSymbolAddress((void**)&qbh, g_qbh);
    cudaGetSymbolAddress((void**)&qbl, g_qbl);
    cudaGetSymbolAddress((void**)&kbh, g_kbh);
    cudaGetSymbolAddress((void**)&kbl, g_kbl);
    cudaGetSymbolAddress((void**)&vbh, g_vbh);
    cudaGetSymbolAddress((void**)&vbl, g_vbl);
    cudaGetSymbolAddress((void**)&gy, g_y);

    cudaFuncSetAttribute(attn_kernel, cudaFuncAttributeMaxDynamicSharedMemorySize,
                         (int)SMEM_DYN);

    init_bins_kernel<<<1, 32>>>();

    // Fused QKV projections -> bf16 hi/lo planes
    QKVArgs qa;
    qa.A0 = query; qa.A1 = key; qa.A2 = value;
    qa.W0 = Wq;    qa.W1 = Wk;  qa.W2 = Wv;
    qa.b0 = bq;    qa.b1 = bk;  qa.b2 = bv;
    qa.Ch0 = qbh;  qa.Cl0 = qbl;
    qa.Ch1 = kbh;  qa.Cl1 = kbl;
    qa.Ch2 = vbh;  qa.Cl2 = vbl;
    qa.C0 = nullptr;
    gemm_bf16_kernel<<<dim3(DD / 128, (BB * NN) / 128, 3), 256>>>(qa, 1);

    precompute_kernel<<<(BB * NN * NN) / 256, 256>>>(coords);
    attn_kernel<<<dim3(NN / 128, BB * HH), 256, SMEM_DYN>>>(bias_table);

    // Output projection (fp32 in, fp32 out)
    QKVArgs oa;
    oa.A0 = gy; oa.A1 = gy; oa.A2 = gy;
    oa.W0 = Wo; oa.W1 = Wo; oa.W2 = Wo;
    oa.b0 = bo; oa.b1 = bo; oa.b2 = bo;
    oa.Ch0 = nullptr; oa.Cl0 = nullptr;
    oa.Ch1 = nullptr; oa.Cl1 = nullptr;
    oa.Ch2 = nullptr; oa.Cl2 = nullptr;
    oa.C0 = out;
    gemm_bf16_kernel<<<dim3(DD / 128, (BB * NN) / 128, 1), 256>>>(oa, 0);
}

// round 13
// speedup vs baseline: 4.6951x; 1.0216x over previous
#include <cuda_runtime.h>
#include <cuda_bf16.h>
#include <cuda_fp16.h>
#include <math_constants.h>

// Problem constants
#define BB 4
#define NN 1024
#define DD 512
#define HH 8
#define HD 64
#define NSP 32
#define NTMP 16

// Scratch (device globals; no allocations allowed)
__device__ __nv_bfloat16 g_qbh[BB * HH * NN * HD];  // Q bf16 hi plane (b,h,n,d)
__device__ __nv_bfloat16 g_qbl[BB * HH * NN * HD];  // Q bf16 lo plane
__device__ __nv_bfloat16 g_kbh[BB * HH * NN * HD];
__device__ __nv_bfloat16 g_kbl[BB * HH * NN * HD];
__device__ unsigned short g_vfh[BB * HH * NN * HD];  // V fp16 hi plane
__device__ unsigned short g_vfl[BB * HH * NN * HD];  // V fp16 lo plane
__device__ float g_y[BB * NN * DD];        // attention out (b,n,h*HD+d)
__device__ unsigned g_mi[BB * NN * NN];    // packed: fp16(mask) << 16 | idx
__device__ float g_sbins[NSP];

// ---------------------------------------------------------------------------
// bf16/fp16 m16n8k16 mma + split helpers
// ---------------------------------------------------------------------------
__device__ __forceinline__ void mma_bf16(float* d,
                                         unsigned a0, unsigned a1, unsigned a2, unsigned a3,
                                         unsigned b0, unsigned b1) {
    asm volatile(
        "mma.sync.aligned.m16n8k16.row.col.f32.bf16.bf16.f32 "
        "{%0,%1,%2,%3}, {%4,%5,%6,%7}, {%8,%9}, {%0,%1,%2,%3};\n"
        : "+f"(d[0]), "+f"(d[1]), "+f"(d[2]), "+f"(d[3])
        : "r"(a0), "r"(a1), "r"(a2), "r"(a3), "r"(b0), "r"(b1));
}

__device__ __forceinline__ void mma_f16(float* d,
                                        unsigned a0, unsigned a1, unsigned a2, unsigned a3,
                                        unsigned b0, unsigned b1) {
    asm volatile(
        "mma.sync.aligned.m16n8k16.row.col.f32.f16.f16.f32 "
        "{%0,%1,%2,%3}, {%4,%5,%6,%7}, {%8,%9}, {%0,%1,%2,%3};\n"
        : "+f"(d[0]), "+f"(d[1]), "+f"(d[2]), "+f"(d[3])
        : "r"(a0), "r"(a1), "r"(a2), "r"(a3), "r"(b0), "r"(b1));
}

// D += Ah*Bh + Ah*Bl + Al*Bh   (drop Al*Bl ~ 2^-18)
__device__ __forceinline__ void mma3b(float* d,
                                      const unsigned* ah, const unsigned* al,
                                      unsigned bh0, unsigned bh1,
                                      unsigned bl0, unsigned bl1) {
    mma_bf16(d, ah[0], ah[1], ah[2], ah[3], bh0, bh1);
    mma_bf16(d, ah[0], ah[1], ah[2], ah[3], bl0, bl1);
    mma_bf16(d, al[0], al[1], al[2], al[3], bh0, bh1);
}

// split two floats into packed-bf16 hi word + lo word (x0 -> low half)
__device__ __forceinline__ void split2(float x0, float x1, unsigned& hi, unsigned& lo) {
    __nv_bfloat162 h = __floats2bfloat162_rn(x0, x1);
    float2 hf = __bfloat1622float2(h);
    __nv_bfloat162 l = __floats2bfloat162_rn(x0 - hf.x, x1 - hf.y);
    hi = *(unsigned*)&h;
    lo = *(unsigned*)&l;
}

// split two floats into packed-fp16 hi word + lo word
__device__ __forceinline__ void split2h(float x0, float x1, unsigned& hi, unsigned& lo) {
    __half2 h = __floats2half2_rn(x0, x1);
    float2 hf = __half22float2(h);
    __half2 l = __floats2half2_rn(x0 - hf.x, x1 - hf.y);
    hi = *(unsigned*)&h;
    lo = *(unsigned*)&l;
}

__device__ __forceinline__ unsigned pack2h(float x0, float x1) {
    __half2 h = __floats2half2_rn(x0, x1);
    return *(unsigned*)&h;
}

__device__ __forceinline__ unsigned smem_u32(const void* p) {
    return (unsigned)__cvta_generic_to_shared(p);
}

__device__ __forceinline__ void cp_async16(unsigned dst, const void* src) {
    asm volatile("cp.async.cg.shared.global [%0], [%1], 16;\n"
                 :: "r"(dst), "l"(src));
}
__device__ __forceinline__ void cp_async_commit() {
    asm volatile("cp.async.commit_group;\n" ::: "memory");
}
__device__ __forceinline__ void cp_async_wait0() {
    asm volatile("cp.async.wait_group 0;\n" ::: "memory");
}

__device__ __forceinline__ void ldsm_x4(unsigned& r0, unsigned& r1,
                                        unsigned& r2, unsigned& r3, unsigned addr) {
    asm volatile(
        "ldmatrix.sync.aligned.m8n8.x4.shared.b16 {%0,%1,%2,%3}, [%4];"
        : "=r"(r0), "=r"(r1), "=r"(r2), "=r"(r3) : "r"(addr));
}

__device__ __forceinline__ void ldsm_x4_trans(unsigned& r0, unsigned& r1,
                                              unsigned& r2, unsigned& r3,
                                              unsigned addr) {
    asm volatile(
        "ldmatrix.sync.aligned.m8n8.x4.trans.shared.b16 {%0,%1,%2,%3}, [%4];"
        : "=r"(r0), "=r"(r1), "=r"(r2), "=r"(r3) : "r"(addr));
}

// decode packed mask+idx -> additive term using smem bias column
__device__ __forceinline__ float mi_term(unsigned wv, const float* bias_sm) {
    float mv = __half2float(__ushort_as_half((unsigned short)(wv >> 16)));
    return bias_sm[wv & 0xffffu] + mv;
}

// ---------------------------------------------------------------------------
// Fill spatial bins: exp(linspace(0, log(257), 32))
// ---------------------------------------------------------------------------
__global__ void init_bins_kernel() {
    int i = threadIdx.x;
    if (i < NSP) {
        double L = log(257.0);
        g_sbins[i] = (float)exp((double)i * (L / 31.0));
    }
}

// ---------------------------------------------------------------------------
// 3xBF16 GEMM: C[m,o] = sum_k A[m,k] * W[o,k] + bias[o]
// mode 0: C row-major fp32
// mode 1: scatter hi/lo planes in (b,h,n,d); z<2 -> bf16 planes, z==2 -> fp16
// Tile 128x128, BK=32, 256 threads (8 warps, 4x2, warp tile 32x64), 2 CTAs/SM
// ---------------------------------------------------------------------------
#define BKW 20

struct QKVArgs {
    const float* A0; const float* A1; const float* A2;
    const float* W0; const float* W1; const float* W2;
    const float* b0; const float* b1; const float* b2;
    void* Ch0; void* Cl0;
    void* Ch1; void* Cl1;
    void* Ch2; void* Cl2;
    float* C0;
};

__global__ void __launch_bounds__(256, 2) gemm_bf16_kernel(QKVArgs args, int mode) {
    __shared__ unsigned Ah[128 * BKW], Al[128 * BKW];
    __shared__ unsigned Bh[128 * BKW], Bl[128 * BKW];

    int z = blockIdx.z;
    const float* A    = (z == 0) ? args.A0 : (z == 1) ? args.A1 : args.A2;
    const float* W    = (z == 0) ? args.W0 : (z == 1) ? args.W1 : args.W2;
    const float* bias = (z == 0) ? args.b0 : (z == 1) ? args.b1 : args.b2;
    unsigned* Ch = (unsigned*)((z == 0) ? args.Ch0 : (z == 1) ? args.Ch1 : args.Ch2);
    unsigned* Cl = (unsigned*)((z == 0) ? args.Cl0 : (z == 1) ? args.Cl1 : args.Cl2);

    const int K = DD, O = DD;
    int tid = threadIdx.x;
    int lane = tid & 31;
    int wid = tid >> 5;
    int warp_m = wid & 3;
    int warp_n = wid >> 2;
    int row0 = blockIdx.y * 128;
    int col0 = blockIdx.x * 128;
    int lg = lane >> 2;
    int lt = lane & 3;

    float acc[2][8][4];
#pragma unroll
    for (int mf = 0; mf < 2; mf++)
#pragma unroll
        for (int nf = 0; nf < 8; nf++)
#pragma unroll
            for (int zz = 0; zz < 4; zz++) acc[mf][nf][zz] = 0.0f;

    for (int k0 = 0; k0 < K; k0 += 32) {
#pragma unroll
        for (int i = 0; i < 4; i++) {
            int f = tid + 256 * i;      // 0..1023
            int r = f >> 3, c4 = f & 7;
            float4 a4 = *(const float4*)&A[(size_t)(row0 + r) * K + k0 + c4 * 4];
            float4 w4 = *(const float4*)&W[(size_t)(col0 + r) * K + k0 + c4 * 4];
            unsigned h0, l0, h1, l1;
            split2(a4.x, a4.y, h0, l0); split2(a4.z, a4.w, h1, l1);
            Ah[r * BKW + c4 * 2] = h0; Ah[r * BKW + c4 * 2 + 1] = h1;
            Al[r * BKW + c4 * 2] = l0; Al[r * BKW + c4 * 2 + 1] = l1;
            split2(w4.x, w4.y, h0, l0); split2(w4.z, w4.w, h1, l1);
            Bh[r * BKW + c4 * 2] = h0; Bh[r * BKW + c4 * 2 + 1] = h1;
            Bl[r * BKW + c4 * 2] = l0; Bl[r * BKW + c4 * 2 + 1] = l1;
        }
        __syncthreads();

#pragma unroll
        for (int kf = 0; kf < 2; kf++) {
            unsigned bh[8][2], bl[8][2];
#pragma unroll
            for (int nf = 0; nf < 8; nf++) {
                int o = warp_n * 64 + nf * 8 + lg;
                int wb = o * BKW + kf * 8 + lt;
                bh[nf][0] = Bh[wb]; bh[nf][1] = Bh[wb + 4];
                bl[nf][0] = Bl[wb]; bl[nf][1] = Bl[wb + 4];
            }
#pragma unroll
            for (int mf = 0; mf < 2; mf++) {
                int m = warp_m * 32 + mf * 16 + lg;
                int wa = m * BKW + kf * 8 + lt;
                unsigned ah[4], al[4];
                ah[0] = Ah[wa];           ah[1] = Ah[wa + 8 * BKW];
                ah[2] = Ah[wa + 4];       ah[3] = Ah[wa + 8 * BKW + 4];
                al[0] = Al[wa];           al[1] = Al[wa + 8 * BKW];
                al[2] = Al[wa + 4];       al[3] = Al[wa + 8 * BKW + 4];
#pragma unroll
                for (int nf = 0; nf < 8; nf++)
                    mma3b(acc[mf][nf], ah, al,
                          bh[nf][0], bh[nf][1], bl[nf][0], bl[nf][1]);
            }
        }
        __syncthreads();
    }

    // Epilogue
#pragma unroll
    for (int mf = 0; mf < 2; mf++) {
#pragma unroll
        for (int nf = 0; nf < 8; nf++) {
            int rr = row0 + warp_m * 32 + mf * 16 + lg;
            int cc = col0 + warp_n * 64 + nf * 8 + lt * 2;
            float b0 = bias[cc], b1 = bias[cc + 1];
#pragma unroll
            for (int half = 0; half < 2; half++) {
                int m = rr + half * 8;
                float v0 = acc[mf][nf][half * 2 + 0] + b0;
                float v1 = acc[mf][nf][half * 2 + 1] + b1;
                if (mode == 0) {
                    *(float2*)&args.C0[(size_t)m * O + cc] = make_float2(v0, v1);
                } else {
                    int b = m >> 10, n = m & (NN - 1);
                    int h = cc >> 6, d = cc & (HD - 1);
                    size_t widx = (((((size_t)b * HH + h) * NN) + n) * HD + d) >> 1;
                    unsigned hw, lw;
                    if (z == 2) split2h(v0, v1, hw, lw);   // V -> fp16 planes
                    else        split2(v0, v1, hw, lw);    // Q,K -> bf16 planes
                    Ch[widx] = hw;
                    Cl[widx] = lw;
                }
            }
        }
    }
}

// ---------------------------------------------------------------------------
// Precompute per-pair packed (fp16 mask | u16 idx)
// ---------------------------------------------------------------------------
__global__ void precompute_kernel(const float* __restrict__ coords) {
    int gid = blockIdx.x * 256 + threadIdx.x;   // 0 .. B*N*N-1 (4M)
    int b = gid >> 20;
    int rem = gid & ((1 << 20) - 1);
    int i = rem >> 10;
    int j = rem & 1023;

    const float* ci = coords + ((size_t)b * NN + i) * 3;
    const float* cj = coords + ((size_t)b * NN + j) * 3;
    float ti = ci[0], yi = ci[1], xi = ci[2];
    float tj = cj[0], yj = cj[1], xj = cj[2];

    float dy = yi - yj, dx = xi - xj, dt = ti - tj;
    float sp2 = dy * dy + dx * dx;
    float sd = sqrtf(fmaxf(sp2, 0.0f));
    float fd = sqrtf(fmaxf(dt * dt + dy * dy + dx * dx, 0.0f));

    int c = 0;
#pragma unroll
    for (int s = 0; s < NSP; s++) c += (g_sbins[s] < sd) ? 1 : 0;
    int sidx = min(c, NSP - 1);

    int tc = (int)ceilf(dt + 16.0f);
    tc = max(0, min(2 * NTMP, tc));

    float maskval = (sd > 256.0f ? -1000.0f : 0.0f) + expf(-0.1f * fd);
    unsigned short hb = __half_as_ushort(__float2half_rn(maskval));
    g_mi[gid] = ((unsigned)hb << 16) | (unsigned)(sidx + tc * NSP);
}

// ---------------------------------------------------------------------------
// Flash attention: 3xBF16 QK, fp16 2-term PV, cp.async double-buffered K/V,
// P in registers, packed mask+idx, bias column in smem. 2 CTAs/SM.
// grid: (N/128, B*H). block: 256 threads (8 warps); warp w owns q rows w*16..+16
// dynamic smem: 2 stages x 4 planes x [64 rows][36 words]
// ---------------------------------------------------------------------------
#define PW 36
#define PLANE (64 * PW)
#define STAGE_WORDS (4 * PLANE)
#define SMEM_DYN (2 * STAGE_WORDS * 4)     // 73728 bytes
#define NBIAS ((2 * NTMP + 1) * NSP)       // 1056

__global__ void __launch_bounds__(256, 2) attn_kernel(const float* __restrict__ bias_table) {
    extern __shared__ unsigned dynsm[];
    __shared__ float bias_sm[NBIAS];

    int bh_ = blockIdx.y;             // 0..31
    int b = bh_ >> 3, h = bh_ & 7;
    int i0 = blockIdx.x * 128;
    int tid = threadIdx.x;
    int lane = tid & 31;
    int w = tid >> 5;                 // 0..7
    int lg = lane >> 2;
    int lt = lane & 3;
    int m = w * 16 + lg;              // q row within tile (first of pair)

    // bias column for this head into smem
    for (int i = tid; i < NBIAS; i += 256)
        bias_sm[i] = bias_table[i * HH + h];

    const unsigned* kbh = (const unsigned*)g_kbh + (size_t)bh_ * NN * (HD / 2);
    const unsigned* kbl = (const unsigned*)g_kbl + (size_t)bh_ * NN * (HD / 2);
    const unsigned* vbh = (const unsigned*)g_vfh + (size_t)bh_ * NN * (HD / 2);
    const unsigned* vbl = (const unsigned*)g_vfl + (size_t)bh_ * NN * (HD / 2);
    const unsigned dyn_base = smem_u32(dynsm);

    // per-thread cp.async source/dest offsets (2 chunks x 4 planes)
    int cp_row0 = tid >> 3, cp_c4 = tid & 7;
    int cp_row1 = cp_row0 + 32;

    // Q A-fragments loaded straight from global bf16 planes (one-time)
    unsigned qhf[4][4], qlf[4][4];
    {
        const unsigned* qhp = (const unsigned*)g_qbh + ((size_t)bh_ * NN + i0) * (HD / 2);
        const unsigned* qlp = (const unsigned*)g_qbl + ((size_t)bh_ * NN + i0) * (HD / 2);
#pragma unroll
        for (int kf = 0; kf < 4; kf++) {
            int base = m * (HD / 2) + kf * 8 + lt;
            qhf[kf][0] = qhp[base];
            qhf[kf][1] = qhp[base + 8 * (HD / 2)];
            qhf[kf][2] = qhp[base + 4];
            qhf[kf][3] = qhp[base + 8 * (HD / 2) + 4];
            qlf[kf][0] = qlp[base];
            qlf[kf][1] = qlp[base + 8 * (HD / 2)];
            qlf[kf][2] = qlp[base + 4];
            qlf[kf][3] = qlp[base + 8 * (HD / 2) + 4];
        }
    }

    float o[8][4];
#pragma unroll
    for (int nf = 0; nf < 8; nf++)
#pragma unroll
        for (int zz = 0; zz < 4; zz++) o[nf][zz] = 0.0f;
    float m0 = -CUDART_INF_F, m1 = -CUDART_INF_F;
    float l0s = 0.0f, l1s = 0.0f;

    const size_t mirow0 = ((size_t)b * NN + (i0 + m)) * NN;
    const size_t mirow1 = mirow0 + 8 * (size_t)NN;

    const unsigned k_row = (lane & 7) + ((lane >> 4) << 3);
    const unsigned k_colw = ((lane >> 3) & 1) << 2;
    const unsigned v_row = lane & 15;
    const unsigned v_colw = (lane >> 4) << 2;

    // async copy of one 64-row K/V tile group into a stage
    auto copy_tile = [&](int stage, int j0) {
        unsigned sb = dyn_base + (unsigned)stage * STAGE_WORDS * 4;
        size_t g0 = (size_t)(j0 + cp_row0) * (HD / 2) + cp_c4 * 4;
        size_t g1 = (size_t)(j0 + cp_row1) * (HD / 2) + cp_c4 * 4;
        unsigned d0 = (cp_row0 * PW + cp_c4 * 4) * 4u;
        unsigned d1 = (cp_row1 * PW + cp_c4 * 4) * 4u;
        cp_async16(sb + d0, kbh + g0);
        cp_async16(sb + d1, kbh + g1);
        cp_async16(sb + PLANE * 4 + d0, kbl + g0);
        cp_async16(sb + PLANE * 4 + d1, kbl + g1);
        cp_async16(sb + 2 * PLANE * 4 + d0, vbh + g0);
        cp_async16(sb + 2 * PLANE * 4 + d1, vbh + g1);
        cp_async16(sb + 3 * PLANE * 4 + d0, vbl + g0);
        cp_async16(sb + 3 * PLANE * 4 + d1, vbl + g1);
    };

    // prologue: prefetch tile 0 into stage 0
    copy_tile(0, 0);
    cp_async_commit();

    for (int jt = 0; jt < NN / 64; jt++) {
        int cur = jt & 1;
        cp_async_wait0();
        __syncthreads();   // stage cur ready; all warps done with stage cur^1
        if (jt + 1 < NN / 64) {
            copy_tile(cur ^ 1, (jt + 1) * 64);
            cp_async_commit();
        }

        unsigned sb = dyn_base + (unsigned)cur * STAGE_WORDS * 4;
        unsigned kh_base = sb;
        unsigned kl_base = sb + PLANE * 4;
        unsigned vh_base = sb + 2 * PLANE * 4;
        unsigned vl_base = sb + 3 * PLANE * 4;
        int j0 = jt * 64;

        // ---- QK^T (3xBF16), K B-frags via ldmatrix.x4
        float s[8][4];
#pragma unroll
        for (int nf = 0; nf < 8; nf++)
            s[nf][0] = s[nf][1] = s[nf][2] = s[nf][3] = 0.0f;
#pragma unroll
        for (int kf = 0; kf < 4; kf++) {
#pragma unroll
            for (int np = 0; np < 4; np++) {
                unsigned woff = ((np * 16 + k_row) * PW + kf * 8 + k_colw) * 4u;
                unsigned h0, h1, h2, h3, l0_, l1_, l2_, l3_;
                ldsm_x4(h0, h1, h2, h3, kh_base + woff);
                ldsm_x4(l0_, l1_, l2_, l3_, kl_base + woff);
                mma3b(s[2 * np],     qhf[kf], qlf[kf], h0, h1, l0_, l1_);
                mma3b(s[2 * np + 1], qhf[kf], qlf[kf], h2, h3, l2_, l3_);
            }
        }

        // ---- bias + mask (packed loads + smem bias)
#pragma unroll
        for (int nf = 0; nf < 8; nf++) {
            int jc = j0 + nf * 8 + lt * 2;
            uint2 w0 = *(const uint2*)&g_mi[mirow0 + jc];
            uint2 w1 = *(const uint2*)&g_mi[mirow1 + jc];
            s[nf][0] = s[nf][0] * 0.125f + mi_term(w0.x, bias_sm);
            s[nf][1] = s[nf][1] * 0.125f + mi_term(w0.y, bias_sm);
            s[nf][2] = s[nf][2] * 0.125f + mi_term(w1.x, bias_sm);
            s[nf][3] = s[nf][3] * 0.125f + mi_term(w1.y, bias_sm);
        }

        // ---- online softmax (2 rows per thread)
        float t0 = s[0][0], t1 = s[0][2];
#pragma unroll
        for (int nf = 0; nf < 8; nf++) {
            t0 = fmaxf(t0, fmaxf(s[nf][0], s[nf][1]));
            t1 = fmaxf(t1, fmaxf(s[nf][2], s[nf][3]));
        }
        t0 = fmaxf(t0, __shfl_xor_sync(0xffffffffu, t0, 1));
        t0 = fmaxf(t0, __shfl_xor_sync(0xffffffffu, t0, 2));
        t1 = fmaxf(t1, __shfl_xor_sync(0xffffffffu, t1, 1));
        t1 = fmaxf(t1, __shfl_xor_sync(0xffffffffu, t1, 2));
        float nm0 = fmaxf(m0, t0), nm1 = fmaxf(m1, t1);
        float sc0 = __expf(m0 - nm0), sc1 = __expf(m1 - nm1);

        float sum0 = 0.0f, sum1 = 0.0f;
#pragma unroll
        for (int nf = 0; nf < 8; nf++) {
            s[nf][0] = __expf(s[nf][0] - nm0);
            s[nf][1] = __expf(s[nf][1] - nm0);
            s[nf][2] = __expf(s[nf][2] - nm1);
            s[nf][3] = __expf(s[nf][3] - nm1);
            sum0 += s[nf][0] + s[nf][1];
            sum1 += s[nf][2] + s[nf][3];
        }
        sum0 += __shfl_xor_sync(0xffffffffu, sum0, 1);
        sum0 += __shfl_xor_sync(0xffffffffu, sum0, 2);
        sum1 += __shfl_xor_sync(0xffffffffu, sum1, 1);
        sum1 += __shfl_xor_sync(0xffffffffu, sum1, 2);
        l0s = l0s * sc0 + sum0;
        l1s = l1s * sc1 + sum1;
        m0 = nm0; m1 = nm1;
#pragma unroll
        for (int nf = 0; nf < 8; nf++) {
            o[nf][0] *= sc0; o[nf][1] *= sc0;
            o[nf][2] *= sc1; o[nf][3] *= sc1;
        }

        // ---- PV (fp16 2-term): P single fp16 A-frag; V fp16 hi/lo
#pragma unroll
        for (int kf = 0; kf < 4; kf++) {
            unsigned phf[4];
            phf[0] = pack2h(s[2 * kf][0],     s[2 * kf][1]);
            phf[1] = pack2h(s[2 * kf][2],     s[2 * kf][3]);
            phf[2] = pack2h(s[2 * kf + 1][0], s[2 * kf + 1][1]);
            phf[3] = pack2h(s[2 * kf + 1][2], s[2 * kf + 1][3]);
            unsigned vrow = kf * 16 + v_row;
#pragma unroll
            for (int nf2 = 0; nf2 < 4; nf2++) {
                unsigned woff = (vrow * PW + nf2 * 8 + v_colw) * 4u;
                unsigned h0, h1, h2, h3, l0_, l1_, l2_, l3_;
                ldsm_x4_trans(h0, h1, h2, h3, vh_base + woff);
                ldsm_x4_trans(l0_, l1_, l2_, l3_, vl_base + woff);
                mma_f16(o[2 * nf2],     phf[0], phf[1], phf[2], phf[3], h0, h1);
                mma_f16(o[2 * nf2],     phf[0], phf[1], phf[2], phf[3], l0_, l1_);
                mma_f16(o[2 * nf2 + 1], phf[0], phf[1], phf[2], phf[3], h2, h3);
                mma_f16(o[2 * nf2 + 1], phf[0], phf[1], phf[2], phf[3], l2_, l3_);
            }
        }
    }

    float inv0 = 1.0f / l0s;
    float inv1 = 1.0f / l1s;
    int r0 = i0 + m;
#pragma unroll
    for (int nf = 0; nf < 8; nf++) {
        int cc = h * HD + nf * 8 + lt * 2;
        *(float2*)&g_y[(size_t)(b * NN + r0) * DD + cc] =
            make_float2(o[nf][0] * inv0, o[nf][1] * inv0);
        *(float2*)&g_y[(size_t)(b * NN + r0 + 8) * DD + cc] =
            make_float2(o[nf][2] * inv1, o[nf][3] * inv1);
    }
}

// ---------------------------------------------------------------------------
// Host launch
// ---------------------------------------------------------------------------
extern "C" void kernel_launch(void* const* d_in, const int* in_sizes, int n_in,
                              void* d_out, int out_size) {
    const float* query = (const float*)d_in[0];
    const float* key   = (const float*)d_in[1];
    const float* value = (const float*)d_in[2];
    const float* coords = (const float*)d_in[3];
    const float* Wq = (const float*)d_in[4];
    const float* bq = (const float*)d_in[5];
    const float* Wk = (const float*)d_in[6];
    const float* bk = (const float*)d_in[7];
    const float* Wv = (const float*)d_in[8];
    const float* bv = (const float*)d_in[9];
    const float* Wo = (const float*)d_in[10];
    const float* bo = (const float*)d_in[11];
    const float* bias_table = (const float*)d_in[12];
    float* out = (float*)d_out;

    void *qbh, *qbl, *kbh, *kbl, *vfh, *vfl;
    float* gy;
    cudaGetSymbolAddress(&qbh, g_qbh);
    cudaGetSymbolAddress(&qbl, g_qbl);
    cudaGetSymbolAddress(&kbh, g_kbh);
    cudaGetSymbolAddress(&kbl, g_kbl);
    cudaGetSymbolAddress(&vfh, g_vfh);
    cudaGetSymbolAddress(&vfl, g_vfl);
    cudaGetSymbolAddress((void**)&gy, g_y);

    cudaFuncSetAttribute(attn_kernel, cudaFuncAttributeMaxDynamicSharedMemorySize,
                         (int)SMEM_DYN);

    init_bins_kernel<<<1, 32>>>();

    // Fused QKV projections -> bf16 (Q,K) / fp16 (V) hi/lo planes
    QKVArgs qa;
    qa.A0 = query; qa.A1 = key; qa.A2 = value;
    qa.W0 = Wq;    qa.W1 = Wk;  qa.W2 = Wv;
    qa.b0 = bq;    qa.b1 = bk;  qa.b2 = bv;
    qa.Ch0 = qbh;  qa.Cl0 = qbl;
    qa.Ch1 = kbh;  qa.Cl1 = kbl;
    qa.Ch2 = vfh;  qa.Cl2 = vfl;
    qa.C0 = nullptr;
    gemm_bf16_kernel<<<dim3(DD / 128, (BB * NN) / 128, 3), 256>>>(qa, 1);

    precompute_kernel<<<(BB * NN * NN) / 256, 256>>>(coords);
    attn_kernel<<<dim3(NN / 128, BB * HH), 256, SMEM_DYN>>>(bias_table);

    // Output projection (fp32 in, fp32 out)
    QKVArgs oa;
    oa.A0 = gy; oa.A1 = gy; oa.A2 = gy;
    oa.W0 = Wo; oa.W1 = Wo; oa.W2 = Wo;
    oa.b0 = bo; oa.b1 = bo; oa.b2 = bo;
    oa.Ch0 = nullptr; oa.Cl0 = nullptr;
    oa.Ch1 = nullptr; oa.Cl1 = nullptr;
    oa.Ch2 = nullptr; oa.Cl2 = nullptr;
    oa.C0 = out;
    gemm_bf16_kernel<<<dim3(DD / 128, (BB * NN) / 128, 1), 256>>>(oa, 0);
}

// round 14
// speedup vs baseline: 5.0062x; 1.0663x over previous
#include <cuda_runtime.h>
#include <cuda_bf16.h>
#include <cuda_fp16.h>
#include <math_constants.h>

// Problem constants
#define BB 4
#define NN 1024
#define DD 512
#define HH 8
#define HD 64
#define NSP 32
#define NTMP 16

#define XZ (BB * NN * DD / 2)   // u32 per activation plane (1M)
#define WZ (DD * DD / 2)        // u32 per weight plane (128K)

// Scratch (device globals; no allocations allowed)
__device__ unsigned g_xh[3 * XZ];   // split inputs hi (query,key,value)
__device__ unsigned g_xl[3 * XZ];
__device__ unsigned g_wh[4 * WZ];   // split weights hi (Wq,Wk,Wv,Wo)
__device__ unsigned g_wl[4 * WZ];
__device__ unsigned g_yh[XZ];       // attention out planes (bf16 hi/lo)
__device__ unsigned g_yl[XZ];
__device__ __nv_bfloat16 g_qbh[BB * HH * NN * HD];  // Q bf16 hi plane (b,h,n,d)
__device__ __nv_bfloat16 g_qbl[BB * HH * NN * HD];
__device__ __nv_bfloat16 g_kbh[BB * HH * NN * HD];
__device__ __nv_bfloat16 g_kbl[BB * HH * NN * HD];
__device__ unsigned short g_vfh[BB * HH * NN * HD];  // V fp16 hi plane
__device__ unsigned short g_vfl[BB * HH * NN * HD];
__device__ unsigned g_mi[BB * NN * NN];    // packed: fp16(mask) << 16 | idx
__device__ float g_sbins[NSP];

// ---------------------------------------------------------------------------
// mma + split helpers
// ---------------------------------------------------------------------------
__device__ __forceinline__ void mma_bf16(float* d,
                                         unsigned a0, unsigned a1, unsigned a2, unsigned a3,
                                         unsigned b0, unsigned b1) {
    asm volatile(
        "mma.sync.aligned.m16n8k16.row.col.f32.bf16.bf16.f32 "
        "{%0,%1,%2,%3}, {%4,%5,%6,%7}, {%8,%9}, {%0,%1,%2,%3};\n"
        : "+f"(d[0]), "+f"(d[1]), "+f"(d[2]), "+f"(d[3])
        : "r"(a0), "r"(a1), "r"(a2), "r"(a3), "r"(b0), "r"(b1));
}

__device__ __forceinline__ void mma_f16(float* d,
                                        unsigned a0, unsigned a1, unsigned a2, unsigned a3,
                                        unsigned b0, unsigned b1) {
    asm volatile(
        "mma.sync.aligned.m16n8k16.row.col.f32.f16.f16.f32 "
        "{%0,%1,%2,%3}, {%4,%5,%6,%7}, {%8,%9}, {%0,%1,%2,%3};\n"
        : "+f"(d[0]), "+f"(d[1]), "+f"(d[2]), "+f"(d[3])
        : "r"(a0), "r"(a1), "r"(a2), "r"(a3), "r"(b0), "r"(b1));
}

__device__ __forceinline__ void mma3b(float* d,
                                      const unsigned* ah, const unsigned* al,
                                      unsigned bh0, unsigned bh1,
                                      unsigned bl0, unsigned bl1) {
    mma_bf16(d, ah[0], ah[1], ah[2], ah[3], bh0, bh1);
    mma_bf16(d, ah[0], ah[1], ah[2], ah[3], bl0, bl1);
    mma_bf16(d, al[0], al[1], al[2], al[3], bh0, bh1);
}

__device__ __forceinline__ void split2(float x0, float x1, unsigned& hi, unsigned& lo) {
    __nv_bfloat162 h = __floats2bfloat162_rn(x0, x1);
    float2 hf = __bfloat1622float2(h);
    __nv_bfloat162 l = __floats2bfloat162_rn(x0 - hf.x, x1 - hf.y);
    hi = *(unsigned*)&h;
    lo = *(unsigned*)&l;
}

__device__ __forceinline__ void split2h(float x0, float x1, unsigned& hi, unsigned& lo) {
    __half2 h = __floats2half2_rn(x0, x1);
    float2 hf = __half22float2(h);
    __half2 l = __floats2half2_rn(x0 - hf.x, x1 - hf.y);
    hi = *(unsigned*)&h;
    lo = *(unsigned*)&l;
}

__device__ __forceinline__ unsigned pack2h(float x0, float x1) {
    __half2 h = __floats2half2_rn(x0, x1);
    return *(unsigned*)&h;
}

__device__ __forceinline__ unsigned smem_u32(const void* p) {
    return (unsigned)__cvta_generic_to_shared(p);
}

__device__ __forceinline__ void cp_async16(unsigned dst, const void* src) {
    asm volatile("cp.async.cg.shared.global [%0], [%1], 16;\n"
                 :: "r"(dst), "l"(src));
}
__device__ __forceinline__ void cp_async_commit() {
    asm volatile("cp.async.commit_group;\n" ::: "memory");
}
__device__ __forceinline__ void cp_async_wait0() {
    asm volatile("cp.async.wait_group 0;\n" ::: "memory");
}

__device__ __forceinline__ void ldsm_x4(unsigned& r0, unsigned& r1,
                                        unsigned& r2, unsigned& r3, unsigned addr) {
    asm volatile(
        "ldmatrix.sync.aligned.m8n8.x4.shared.b16 {%0,%1,%2,%3}, [%4];"
        : "=r"(r0), "=r"(r1), "=r"(r2), "=r"(r3) : "r"(addr));
}

__device__ __forceinline__ void ldsm_x4_trans(unsigned& r0, unsigned& r1,
                                              unsigned& r2, unsigned& r3,
                                              unsigned addr) {
    asm volatile(
        "ldmatrix.sync.aligned.m8n8.x4.trans.shared.b16 {%0,%1,%2,%3}, [%4];"
        : "=r"(r0), "=r"(r1), "=r"(r2), "=r"(r3) : "r"(addr));
}

__device__ __forceinline__ float mi_term(unsigned wv, const float* bias_sm) {
    float mv = __half2float(__ushort_as_half((unsigned short)(wv >> 16)));
    return bias_sm[wv & 0xffffu] + mv;
}

// ---------------------------------------------------------------------------
// init bins + elementwise fp32 -> bf16 hi/lo plane split
// ---------------------------------------------------------------------------
__global__ void init_bins_kernel() {
    int i = threadIdx.x;
    if (i < NSP) {
        double L = log(257.0);
        g_sbins[i] = (float)exp((double)i * (L / 31.0));
    }
}

__global__ void presplit_kernel(const float* __restrict__ src,
                                unsigned* __restrict__ hi,
                                unsigned* __restrict__ lo, int n4) {
    int i = blockIdx.x * 256 + threadIdx.x;
    if (i < n4) {
        float4 v = ((const float4*)src)[i];
        unsigned h0, l0, h1, l1;
        split2(v.x, v.y, h0, l0);
        split2(v.z, v.w, h1, l1);
        ((uint2*)hi)[i] = make_uint2(h0, h1);
        ((uint2*)lo)[i] = make_uint2(l0, l1);
    }
}

// ---------------------------------------------------------------------------
// 3xBF16 GEMM on pre-split planes, cp.async double-buffered, ldmatrix frags.
// C[m,o] = sum_k A[m,k]*W[o,k] + bias[o]
// mode 0: C row-major fp32; mode 1: scatter hi/lo attn planes (z<2 bf16, z==2 fp16)
// Tile 128x128, BK=32, 256 threads (8 warps 4x2, warp tile 32x64), 2 CTAs/SM
// ---------------------------------------------------------------------------
#define PWG 20                          // u32 per smem row (16 data + 4 pad)
#define GPLANE (128 * PWG)              // u32 per plane
#define GSTAGE (4 * GPLANE)             // u32 per stage (Ah,Al,Wh,Wl)
#define GSMEM (2 * GSTAGE * 4)          // 81920 bytes

struct GemmArgs {
    const unsigned* Ah; const unsigned* Al;   // activation planes (z-indexed)
    const unsigned* Wh; const unsigned* Wl;   // weight planes (z-indexed)
    const float* b0; const float* b1; const float* b2;
    void* Ch0; void* Cl0; void* Ch1; void* Cl1; void* Ch2; void* Cl2;
    float* C0;
};

__global__ void __launch_bounds__(256, 2) gemm_planes_kernel(GemmArgs args, int mode) {
    extern __shared__ unsigned gsm[];

    int z = blockIdx.z;
    const unsigned* Ah = args.Ah + (size_t)z * XZ;
    const unsigned* Al = args.Al + (size_t)z * XZ;
    const unsigned* Wh = args.Wh + (size_t)z * WZ;
    const unsigned* Wl = args.Wl + (size_t)z * WZ;
    const float* bias = (z == 0) ? args.b0 : (z == 1) ? args.b1 : args.b2;
    unsigned* Ch = (unsigned*)((z == 0) ? args.Ch0 : (z == 1) ? args.Ch1 : args.Ch2);
    unsigned* Cl = (unsigned*)((z == 0) ? args.Cl0 : (z == 1) ? args.Cl1 : args.Cl2);

    int tid = threadIdx.x;
    int lane = tid & 31;
    int wid = tid >> 5;
    int warp_m = wid & 3;
    int warp_n = wid >> 2;
    int row0 = blockIdx.y * 128;
    int col0 = blockIdx.x * 128;
    int lg = lane >> 2;
    int lt = lane & 3;

    const unsigned gbase = smem_u32(gsm);
    const int KW = DD / 2;   // u32 per global plane row

    // ldmatrix per-thread address params
    const unsigned a_row = lane & 15;                         // A-frag
    const unsigned a_colw = (lane >> 4) << 2;
    const unsigned b_row = (lane & 7) + ((lane >> 4) << 3);   // B-frag
    const unsigned b_colw = ((lane >> 3) & 1) << 2;

    auto copyk = [&](int stage, int k0) {
        unsigned sb = gbase + (unsigned)stage * GSTAGE * 4u;
        int ku = k0 >> 1;
#pragma unroll
        for (int c = 0; c < 2; c++) {
            int f = tid + 256 * c;          // 0..511
            int r = f >> 2, c4 = f & 3;
            unsigned doff = (r * PWG + c4 * 4) * 4u;
            size_t ga = (size_t)(row0 + r) * KW + ku + c4 * 4;
            size_t gw = (size_t)(col0 + r) * KW + ku + c4 * 4;
            cp_async16(sb + doff, Ah + ga);
            cp_async16(sb + GPLANE * 4 + doff, Al + ga);
            cp_async16(sb + 2 * GPLANE * 4 + doff, Wh + gw);
            cp_async16(sb + 3 * GPLANE * 4 + doff, Wl + gw);
        }
    };

    float acc[2][8][4];
#pragma unroll
    for (int mf = 0; mf < 2; mf++)
#pragma unroll
        for (int nf = 0; nf < 8; nf++)
#pragma unroll
            for (int zz = 0; zz < 4; zz++) acc[mf][nf][zz] = 0.0f;

    copyk(0, 0);
    cp_async_commit();

    for (int kt = 0; kt < DD / 32; kt++) {
        int cur = kt & 1;
        cp_async_wait0();
        __syncthreads();
        if (kt + 1 < DD / 32) {
            copyk(cur ^ 1, (kt + 1) * 32);
            cp_async_commit();
        }

        unsigned sb = gbase + (unsigned)cur * GSTAGE * 4u;
        unsigned ahb = sb;
        unsigned alb = sb + GPLANE * 4;
        unsigned whb = sb + 2 * GPLANE * 4;
        unsigned wlb = sb + 3 * GPLANE * 4;

#pragma unroll
        for (int kf = 0; kf < 2; kf++) {
            unsigned bh[8][2], bl[8][2];
#pragma unroll
            for (int np = 0; np < 4; np++) {
                unsigned woff = ((warp_n * 64 + np * 16 + b_row) * PWG + kf * 8 + b_colw) * 4u;
                ldsm_x4(bh[2 * np][0], bh[2 * np][1], bh[2 * np + 1][0], bh[2 * np + 1][1],
                        whb + woff);
                ldsm_x4(bl[2 * np][0], bl[2 * np][1], bl[2 * np + 1][0], bl[2 * np + 1][1],
                        wlb + woff);
            }
#pragma unroll
            for (int mf = 0; mf < 2; mf++) {
                unsigned aoff = ((warp_m * 32 + mf * 16 + a_row) * PWG + kf * 8 + a_colw) * 4u;
                unsigned ah4[4], al4[4];
                ldsm_x4(ah4[0], ah4[1], ah4[2], ah4[3], ahb + aoff);
                ldsm_x4(al4[0], al4[1], al4[2], al4[3], alb + aoff);
#pragma unroll
                for (int nf = 0; nf < 8; nf++)
                    mma3b(acc[mf][nf], ah4, al4,
                          bh[nf][0], bh[nf][1], bl[nf][0], bl[nf][1]);
            }
        }
    }

    // Epilogue
#pragma unroll
    for (int mf = 0; mf < 2; mf++) {
#pragma unroll
        for (int nf = 0; nf < 8; nf++) {
            int rr = row0 + warp_m * 32 + mf * 16 + lg;
            int cc = col0 + warp_n * 64 + nf * 8 + lt * 2;
            float b0 = bias[cc], b1 = bias[cc + 1];
#pragma unroll
            for (int half = 0; half < 2; half++) {
                int m = rr + half * 8;
                float v0 = acc[mf][nf][half * 2 + 0] + b0;
                float v1 = acc[mf][nf][half * 2 + 1] + b1;
                if (mode == 0) {
                    *(float2*)&args.C0[(size_t)m * DD + cc] = make_float2(v0, v1);
                } else {
                    int b = m >> 10, n = m & (NN - 1);
                    int h = cc >> 6, d = cc & (HD - 1);
                    size_t widx = (((((size_t)b * HH + h) * NN) + n) * HD + d) >> 1;
                    unsigned hw, lw;
                    if (z == 2) split2h(v0, v1, hw, lw);   // V -> fp16 planes
                    else        split2(v0, v1, hw, lw);    // Q,K -> bf16 planes
                    Ch[widx] = hw;
                    Cl[widx] = lw;
                }
            }
        }
    }
}

// ---------------------------------------------------------------------------
// Precompute per-pair packed (fp16 mask | u16 idx)
// ---------------------------------------------------------------------------
__global__ void precompute_kernel(const float* __restrict__ coords) {
    int gid = blockIdx.x * 256 + threadIdx.x;   // 0 .. B*N*N-1 (4M)
    int b = gid >> 20;
    int rem = gid & ((1 << 20) - 1);
    int i = rem >> 10;
    int j = rem & 1023;

    const float* ci = coords + ((size_t)b * NN + i) * 3;
    const float* cj = coords + ((size_t)b * NN + j) * 3;
    float ti = ci[0], yi = ci[1], xi = ci[2];
    float tj = cj[0], yj = cj[1], xj = cj[2];

    float dy = yi - yj, dx = xi - xj, dt = ti - tj;
    float sp2 = dy * dy + dx * dx;
    float sd = sqrtf(fmaxf(sp2, 0.0f));
    float fd = sqrtf(fmaxf(dt * dt + dy * dy + dx * dx, 0.0f));

    int c = 0;
#pragma unroll
    for (int s = 0; s < NSP; s++) c += (g_sbins[s] < sd) ? 1 : 0;
    int sidx = min(c, NSP - 1);

    int tc = (int)ceilf(dt + 16.0f);
    tc = max(0, min(2 * NTMP, tc));

    float maskval = (sd > 256.0f ? -1000.0f : 0.0f) + expf(-0.1f * fd);
    unsigned short hb = __half_as_ushort(__float2half_rn(maskval));
    g_mi[gid] = ((unsigned)hb << 16) | (unsigned)(sidx + tc * NSP);
}

// ---------------------------------------------------------------------------
// Flash attention: 3xBF16 QK, fp16 2-term PV, cp.async double-buffered K/V,
// P in registers, packed mask+idx, bias column in smem. 2 CTAs/SM.
// Output written directly as bf16 hi/lo planes (for out-proj A side).
// ---------------------------------------------------------------------------
#define PW 36
#define PLANE (64 * PW)
#define STAGE_WORDS (4 * PLANE)
#define SMEM_DYN (2 * STAGE_WORDS * 4)     // 73728 bytes
#define NBIAS ((2 * NTMP + 1) * NSP)       // 1056

__global__ void __launch_bounds__(256, 2) attn_kernel(const float* __restrict__ bias_table) {
    extern __shared__ unsigned dynsm[];
    __shared__ float bias_sm[NBIAS];

    int bh_ = blockIdx.y;             // 0..31
    int b = bh_ >> 3, h = bh_ & 7;
    int i0 = blockIdx.x * 128;
    int tid = threadIdx.x;
    int lane = tid & 31;
    int w = tid >> 5;                 // 0..7
    int lg = lane >> 2;
    int lt = lane & 3;
    int m = w * 16 + lg;              // q row within tile (first of pair)

    for (int i = tid; i < NBIAS; i += 256)
        bias_sm[i] = bias_table[i * HH + h];

    const unsigned* kbh = (const unsigned*)g_kbh + (size_t)bh_ * NN * (HD / 2);
    const unsigned* kbl = (const unsigned*)g_kbl + (size_t)bh_ * NN * (HD / 2);
    const unsigned* vbh = (const unsigned*)g_vfh + (size_t)bh_ * NN * (HD / 2);
    const unsigned* vbl = (const unsigned*)g_vfl + (size_t)bh_ * NN * (HD / 2);
    const unsigned dyn_base = smem_u32(dynsm);

    int cp_row0 = tid >> 3, cp_c4 = tid & 7;
    int cp_row1 = cp_row0 + 32;

    // Q A-fragments from global bf16 planes (one-time)
    unsigned qhf[4][4], qlf[4][4];
    {
        const unsigned* qhp = (const unsigned*)g_qbh + ((size_t)bh_ * NN + i0) * (HD / 2);
        const unsigned* qlp = (const unsigned*)g_qbl + ((size_t)bh_ * NN + i0) * (HD / 2);
#pragma unroll
        for (int kf = 0; kf < 4; kf++) {
            int base = m * (HD / 2) + kf * 8 + lt;
            qhf[kf][0] = qhp[base];
            qhf[kf][1] = qhp[base + 8 * (HD / 2)];
            qhf[kf][2] = qhp[base + 4];
            qhf[kf][3] = qhp[base + 8 * (HD / 2) + 4];
            qlf[kf][0] = qlp[base];
            qlf[kf][1] = qlp[base + 8 * (HD / 2)];
            qlf[kf][2] = qlp[base + 4];
            qlf[kf][3] = qlp[base + 8 * (HD / 2) + 4];
        }
    }

    float o[8][4];
#pragma unroll
    for (int nf = 0; nf < 8; nf++)
#pragma unroll
        for (int zz = 0; zz < 4; zz++) o[nf][zz] = 0.0f;
    float m0 = -CUDART_INF_F, m1 = -CUDART_INF_F;
    float l0s = 0.0f, l1s = 0.0f;

    const size_t mirow0 = ((size_t)b * NN + (i0 + m)) * NN;
    const size_t mirow1 = mirow0 + 8 * (size_t)NN;

    const unsigned k_row = (lane & 7) + ((lane >> 4) << 3);
    const unsigned k_colw = ((lane >> 3) & 1) << 2;
    const unsigned v_row = lane & 15;
    const unsigned v_colw = (lane >> 4) << 2;

    auto copy_tile = [&](int stage, int j0) {
        unsigned sb = dyn_base + (unsigned)stage * STAGE_WORDS * 4;
        size_t g0 = (size_t)(j0 + cp_row0) * (HD / 2) + cp_c4 * 4;
        size_t g1 = (size_t)(j0 + cp_row1) * (HD / 2) + cp_c4 * 4;
        unsigned d0 = (cp_row0 * PW + cp_c4 * 4) * 4u;
        unsigned d1 = (cp_row1 * PW + cp_c4 * 4) * 4u;
        cp_async16(sb + d0, kbh + g0);
        cp_async16(sb + d1, kbh + g1);
        cp_async16(sb + PLANE * 4 + d0, kbl + g0);
        cp_async16(sb + PLANE * 4 + d1, kbl + g1);
        cp_async16(sb + 2 * PLANE * 4 + d0, vbh + g0);
        cp_async16(sb + 2 * PLANE * 4 + d1, vbh + g1);
        cp_async16(sb + 3 * PLANE * 4 + d0, vbl + g0);
        cp_async16(sb + 3 * PLANE * 4 + d1, vbl + g1);
    };

    copy_tile(0, 0);
    cp_async_commit();

    for (int jt = 0; jt < NN / 64; jt++) {
        int cur = jt & 1;
        cp_async_wait0();
        __syncthreads();
        if (jt + 1 < NN / 64) {
            copy_tile(cur ^ 1, (jt + 1) * 64);
            cp_async_commit();
        }

        unsigned sb = dyn_base + (unsigned)cur * STAGE_WORDS * 4;
        unsigned kh_base = sb;
        unsigned kl_base = sb + PLANE * 4;
        unsigned vh_base = sb + 2 * PLANE * 4;
        unsigned vl_base = sb + 3 * PLANE * 4;
        int j0 = jt * 64;

        // ---- QK^T (3xBF16)
        float s[8][4];
#pragma unroll
        for (int nf = 0; nf < 8; nf++)
            s[nf][0] = s[nf][1] = s[nf][2] = s[nf][3] = 0.0f;
#pragma unroll
        for (int kf = 0; kf < 4; kf++) {
#pragma unroll
            for (int np = 0; np < 4; np++) {
                unsigned woff = ((np * 16 + k_row) * PW + kf * 8 + k_colw) * 4u;
                unsigned h0, h1, h2, h3, l0_, l1_, l2_, l3_;
                ldsm_x4(h0, h1, h2, h3, kh_base + woff);
                ldsm_x4(l0_, l1_, l2_, l3_, kl_base + woff);
                mma3b(s[2 * np],     qhf[kf], qlf[kf], h0, h1, l0_, l1_);
                mma3b(s[2 * np + 1], qhf[kf], qlf[kf], h2, h3, l2_, l3_);
            }
        }

        // ---- bias + mask
#pragma unroll
        for (int nf = 0; nf < 8; nf++) {
            int jc = j0 + nf * 8 + lt * 2;
            uint2 w0 = *(const uint2*)&g_mi[mirow0 + jc];
            uint2 w1 = *(const uint2*)&g_mi[mirow1 + jc];
            s[nf][0] = s[nf][0] * 0.125f + mi_term(w0.x, bias_sm);
            s[nf][1] = s[nf][1] * 0.125f + mi_term(w0.y, bias_sm);
            s[nf][2] = s[nf][2] * 0.125f + mi_term(w1.x, bias_sm);
            s[nf][3] = s[nf][3] * 0.125f + mi_term(w1.y, bias_sm);
        }

        // ---- online softmax
        float t0 = s[0][0], t1 = s[0][2];
#pragma unroll
        for (int nf = 0; nf < 8; nf++) {
            t0 = fmaxf(t0, fmaxf(s[nf][0], s[nf][1]));
            t1 = fmaxf(t1, fmaxf(s[nf][2], s[nf][3]));
        }
        t0 = fmaxf(t0, __shfl_xor_sync(0xffffffffu, t0, 1));
        t0 = fmaxf(t0, __shfl_xor_sync(0xffffffffu, t0, 2));
        t1 = fmaxf(t1, __shfl_xor_sync(0xffffffffu, t1, 1));
        t1 = fmaxf(t1, __shfl_xor_sync(0xffffffffu, t1, 2));
        float nm0 = fmaxf(m0, t0), nm1 = fmaxf(m1, t1);
        float sc0 = __expf(m0 - nm0), sc1 = __expf(m1 - nm1);

        float sum0 = 0.0f, sum1 = 0.0f;
#pragma unroll
        for (int nf = 0; nf < 8; nf++) {
            s[nf][0] = __expf(s[nf][0] - nm0);
            s[nf][1] = __expf(s[nf][1] - nm0);
            s[nf][2] = __expf(s[nf][2] - nm1);
            s[nf][3] = __expf(s[nf][3] - nm1);
            sum0 += s[nf][0] + s[nf][1];
            sum1 += s[nf][2] + s[nf][3];
        }
        sum0 += __shfl_xor_sync(0xffffffffu, sum0, 1);
        sum0 += __shfl_xor_sync(0xffffffffu, sum0, 2);
        sum1 += __shfl_xor_sync(0xffffffffu, sum1, 1);
        sum1 += __shfl_xor_sync(0xffffffffu, sum1, 2);
        l0s = l0s * sc0 + sum0;
        l1s = l1s * sc1 + sum1;
        m0 = nm0; m1 = nm1;
#pragma unroll
        for (int nf = 0; nf < 8; nf++) {
            o[nf][0] *= sc0; o[nf][1] *= sc0;
            o[nf][2] *= sc1; o[nf][3] *= sc1;
        }

        // ---- PV (fp16 2-term)
#pragma unroll
        for (int kf = 0; kf < 4; kf++) {
            unsigned phf[4];
            phf[0] = pack2h(s[2 * kf][0],     s[2 * kf][1]);
            phf[1] = pack2h(s[2 * kf][2],     s[2 * kf][3]);
            phf[2] = pack2h(s[2 * kf + 1][0], s[2 * kf + 1][1]);
            phf[3] = pack2h(s[2 * kf + 1][2], s[2 * kf + 1][3]);
            unsigned vrow = kf * 16 + v_row;
#pragma unroll
            for (int nf2 = 0; nf2 < 4; nf2++) {
                unsigned woff = (vrow * PW + nf2 * 8 + v_colw) * 4u;
                unsigned h0, h1, h2, h3, l0_, l1_, l2_, l3_;
                ldsm_x4_trans(h0, h1, h2, h3, vh_base + woff);
                ldsm_x4_trans(l0_, l1_, l2_, l3_, vl_base + woff);
                mma_f16(o[2 * nf2],     phf[0], phf[1], phf[2], phf[3], h0, h1);
                mma_f16(o[2 * nf2],     phf[0], phf[1], phf[2], phf[3], l0_, l1_);
                mma_f16(o[2 * nf2 + 1], phf[0], phf[1], phf[2], phf[3], h2, h3);
                mma_f16(o[2 * nf2 + 1], phf[0], phf[1], phf[2], phf[3], l2_, l3_);
            }
        }
    }

    // Epilogue: normalize and write bf16 hi/lo planes
    float inv0 = 1.0f / l0s;
    float inv1 = 1.0f / l1s;
    int r0 = i0 + m;
#pragma unroll
    for (int nf = 0; nf < 8; nf++) {
        int cc = h * HD + nf * 8 + lt * 2;
        size_t idx0 = ((size_t)(b * NN + r0) * DD + cc) >> 1;
        size_t idx1 = ((size_t)(b * NN + r0 + 8) * DD + cc) >> 1;
        unsigned hw, lw;
        split2(o[nf][0] * inv0, o[nf][1] * inv0, hw, lw);
        g_yh[idx0] = hw; g_yl[idx0] = lw;
        split2(o[nf][2] * inv1, o[nf][3] * inv1, hw, lw);
        g_yh[idx1] = hw; g_yl[idx1] = lw;
    }
}

// ---------------------------------------------------------------------------
// Host launch
// ---------------------------------------------------------------------------
extern "C" void kernel_launch(void* const* d_in, const int* in_sizes, int n_in,
                              void* d_out, int out_size) {
    const float* query = (const float*)d_in[0];
    const float* key   = (const float*)d_in[1];
    const float* value = (const float*)d_in[2];
    const float* coords = (const float*)d_in[3];
    const float* Wq = (const float*)d_in[4];
    const float* bq = (const float*)d_in[5];
    const float* Wk = (const float*)d_in[6];
    const float* bk = (const float*)d_in[7];
    const float* Wv = (const float*)d_in[8];
    const float* bv = (const float*)d_in[9];
    const float* Wo = (const float*)d_in[10];
    const float* bo = (const float*)d_in[11];
    const float* bias_table = (const float*)d_in[12];
    float* out = (float*)d_out;

    unsigned *xh, *xl, *wh, *wl, *yh, *yl;
    void *qbh, *qbl, *kbh, *kbl, *vfh, *vfl;
    cudaGetSymbolAddress((void**)&xh, g_xh);
    cudaGetSymbolAddress((void**)&xl, g_xl);
    cudaGetSymbolAddress((void**)&wh, g_wh);
    cudaGetSymbolAddress((void**)&wl, g_wl);
    cudaGetSymbolAddress((void**)&yh, g_yh);
    cudaGetSymbolAddress((void**)&yl, g_yl);
    cudaGetSymbolAddress(&qbh, g_qbh);
    cudaGetSymbolAddress(&qbl, g_qbl);
    cudaGetSymbolAddress(&kbh, g_kbh);
    cudaGetSymbolAddress(&kbl, g_kbl);
    cudaGetSymbolAddress(&vfh, g_vfh);
    cudaGetSymbolAddress(&vfl, g_vfl);

    cudaFuncSetAttribute(attn_kernel, cudaFuncAttributeMaxDynamicSharedMemorySize,
                         (int)SMEM_DYN);
    cudaFuncSetAttribute(gemm_planes_kernel, cudaFuncAttributeMaxDynamicSharedMemorySize,
                         (int)GSMEM);

    init_bins_kernel<<<1, 32>>>();

    // Pre-split activations and weights into bf16 hi/lo planes
    const int XN4 = BB * NN * DD / 4;   // 524288
    const int WN4 = DD * DD / 4;        // 65536
    presplit_kernel<<<XN4 / 256, 256>>>(query, xh,          xl,          XN4);
    presplit_kernel<<<XN4 / 256, 256>>>(key,   xh + XZ,     xl + XZ,     XN4);
    presplit_kernel<<<XN4 / 256, 256>>>(value, xh + 2 * XZ, xl + 2 * XZ, XN4);
    presplit_kernel<<<WN4 / 256, 256>>>(Wq, wh,          wl,          WN4);
    presplit_kernel<<<WN4 / 256, 256>>>(Wk, wh + WZ,     wl + WZ,     WN4);
    presplit_kernel<<<WN4 / 256, 256>>>(Wv, wh + 2 * WZ, wl + 2 * WZ, WN4);
    presplit_kernel<<<WN4 / 256, 256>>>(Wo, wh + 3 * WZ, wl + 3 * WZ, WN4);

    // Fused QKV projections -> attn planes
    GemmArgs qa;
    qa.Ah = xh; qa.Al = xl; qa.Wh = wh; qa.Wl = wl;
    qa.b0 = bq; qa.b1 = bk; qa.b2 = bv;
    qa.Ch0 = qbh; qa.Cl0 = qbl;
    qa.Ch1 = kbh; qa.Cl1 = kbl;
    qa.Ch2 = vfh; qa.Cl2 = vfl;
    qa.C0 = nullptr;
    gemm_planes_kernel<<<dim3(DD / 128, (BB * NN) / 128, 3), 256, GSMEM>>>(qa, 1);

    precompute_kernel<<<(BB * NN * NN) / 256, 256>>>(coords);
    attn_kernel<<<dim3(NN / 128, BB * HH), 256, SMEM_DYN>>>(bias_table);

    // Output projection (y planes @ Wo planes -> fp32 out)
    GemmArgs oa;
    oa.Ah = yh; oa.Al = yl;
    oa.Wh = wh + 3 * WZ; oa.Wl = wl + 3 * WZ;
    oa.b0 = bo; oa.b1 = bo; oa.b2 = bo;
    oa.Ch0 = nullptr; oa.Cl0 = nullptr;
    oa.Ch1 = nullptr; oa.Cl1 = nullptr;
    oa.Ch2 = nullptr; oa.Cl2 = nullptr;
    oa.C0 = out;
    gemm_planes_kernel<<<dim3(DD / 128, (BB * NN) / 128, 1), 256, GSMEM>>>(oa, 0);
}

// round 15
// speedup vs baseline: 5.1705x; 1.0328x over previous
#include <cuda_runtime.h>
#include <cuda_bf16.h>
#include <cuda_fp16.h>
#include <math_constants.h>

// Problem constants
#define BB 4
#define NN 1024
#define DD 512
#define HH 8
#define HD 64
#define NSP 32
#define NTMP 16

#define XZ (BB * NN * DD / 2)   // u32 per activation plane (1M)
#define WZ (DD * DD / 2)        // u32 per weight plane (128K)

// Scratch (device globals; no allocations allowed)
__device__ unsigned g_xh[3 * XZ];   // split inputs hi (query,key,value)
__device__ unsigned g_xl[3 * XZ];
__device__ unsigned g_wh[4 * WZ];   // split weights hi (Wq,Wk,Wv,Wo)
__device__ unsigned g_wl[4 * WZ];
__device__ unsigned g_yh[XZ];       // attention out planes (bf16 hi/lo)
__device__ unsigned g_yl[XZ];
__device__ unsigned short g_qfh[BB * HH * NN * HD];  // Q fp16 hi plane (b,h,n,d)
__device__ unsigned short g_qfl[BB * HH * NN * HD];  // (written, unused)
__device__ unsigned short g_kfh[BB * HH * NN * HD];  // K fp16 hi/lo
__device__ unsigned short g_kfl[BB * HH * NN * HD];
__device__ unsigned short g_vfh[BB * HH * NN * HD];  // V fp16 hi/lo
__device__ unsigned short g_vfl[BB * HH * NN * HD];
__device__ unsigned g_mi[BB * NN * NN];    // packed: fp16(mask) << 16 | idx
__device__ float g_sbins[NSP];

// ---------------------------------------------------------------------------
// mma + split helpers
// ---------------------------------------------------------------------------
__device__ __forceinline__ void mma_bf16(float* d,
                                         unsigned a0, unsigned a1, unsigned a2, unsigned a3,
                                         unsigned b0, unsigned b1) {
    asm volatile(
        "mma.sync.aligned.m16n8k16.row.col.f32.bf16.bf16.f32 "
        "{%0,%1,%2,%3}, {%4,%5,%6,%7}, {%8,%9}, {%0,%1,%2,%3};\n"
        : "+f"(d[0]), "+f"(d[1]), "+f"(d[2]), "+f"(d[3])
        : "r"(a0), "r"(a1), "r"(a2), "r"(a3), "r"(b0), "r"(b1));
}

__device__ __forceinline__ void mma_f16(float* d,
                                        unsigned a0, unsigned a1, unsigned a2, unsigned a3,
                                        unsigned b0, unsigned b1) {
    asm volatile(
        "mma.sync.aligned.m16n8k16.row.col.f32.f16.f16.f32 "
        "{%0,%1,%2,%3}, {%4,%5,%6,%7}, {%8,%9}, {%0,%1,%2,%3};\n"
        : "+f"(d[0]), "+f"(d[1]), "+f"(d[2]), "+f"(d[3])
        : "r"(a0), "r"(a1), "r"(a2), "r"(a3), "r"(b0), "r"(b1));
}

__device__ __forceinline__ void mma3b(float* d,
                                      const unsigned* ah, const unsigned* al,
                                      unsigned bh0, unsigned bh1,
                                      unsigned bl0, unsigned bl1) {
    mma_bf16(d, ah[0], ah[1], ah[2], ah[3], bh0, bh1);
    mma_bf16(d, ah[0], ah[1], ah[2], ah[3], bl0, bl1);
    mma_bf16(d, al[0], al[1], al[2], al[3], bh0, bh1);
}

__device__ __forceinline__ void split2(float x0, float x1, unsigned& hi, unsigned& lo) {
    __nv_bfloat162 h = __floats2bfloat162_rn(x0, x1);
    float2 hf = __bfloat1622float2(h);
    __nv_bfloat162 l = __floats2bfloat162_rn(x0 - hf.x, x1 - hf.y);
    hi = *(unsigned*)&h;
    lo = *(unsigned*)&l;
}

__device__ __forceinline__ void split2h(float x0, float x1, unsigned& hi, unsigned& lo) {
    __half2 h = __floats2half2_rn(x0, x1);
    float2 hf = __half22float2(h);
    __half2 l = __floats2half2_rn(x0 - hf.x, x1 - hf.y);
    hi = *(unsigned*)&h;
    lo = *(unsigned*)&l;
}

__device__ __forceinline__ unsigned pack2h(float x0, float x1) {
    __half2 h = __floats2half2_rn(x0, x1);
    return *(unsigned*)&h;
}

__device__ __forceinline__ unsigned smem_u32(const void* p) {
    return (unsigned)__cvta_generic_to_shared(p);
}

__device__ __forceinline__ void cp_async16(unsigned dst, const void* src) {
    asm volatile("cp.async.cg.shared.global [%0], [%1], 16;\n"
                 :: "r"(dst), "l"(src));
}
__device__ __forceinline__ void cp_async_commit() {
    asm volatile("cp.async.commit_group;\n" ::: "memory");
}
__device__ __forceinline__ void cp_async_wait0() {
    asm volatile("cp.async.wait_group 0;\n" ::: "memory");
}

__device__ __forceinline__ void ldsm_x4(unsigned& r0, unsigned& r1,
                                        unsigned& r2, unsigned& r3, unsigned addr) {
    asm volatile(
        "ldmatrix.sync.aligned.m8n8.x4.shared.b16 {%0,%1,%2,%3}, [%4];"
        : "=r"(r0), "=r"(r1), "=r"(r2), "=r"(r3) : "r"(addr));
}

__device__ __forceinline__ void ldsm_x4_trans(unsigned& r0, unsigned& r1,
                                              unsigned& r2, unsigned& r3,
                                              unsigned addr) {
    asm volatile(
        "ldmatrix.sync.aligned.m8n8.x4.trans.shared.b16 {%0,%1,%2,%3}, [%4];"
        : "=r"(r0), "=r"(r1), "=r"(r2), "=r"(r3) : "r"(addr));
}

__device__ __forceinline__ float mi_term(unsigned wv, const float* bias_sm) {
    float mv = __half2float(__ushort_as_half((unsigned short)(wv >> 16)));
    return bias_sm[wv & 0xffffu] + mv;
}

// ---------------------------------------------------------------------------
// init bins + elementwise fp32 -> bf16 hi/lo plane split
// ---------------------------------------------------------------------------
__global__ void init_bins_kernel() {
    int i = threadIdx.x;
    if (i < NSP) {
        double L = log(257.0);
        g_sbins[i] = (float)exp((double)i * (L / 31.0));
    }
}

__global__ void presplit_kernel(const float* __restrict__ src,
                                unsigned* __restrict__ hi,
                                unsigned* __restrict__ lo, int n4) {
    int i = blockIdx.x * 256 + threadIdx.x;
    if (i < n4) {
        float4 v = ((const float4*)src)[i];
        unsigned h0, l0, h1, l1;
        split2(v.x, v.y, h0, l0);
        split2(v.z, v.w, h1, l1);
        ((uint2*)hi)[i] = make_uint2(h0, h1);
        ((uint2*)lo)[i] = make_uint2(l0, l1);
    }
}

// ---------------------------------------------------------------------------
// 3xBF16 GEMM on pre-split planes, cp.async double-buffered, ldmatrix frags.
// mode 0: C row-major fp32; mode 1: scatter fp16 hi/lo attn planes
// Tile 128x128, BK=32, 256 threads (8 warps 4x2, warp tile 32x64), 2 CTAs/SM
// ---------------------------------------------------------------------------
#define PWG 20
#define GPLANE (128 * PWG)
#define GSTAGE (4 * GPLANE)
#define GSMEM (2 * GSTAGE * 4)          // 81920 bytes

struct GemmArgs {
    const unsigned* Ah; const unsigned* Al;
    const unsigned* Wh; const unsigned* Wl;
    const float* b0; const float* b1; const float* b2;
    void* Ch0; void* Cl0; void* Ch1; void* Cl1; void* Ch2; void* Cl2;
    float* C0;
};

__global__ void __launch_bounds__(256, 2) gemm_planes_kernel(GemmArgs args, int mode) {
    extern __shared__ unsigned gsm[];

    int z = blockIdx.z;
    const unsigned* Ah = args.Ah + (size_t)z * XZ;
    const unsigned* Al = args.Al + (size_t)z * XZ;
    const unsigned* Wh = args.Wh + (size_t)z * WZ;
    const unsigned* Wl = args.Wl + (size_t)z * WZ;
    const float* bias = (z == 0) ? args.b0 : (z == 1) ? args.b1 : args.b2;
    unsigned* Ch = (unsigned*)((z == 0) ? args.Ch0 : (z == 1) ? args.Ch1 : args.Ch2);
    unsigned* Cl = (unsigned*)((z == 0) ? args.Cl0 : (z == 1) ? args.Cl1 : args.Cl2);

    int tid = threadIdx.x;
    int lane = tid & 31;
    int wid = tid >> 5;
    int warp_m = wid & 3;
    int warp_n = wid >> 2;
    int row0 = blockIdx.y * 128;
    int col0 = blockIdx.x * 128;
    int lg = lane >> 2;
    int lt = lane & 3;

    const unsigned gbase = smem_u32(gsm);
    const int KW = DD / 2;

    const unsigned a_row = lane & 15;
    const unsigned a_colw = (lane >> 4) << 2;
    const unsigned b_row = (lane & 7) + ((lane >> 4) << 3);
    const unsigned b_colw = ((lane >> 3) & 1) << 2;

    auto copyk = [&](int stage, int k0) {
        unsigned sb = gbase + (unsigned)stage * GSTAGE * 4u;
        int ku = k0 >> 1;
#pragma unroll
        for (int c = 0; c < 2; c++) {
            int f = tid + 256 * c;
            int r = f >> 2, c4 = f & 3;
            unsigned doff = (r * PWG + c4 * 4) * 4u;
            size_t ga = (size_t)(row0 + r) * KW + ku + c4 * 4;
            size_t gw = (size_t)(col0 + r) * KW + ku + c4 * 4;
            cp_async16(sb + doff, Ah + ga);
            cp_async16(sb + GPLANE * 4 + doff, Al + ga);
            cp_async16(sb + 2 * GPLANE * 4 + doff, Wh + gw);
            cp_async16(sb + 3 * GPLANE * 4 + doff, Wl + gw);
        }
    };

    float acc[2][8][4];
#pragma unroll
    for (int mf = 0; mf < 2; mf++)
#pragma unroll
        for (int nf = 0; nf < 8; nf++)
#pragma unroll
            for (int zz = 0; zz < 4; zz++) acc[mf][nf][zz] = 0.0f;

    copyk(0, 0);
    cp_async_commit();

    for (int kt = 0; kt < DD / 32; kt++) {
        int cur = kt & 1;
        cp_async_wait0();
        __syncthreads();
        if (kt + 1 < DD / 32) {
            copyk(cur ^ 1, (kt + 1) * 32);
            cp_async_commit();
        }

        unsigned sb = gbase + (unsigned)cur * GSTAGE * 4u;
        unsigned ahb = sb;
        unsigned alb = sb + GPLANE * 4;
        unsigned whb = sb + 2 * GPLANE * 4;
        unsigned wlb = sb + 3 * GPLANE * 4;

#pragma unroll
        for (int kf = 0; kf < 2; kf++) {
            unsigned bh[8][2], bl[8][2];
#pragma unroll
            for (int np = 0; np < 4; np++) {
                unsigned woff = ((warp_n * 64 + np * 16 + b_row) * PWG + kf * 8 + b_colw) * 4u;
                ldsm_x4(bh[2 * np][0], bh[2 * np][1], bh[2 * np + 1][0], bh[2 * np + 1][1],
                        whb + woff);
                ldsm_x4(bl[2 * np][0], bl[2 * np][1], bl[2 * np + 1][0], bl[2 * np + 1][1],
                        wlb + woff);
            }
#pragma unroll
            for (int mf = 0; mf < 2; mf++) {
                unsigned aoff = ((warp_m * 32 + mf * 16 + a_row) * PWG + kf * 8 + a_colw) * 4u;
                unsigned ah4[4], al4[4];
                ldsm_x4(ah4[0], ah4[1], ah4[2], ah4[3], ahb + aoff);
                ldsm_x4(al4[0], al4[1], al4[2], al4[3], alb + aoff);
#pragma unroll
                for (int nf = 0; nf < 8; nf++)
                    mma3b(acc[mf][nf], ah4, al4,
                          bh[nf][0], bh[nf][1], bl[nf][0], bl[nf][1]);
            }
        }
    }

    // Epilogue
#pragma unroll
    for (int mf = 0; mf < 2; mf++) {
#pragma unroll
        for (int nf = 0; nf < 8; nf++) {
            int rr = row0 + warp_m * 32 + mf * 16 + lg;
            int cc = col0 + warp_n * 64 + nf * 8 + lt * 2;
            float b0 = bias[cc], b1 = bias[cc + 1];
#pragma unroll
            for (int half = 0; half < 2; half++) {
                int m = rr + half * 8;
                float v0 = acc[mf][nf][half * 2 + 0] + b0;
                float v1 = acc[mf][nf][half * 2 + 1] + b1;
                if (mode == 0) {
                    *(float2*)&args.C0[(size_t)m * DD + cc] = make_float2(v0, v1);
                } else {
                    int b = m >> 10, n = m & (NN - 1);
                    int h = cc >> 6, d = cc & (HD - 1);
                    size_t widx = (((((size_t)b * HH + h) * NN) + n) * HD + d) >> 1;
                    unsigned hw, lw;
                    split2h(v0, v1, hw, lw);   // all attn planes fp16
                    Ch[widx] = hw;
                    Cl[widx] = lw;
                }
            }
        }
    }
}

// ---------------------------------------------------------------------------
// Precompute per-pair packed (fp16 mask | u16 idx)
// ---------------------------------------------------------------------------
__global__ void precompute_kernel(const float* __restrict__ coords) {
    int gid = blockIdx.x * 256 + threadIdx.x;
    int b = gid >> 20;
    int rem = gid & ((1 << 20) - 1);
    int i = rem >> 10;
    int j = rem & 1023;

    const float* ci = coords + ((size_t)b * NN + i) * 3;
    const float* cj = coords + ((size_t)b * NN + j) * 3;
    float ti = ci[0], yi = ci[1], xi = ci[2];
    float tj = cj[0], yj = cj[1], xj = cj[2];

    float dy = yi - yj, dx = xi - xj, dt = ti - tj;
    float sp2 = dy * dy + dx * dx;
    float sd = sqrtf(fmaxf(sp2, 0.0f));
    float fd = sqrtf(fmaxf(dt * dt + dy * dy + dx * dx, 0.0f));

    int c = 0;
#pragma unroll
    for (int s = 0; s < NSP; s++) c += (g_sbins[s] < sd) ? 1 : 0;
    int sidx = min(c, NSP - 1);

    int tc = (int)ceilf(dt + 16.0f);
    tc = max(0, min(2 * NTMP, tc));

    float maskval = (sd > 256.0f ? -1000.0f : 0.0f) + expf(-0.1f * fd);
    unsigned short hb = __half_as_ushort(__float2half_rn(maskval));
    g_mi[gid] = ((unsigned)hb << 16) | (unsigned)(sidx + tc * NSP);
}

// ---------------------------------------------------------------------------
// Flash attention: fp16 2-term QK (Q single, K hi/lo) and PV (P single, V hi/lo),
// cp.async double-buffered K/V, P in registers, packed mask+idx, smem bias.
// 2 CTAs/SM. grid: (N/128, B*H). 256 threads (8 warps).
// ---------------------------------------------------------------------------
#define PW 36
#define PLANE (64 * PW)
#define STAGE_WORDS (4 * PLANE)
#define SMEM_DYN (2 * STAGE_WORDS * 4)     // 73728 bytes
#define NBIAS ((2 * NTMP + 1) * NSP)       // 1056

__global__ void __launch_bounds__(256, 2) attn_kernel(const float* __restrict__ bias_table) {
    extern __shared__ unsigned dynsm[];
    __shared__ float bias_sm[NBIAS];

    int bh_ = blockIdx.y;
    int b = bh_ >> 3, h = bh_ & 7;
    int i0 = blockIdx.x * 128;
    int tid = threadIdx.x;
    int lane = tid & 31;
    int w = tid >> 5;
    int lg = lane >> 2;
    int lt = lane & 3;
    int m = w * 16 + lg;

    for (int i = tid; i < NBIAS; i += 256)
        bias_sm[i] = bias_table[i * HH + h];

    const unsigned* kbh = (const unsigned*)g_kfh + (size_t)bh_ * NN * (HD / 2);
    const unsigned* kbl = (const unsigned*)g_kfl + (size_t)bh_ * NN * (HD / 2);
    const unsigned* vbh = (const unsigned*)g_vfh + (size_t)bh_ * NN * (HD / 2);
    const unsigned* vbl = (const unsigned*)g_vfl + (size_t)bh_ * NN * (HD / 2);
    const unsigned dyn_base = smem_u32(dynsm);

    int cp_row0 = tid >> 3, cp_c4 = tid & 7;
    int cp_row1 = cp_row0 + 32;

    // Q A-fragments (single fp16) from global plane (one-time)
    unsigned qf[4][4];
    {
        const unsigned* qhp = (const unsigned*)g_qfh + ((size_t)bh_ * NN + i0) * (HD / 2);
#pragma unroll
        for (int kf = 0; kf < 4; kf++) {
            int base = m * (HD / 2) + kf * 8 + lt;
            qf[kf][0] = qhp[base];
            qf[kf][1] = qhp[base + 8 * (HD / 2)];
            qf[kf][2] = qhp[base + 4];
            qf[kf][3] = qhp[base + 8 * (HD / 2) + 4];
        }
    }

    float o[8][4];
#pragma unroll
    for (int nf = 0; nf < 8; nf++)
#pragma unroll
        for (int zz = 0; zz < 4; zz++) o[nf][zz] = 0.0f;
    float m0 = -CUDART_INF_F, m1 = -CUDART_INF_F;
    float l0s = 0.0f, l1s = 0.0f;

    const size_t mirow0 = ((size_t)b * NN + (i0 + m)) * NN;
    const size_t mirow1 = mirow0 + 8 * (size_t)NN;

    const unsigned k_row = (lane & 7) + ((lane >> 4) << 3);
    const unsigned k_colw = ((lane >> 3) & 1) << 2;
    const unsigned v_row = lane & 15;
    const unsigned v_colw = (lane >> 4) << 2;

    auto copy_tile = [&](int stage, int j0) {
        unsigned sb = dyn_base + (unsigned)stage * STAGE_WORDS * 4;
        size_t g0 = (size_t)(j0 + cp_row0) * (HD / 2) + cp_c4 * 4;
        size_t g1 = (size_t)(j0 + cp_row1) * (HD / 2) + cp_c4 * 4;
        unsigned d0 = (cp_row0 * PW + cp_c4 * 4) * 4u;
        unsigned d1 = (cp_row1 * PW + cp_c4 * 4) * 4u;
        cp_async16(sb + d0, kbh + g0);
        cp_async16(sb + d1, kbh + g1);
        cp_async16(sb + PLANE * 4 + d0, kbl + g0);
        cp_async16(sb + PLANE * 4 + d1, kbl + g1);
        cp_async16(sb + 2 * PLANE * 4 + d0, vbh + g0);
        cp_async16(sb + 2 * PLANE * 4 + d1, vbh + g1);
        cp_async16(sb + 3 * PLANE * 4 + d0, vbl + g0);
        cp_async16(sb + 3 * PLANE * 4 + d1, vbl + g1);
    };

    copy_tile(0, 0);
    cp_async_commit();

    for (int jt = 0; jt < NN / 64; jt++) {
        int cur = jt & 1;
        cp_async_wait0();
        __syncthreads();
        if (jt + 1 < NN / 64) {
            copy_tile(cur ^ 1, (jt + 1) * 64);
            cp_async_commit();
        }

        unsigned sb = dyn_base + (unsigned)cur * STAGE_WORDS * 4;
        unsigned kh_base = sb;
        unsigned kl_base = sb + PLANE * 4;
        unsigned vh_base = sb + 2 * PLANE * 4;
        unsigned vl_base = sb + 3 * PLANE * 4;
        int j0 = jt * 64;

        // ---- QK^T: fp16 2-term (Q single, K hi/lo)
        float s[8][4];
#pragma unroll
        for (int nf = 0; nf < 8; nf++)
            s[nf][0] = s[nf][1] = s[nf][2] = s[nf][3] = 0.0f;
#pragma unroll
        for (int kf = 0; kf < 4; kf++) {
#pragma unroll
            for (int np = 0; np < 4; np++) {
                unsigned woff = ((np * 16 + k_row) * PW + kf * 8 + k_colw) * 4u;
                unsigned h0, h1, h2, h3, l0_, l1_, l2_, l3_;
                ldsm_x4(h0, h1, h2, h3, kh_base + woff);
                ldsm_x4(l0_, l1_, l2_, l3_, kl_base + woff);
                mma_f16(s[2 * np],     qf[kf][0], qf[kf][1], qf[kf][2], qf[kf][3], h0, h1);
                mma_f16(s[2 * np],     qf[kf][0], qf[kf][1], qf[kf][2], qf[kf][3], l0_, l1_);
                mma_f16(s[2 * np + 1], qf[kf][0], qf[kf][1], qf[kf][2], qf[kf][3], h2, h3);
                mma_f16(s[2 * np + 1], qf[kf][0], qf[kf][1], qf[kf][2], qf[kf][3], l2_, l3_);
            }
        }

        // ---- bias + mask
#pragma unroll
        for (int nf = 0; nf < 8; nf++) {
            int jc = j0 + nf * 8 + lt * 2;
            uint2 w0 = *(const uint2*)&g_mi[mirow0 + jc];
            uint2 w1 = *(const uint2*)&g_mi[mirow1 + jc];
            s[nf][0] = s[nf][0] * 0.125f + mi_term(w0.x, bias_sm);
            s[nf][1] = s[nf][1] * 0.125f + mi_term(w0.y, bias_sm);
            s[nf][2] = s[nf][2] * 0.125f + mi_term(w1.x, bias_sm);
            s[nf][3] = s[nf][3] * 0.125f + mi_term(w1.y, bias_sm);
        }

        // ---- online softmax
        float t0 = s[0][0], t1 = s[0][2];
#pragma unroll
        for (int nf = 0; nf < 8; nf++) {
            t0 = fmaxf(t0, fmaxf(s[nf][0], s[nf][1]));
            t1 = fmaxf(t1, fmaxf(s[nf][2], s[nf][3]));
        }
        t0 = fmaxf(t0, __shfl_xor_sync(0xffffffffu, t0, 1));
        t0 = fmaxf(t0, __shfl_xor_sync(0xffffffffu, t0, 2));
        t1 = fmaxf(t1, __shfl_xor_sync(0xffffffffu, t1, 1));
        t1 = fmaxf(t1, __shfl_xor_sync(0xffffffffu, t1, 2));
        float nm0 = fmaxf(m0, t0), nm1 = fmaxf(m1, t1);
        float sc0 = __expf(m0 - nm0), sc1 = __expf(m1 - nm1);

        float sum0 = 0.0f, sum1 = 0.0f;
#pragma unroll
        for (int nf = 0; nf < 8; nf++) {
            s[nf][0] = __expf(s[nf][0] - nm0);
            s[nf][1] = __expf(s[nf][1] - nm0);
            s[nf][2] = __expf(s[nf][2] - nm1);
            s[nf][3] = __expf(s[nf][3] - nm1);
            sum0 += s[nf][0] + s[nf][1];
            sum1 += s[nf][2] + s[nf][3];
        }
        sum0 += __shfl_xor_sync(0xffffffffu, sum0, 1);
        sum0 += __shfl_xor_sync(0xffffffffu, sum0, 2);
        sum1 += __shfl_xor_sync(0xffffffffu, sum1, 1);
        sum1 += __shfl_xor_sync(0xffffffffu, sum1, 2);
        l0s = l0s * sc0 + sum0;
        l1s = l1s * sc1 + sum1;
        m0 = nm0; m1 = nm1;
#pragma unroll
        for (int nf = 0; nf < 8; nf++) {
            o[nf][0] *= sc0; o[nf][1] *= sc0;
            o[nf][2] *= sc1; o[nf][3] *= sc1;
        }

        // ---- PV (fp16 2-term)
#pragma unroll
        for (int kf = 0; kf < 4; kf++) {
            unsigned phf[4];
            phf[0] = pack2h(s[2 * kf][0],     s[2 * kf][1]);
            phf[1] = pack2h(s[2 * kf][2],     s[2 * kf][3]);
            phf[2] = pack2h(s[2 * kf + 1][0], s[2 * kf + 1][1]);
            phf[3] = pack2h(s[2 * kf + 1][2], s[2 * kf + 1][3]);
            unsigned vrow = kf * 16 + v_row;
#pragma unroll
            for (int nf2 = 0; nf2 < 4; nf2++) {
                unsigned woff = (vrow * PW + nf2 * 8 + v_colw) * 4u;
                unsigned h0, h1, h2, h3, l0_, l1_, l2_, l3_;
                ldsm_x4_trans(h0, h1, h2, h3, vh_base + woff);
                ldsm_x4_trans(l0_, l1_, l2_, l3_, vl_base + woff);
                mma_f16(o[2 * nf2],     phf[0], phf[1], phf[2], phf[3], h0, h1);
                mma_f16(o[2 * nf2],     phf[0], phf[1], phf[2], phf[3], l0_, l1_);
                mma_f16(o[2 * nf2 + 1], phf[0], phf[1], phf[2], phf[3], h2, h3);
                mma_f16(o[2 * nf2 + 1], phf[0], phf[1], phf[2], phf[3], l2_, l3_);
            }
        }
    }

    // Epilogue: normalize and write bf16 hi/lo planes
    float inv0 = 1.0f / l0s;
    float inv1 = 1.0f / l1s;
    int r0 = i0 + m;
#pragma unroll
    for (int nf = 0; nf < 8; nf++) {
        int cc = h * HD + nf * 8 + lt * 2;
        size_t idx0 = ((size_t)(b * NN + r0) * DD + cc) >> 1;
        size_t idx1 = ((size_t)(b * NN + r0 + 8) * DD + cc) >> 1;
        unsigned hw, lw;
        split2(o[nf][0] * inv0, o[nf][1] * inv0, hw, lw);
        g_yh[idx0] = hw; g_yl[idx0] = lw;
        split2(o[nf][2] * inv1, o[nf][3] * inv1, hw, lw);
        g_yh[idx1] = hw; g_yl[idx1] = lw;
    }
}

// ---------------------------------------------------------------------------
// Host launch
// ---------------------------------------------------------------------------
extern "C" void kernel_launch(void* const* d_in, const int* in_sizes, int n_in,
                              void* d_out, int out_size) {
    const float* query = (const float*)d_in[0];
    const float* key   = (const float*)d_in[1];
    const float* value = (const float*)d_in[2];
    const float* coords = (const float*)d_in[3];
    const float* Wq = (const float*)d_in[4];
    const float* bq = (const float*)d_in[5];
    const float* Wk = (const float*)d_in[6];
    const float* bk = (const float*)d_in[7];
    const float* Wv = (const float*)d_in[8];
    const float* bv = (const float*)d_in[9];
    const float* Wo = (const float*)d_in[10];
    const float* bo = (const float*)d_in[11];
    const float* bias_table = (const float*)d_in[12];
    float* out = (float*)d_out;

    unsigned *xh, *xl, *wh, *wl, *yh, *yl;
    void *qfh, *qfl, *kfh, *kfl, *vfh, *vfl;
    cudaGetSymbolAddress((void**)&xh, g_xh);
    cudaGetSymbolAddress((void**)&xl, g_xl);
    cudaGetSymbolAddress((void**)&wh, g_wh);
    cudaGetSymbolAddress((void**)&wl, g_wl);
    cudaGetSymbolAddress((void**)&yh, g_yh);
    cudaGetSymbolAddress((void**)&yl, g_yl);
    cudaGetSymbolAddress(&qfh, g_qfh);
    cudaGetSymbolAddress(&qfl, g_qfl);
    cudaGetSymbolAddress(&kfh, g_kfh);
    cudaGetSymbolAddress(&kfl, g_kfl);
    cudaGetSymbolAddress(&vfh, g_vfh);
    cudaGetSymbolAddress(&vfl, g_vfl);

    cudaFuncSetAttribute(attn_kernel, cudaFuncAttributeMaxDynamicSharedMemorySize,
                         (int)SMEM_DYN);
    cudaFuncSetAttribute(gemm_planes_kernel, cudaFuncAttributeMaxDynamicSharedMemorySize,
                         (int)GSMEM);

    init_bins_kernel<<<1, 32>>>();

    // Pre-split activations and weights into bf16 hi/lo planes
    const int XN4 = BB * NN * DD / 4;
    const int WN4 = DD * DD / 4;
    presplit_kernel<<<XN4 / 256, 256>>>(query, xh,          xl,          XN4);
    presplit_kernel<<<XN4 / 256, 256>>>(key,   xh + XZ,     xl + XZ,     XN4);
    presplit_kernel<<<XN4 / 256, 256>>>(value, xh + 2 * XZ, xl + 2 * XZ, XN4);
    presplit_kernel<<<WN4 / 256, 256>>>(Wq, wh,          wl,          WN4);
    presplit_kernel<<<WN4 / 256, 256>>>(Wk, wh + WZ,     wl + WZ,     WN4);
    presplit_kernel<<<WN4 / 256, 256>>>(Wv, wh + 2 * WZ, wl + 2 * WZ, WN4);
    presplit_kernel<<<WN4 / 256, 256>>>(Wo, wh + 3 * WZ, wl + 3 * WZ, WN4);

    // Fused QKV projections -> fp16 attn planes
    GemmArgs qa;
    qa.Ah = xh; qa.Al = xl; qa.Wh = wh; qa.Wl = wl;
    qa.b0 = bq; qa.b1 = bk; qa.b2 = bv;
    qa.Ch0 = qfh; qa.Cl0 = qfl;
    qa.Ch1 = kfh; qa.Cl1 = kfl;
    qa.Ch2 = vfh; qa.Cl2 = vfl;
    qa.C0 = nullptr;
    gemm_planes_kernel<<<dim3(DD / 128, (BB * NN) / 128, 3), 256, GSMEM>>>(qa, 1);

    precompute_kernel<<<(BB * NN * NN) / 256, 256>>>(coords);
    attn_kernel<<<dim3(NN / 128, BB * HH), 256, SMEM_DYN>>>(bias_table);

    // Output projection (y planes @ Wo planes -> fp32 out)
    GemmArgs oa;
    oa.Ah = yh; oa.Al = yl;
    oa.Wh = wh + 3 * WZ; oa.Wl = wl + 3 * WZ;
    oa.b0 = bo; oa.b1 = bo; oa.b2 = bo;
    oa.Ch0 = nullptr; oa.Cl0 = nullptr;
    oa.Ch1 = nullptr; oa.Cl1 = nullptr;
    oa.Ch2 = nullptr; oa.Cl2 = nullptr;
    oa.C0 = out;
    gemm_planes_kernel<<<dim3(DD / 128, (BB * NN) / 128, 1), 256, GSMEM>>>(oa, 0);
}

// round 16
// speedup vs baseline: 5.7992x; 1.1216x over previous
#include <cuda_runtime.h>
#include <cuda_bf16.h>
#include <cuda_fp16.h>
#include <math_constants.h>

// Problem constants
#define BB 4
#define NN 1024
#define DD 512
#define HH 8
#define HD 64
#define NSP 32
#define NTMP 16

#define XZ (BB * NN * DD / 2)   // u32 per activation plane (1M)
#define WZ (DD * DD / 2)        // u32 per weight plane (128K)

// Scratch (device globals; no allocations allowed)
__device__ unsigned g_xh[3 * XZ];   // split inputs hi (query,key,value)
__device__ unsigned g_xl[3 * XZ];
__device__ unsigned g_wh[4 * WZ];   // split weights hi (Wq,Wk,Wv,Wo)
__device__ unsigned g_wl[4 * WZ];
__device__ unsigned g_yh[XZ];       // attention out planes (bf16 hi/lo)
__device__ unsigned g_yl[XZ];
__device__ unsigned short g_qfh[BB * HH * NN * HD];  // Q fp16 plane (b,h,n,d)
__device__ unsigned short g_kfh[BB * HH * NN * HD];  // K fp16 plane
__device__ unsigned short g_vfh[BB * HH * NN * HD];  // V fp16 plane
__device__ unsigned g_mi[BB * NN * NN];    // packed: fp16(mask) << 16 | idx
__device__ float g_sbins[NSP];

// ---------------------------------------------------------------------------
// mma + split helpers
// ---------------------------------------------------------------------------
__device__ __forceinline__ void mma_bf16(float* d,
                                         unsigned a0, unsigned a1, unsigned a2, unsigned a3,
                                         unsigned b0, unsigned b1) {
    asm volatile(
        "mma.sync.aligned.m16n8k16.row.col.f32.bf16.bf16.f32 "
        "{%0,%1,%2,%3}, {%4,%5,%6,%7}, {%8,%9}, {%0,%1,%2,%3};\n"
        : "+f"(d[0]), "+f"(d[1]), "+f"(d[2]), "+f"(d[3])
        : "r"(a0), "r"(a1), "r"(a2), "r"(a3), "r"(b0), "r"(b1));
}

__device__ __forceinline__ void mma_f16(float* d,
                                        unsigned a0, unsigned a1, unsigned a2, unsigned a3,
                                        unsigned b0, unsigned b1) {
    asm volatile(
        "mma.sync.aligned.m16n8k16.row.col.f32.f16.f16.f32 "
        "{%0,%1,%2,%3}, {%4,%5,%6,%7}, {%8,%9}, {%0,%1,%2,%3};\n"
        : "+f"(d[0]), "+f"(d[1]), "+f"(d[2]), "+f"(d[3])
        : "r"(a0), "r"(a1), "r"(a2), "r"(a3), "r"(b0), "r"(b1));
}

__device__ __forceinline__ void mma3b(float* d,
                                      const unsigned* ah, const unsigned* al,
                                      unsigned bh0, unsigned bh1,
                                      unsigned bl0, unsigned bl1) {
    mma_bf16(d, ah[0], ah[1], ah[2], ah[3], bh0, bh1);
    mma_bf16(d, ah[0], ah[1], ah[2], ah[3], bl0, bl1);
    mma_bf16(d, al[0], al[1], al[2], al[3], bh0, bh1);
}

__device__ __forceinline__ void split2(float x0, float x1, unsigned& hi, unsigned& lo) {
    __nv_bfloat162 h = __floats2bfloat162_rn(x0, x1);
    float2 hf = __bfloat1622float2(h);
    __nv_bfloat162 l = __floats2bfloat162_rn(x0 - hf.x, x1 - hf.y);
    hi = *(unsigned*)&h;
    lo = *(unsigned*)&l;
}

__device__ __forceinline__ unsigned pack2h(float x0, float x1) {
    __half2 h = __floats2half2_rn(x0, x1);
    return *(unsigned*)&h;
}

__device__ __forceinline__ unsigned smem_u32(const void* p) {
    return (unsigned)__cvta_generic_to_shared(p);
}

__device__ __forceinline__ void cp_async16(unsigned dst, const void* src) {
    asm volatile("cp.async.cg.shared.global [%0], [%1], 16;\n"
                 :: "r"(dst), "l"(src));
}
__device__ __forceinline__ void cp_async_commit() {
    asm volatile("cp.async.commit_group;\n" ::: "memory");
}
__device__ __forceinline__ void cp_async_wait0() {
    asm volatile("cp.async.wait_group 0;\n" ::: "memory");
}

__device__ __forceinline__ void ldsm_x4(unsigned& r0, unsigned& r1,
                                        unsigned& r2, unsigned& r3, unsigned addr) {
    asm volatile(
        "ldmatrix.sync.aligned.m8n8.x4.shared.b16 {%0,%1,%2,%3}, [%4];"
        : "=r"(r0), "=r"(r1), "=r"(r2), "=r"(r3) : "r"(addr));
}

__device__ __forceinline__ void ldsm_x4_trans(unsigned& r0, unsigned& r1,
                                              unsigned& r2, unsigned& r3,
                                              unsigned addr) {
    asm volatile(
        "ldmatrix.sync.aligned.m8n8.x4.trans.shared.b16 {%0,%1,%2,%3}, [%4];"
        : "=r"(r0), "=r"(r1), "=r"(r2), "=r"(r3) : "r"(addr));
}

__device__ __forceinline__ float mi_term(unsigned wv, const float* bias_sm) {
    float mv = __half2float(__ushort_as_half((unsigned short)(wv >> 16)));
    return bias_sm[wv & 0xffffu] + mv;
}

// ---------------------------------------------------------------------------
// init bins + elementwise fp32 -> bf16 hi/lo plane split
// ---------------------------------------------------------------------------
__global__ void init_bins_kernel() {
    int i = threadIdx.x;
    if (i < NSP) {
        double L = log(257.0);
        g_sbins[i] = (float)exp((double)i * (L / 31.0));
    }
}

__global__ void presplit_kernel(const float* __restrict__ src,
                                unsigned* __restrict__ hi,
                                unsigned* __restrict__ lo, int n4) {
    int i = blockIdx.x * 256 + threadIdx.x;
    if (i < n4) {
        float4 v = ((const float4*)src)[i];
        unsigned h0, l0, h1, l1;
        split2(v.x, v.y, h0, l0);
        split2(v.z, v.w, h1, l1);
        ((uint2*)hi)[i] = make_uint2(h0, h1);
        ((uint2*)lo)[i] = make_uint2(l0, l1);
    }
}

// ---------------------------------------------------------------------------
// 3xBF16 GEMM on pre-split planes, cp.async double-buffered, ldmatrix frags.
// mode 0: C row-major fp32; mode 1: scatter single-fp16 attn plane
// Tile 128x128, BK=32, 256 threads (8 warps 4x2, warp tile 32x64), 2 CTAs/SM
// ---------------------------------------------------------------------------
#define PWG 20
#define GPLANE (128 * PWG)
#define GSTAGE (4 * GPLANE)
#define GSMEM (2 * GSTAGE * 4)          // 81920 bytes

struct GemmArgs {
    const unsigned* Ah; const unsigned* Al;
    const unsigned* Wh; const unsigned* Wl;
    const float* b0; const float* b1; const float* b2;
    void* C16_0; void* C16_1; void* C16_2;   // fp16 attn planes
    float* C0;
};

__global__ void __launch_bounds__(256, 2) gemm_planes_kernel(GemmArgs args, int mode) {
    extern __shared__ unsigned gsm[];

    int z = blockIdx.z;
    const unsigned* Ah = args.Ah + (size_t)z * XZ;
    const unsigned* Al = args.Al + (size_t)z * XZ;
    const unsigned* Wh = args.Wh + (size_t)z * WZ;
    const unsigned* Wl = args.Wl + (size_t)z * WZ;
    const float* bias = (z == 0) ? args.b0 : (z == 1) ? args.b1 : args.b2;
    unsigned* C16 = (unsigned*)((z == 0) ? args.C16_0 : (z == 1) ? args.C16_1 : args.C16_2);

    int tid = threadIdx.x;
    int lane = tid & 31;
    int wid = tid >> 5;
    int warp_m = wid & 3;
    int warp_n = wid >> 2;
    int row0 = blockIdx.y * 128;
    int col0 = blockIdx.x * 128;
    int lg = lane >> 2;
    int lt = lane & 3;

    const unsigned gbase = smem_u32(gsm);
    const int KW = DD / 2;

    const unsigned a_row = lane & 15;
    const unsigned a_colw = (lane >> 4) << 2;
    const unsigned b_row = (lane & 7) + ((lane >> 4) << 3);
    const unsigned b_colw = ((lane >> 3) & 1) << 2;

    auto copyk = [&](int stage, int k0) {
        unsigned sb = gbase + (unsigned)stage * GSTAGE * 4u;
        int ku = k0 >> 1;
#pragma unroll
        for (int c = 0; c < 2; c++) {
            int f = tid + 256 * c;
            int r = f >> 2, c4 = f & 3;
            unsigned doff = (r * PWG + c4 * 4) * 4u;
            size_t ga = (size_t)(row0 + r) * KW + ku + c4 * 4;
            size_t gw = (size_t)(col0 + r) * KW + ku + c4 * 4;
            cp_async16(sb + doff, Ah + ga);
            cp_async16(sb + GPLANE * 4 + doff, Al + ga);
            cp_async16(sb + 2 * GPLANE * 4 + doff, Wh + gw);
            cp_async16(sb + 3 * GPLANE * 4 + doff, Wl + gw);
        }
    };

    float acc[2][8][4];
#pragma unroll
    for (int mf = 0; mf < 2; mf++)
#pragma unroll
        for (int nf = 0; nf < 8; nf++)
#pragma unroll
            for (int zz = 0; zz < 4; zz++) acc[mf][nf][zz] = 0.0f;

    copyk(0, 0);
    cp_async_commit();

    for (int kt = 0; kt < DD / 32; kt++) {
        int cur = kt & 1;
        cp_async_wait0();
        __syncthreads();
        if (kt + 1 < DD / 32) {
            copyk(cur ^ 1, (kt + 1) * 32);
            cp_async_commit();
        }

        unsigned sb = gbase + (unsigned)cur * GSTAGE * 4u;
        unsigned ahb = sb;
        unsigned alb = sb + GPLANE * 4;
        unsigned whb = sb + 2 * GPLANE * 4;
        unsigned wlb = sb + 3 * GPLANE * 4;

#pragma unroll
        for (int kf = 0; kf < 2; kf++) {
            unsigned bh[8][2], bl[8][2];
#pragma unroll
            for (int np = 0; np < 4; np++) {
                unsigned woff = ((warp_n * 64 + np * 16 + b_row) * PWG + kf * 8 + b_colw) * 4u;
                ldsm_x4(bh[2 * np][0], bh[2 * np][1], bh[2 * np + 1][0], bh[2 * np + 1][1],
                        whb + woff);
                ldsm_x4(bl[2 * np][0], bl[2 * np][1], bl[2 * np + 1][0], bl[2 * np + 1][1],
                        wlb + woff);
            }
#pragma unroll
            for (int mf = 0; mf < 2; mf++) {
                unsigned aoff = ((warp_m * 32 + mf * 16 + a_row) * PWG + kf * 8 + a_colw) * 4u;
                unsigned ah4[4], al4[4];
                ldsm_x4(ah4[0], ah4[1], ah4[2], ah4[3], ahb + aoff);
                ldsm_x4(al4[0], al4[1], al4[2], al4[3], alb + aoff);
#pragma unroll
                for (int nf = 0; nf < 8; nf++)
                    mma3b(acc[mf][nf], ah4, al4,
                          bh[nf][0], bh[nf][1], bl[nf][0], bl[nf][1]);
            }
        }
    }

    // Epilogue
#pragma unroll
    for (int mf = 0; mf < 2; mf++) {
#pragma unroll
        for (int nf = 0; nf < 8; nf++) {
            int rr = row0 + warp_m * 32 + mf * 16 + lg;
            int cc = col0 + warp_n * 64 + nf * 8 + lt * 2;
            float b0 = bias[cc], b1 = bias[cc + 1];
#pragma unroll
            for (int half = 0; half < 2; half++) {
                int m = rr + half * 8;
                float v0 = acc[mf][nf][half * 2 + 0] + b0;
                float v1 = acc[mf][nf][half * 2 + 1] + b1;
                if (mode == 0) {
                    *(float2*)&args.C0[(size_t)m * DD + cc] = make_float2(v0, v1);
                } else {
                    int b = m >> 10, n = m & (NN - 1);
                    int h = cc >> 6, d = cc & (HD - 1);
                    size_t widx = (((((size_t)b * HH + h) * NN) + n) * HD + d) >> 1;
                    C16[widx] = pack2h(v0, v1);   // single fp16 plane
                }
            }
        }
    }
}

// ---------------------------------------------------------------------------
// Precompute per-pair packed (fp16 mask | u16 idx)
// ---------------------------------------------------------------------------
__global__ void precompute_kernel(const float* __restrict__ coords) {
    int gid = blockIdx.x * 256 + threadIdx.x;
    int b = gid >> 20;
    int rem = gid & ((1 << 20) - 1);
    int i = rem >> 10;
    int j = rem & 1023;

    const float* ci = coords + ((size_t)b * NN + i) * 3;
    const float* cj = coords + ((size_t)b * NN + j) * 3;
    float ti = ci[0], yi = ci[1], xi = ci[2];
    float tj = cj[0], yj = cj[1], xj = cj[2];

    float dy = yi - yj, dx = xi - xj, dt = ti - tj;
    float sp2 = dy * dy + dx * dx;
    float sd = sqrtf(fmaxf(sp2, 0.0f));
    float fd = sqrtf(fmaxf(dt * dt + dy * dy + dx * dx, 0.0f));

    int c = 0;
#pragma unroll
    for (int s = 0; s < NSP; s++) c += (g_sbins[s] < sd) ? 1 : 0;
    int sidx = min(c, NSP - 1);

    int tc = (int)ceilf(dt + 16.0f);
    tc = max(0, min(2 * NTMP, tc));

    float maskval = (sd > 256.0f ? -1000.0f : 0.0f) + expf(-0.1f * fd);
    unsigned short hb = __half_as_ushort(__float2half_rn(maskval));
    g_mi[gid] = ((unsigned)hb << 16) | (unsigned)(sidx + tc * NSP);
}

// ---------------------------------------------------------------------------
// Flash attention: single-fp16 Q,K,V,P. cp.async double-buffered K/V,
// P in registers, packed mask+idx, smem bias. 2 CTAs/SM.
// grid: (N/128, B*H). 256 threads (8 warps); warp w owns q rows w*16..+16
// dynamic smem: 2 stages x 2 planes (K,V) x [64 rows][36 words]
// ---------------------------------------------------------------------------
#define PW 36
#define PLANE (64 * PW)
#define STAGE_WORDS (2 * PLANE)
#define SMEM_DYN (2 * STAGE_WORDS * 4)     // 36864 bytes
#define NBIAS ((2 * NTMP + 1) * NSP)       // 1056

__global__ void __launch_bounds__(256, 2) attn_kernel(const float* __restrict__ bias_table) {
    extern __shared__ unsigned dynsm[];
    __shared__ float bias_sm[NBIAS];

    int bh_ = blockIdx.y;
    int b = bh_ >> 3, h = bh_ & 7;
    int i0 = blockIdx.x * 128;
    int tid = threadIdx.x;
    int lane = tid & 31;
    int w = tid >> 5;
    int lg = lane >> 2;
    int lt = lane & 3;
    int m = w * 16 + lg;

    for (int i = tid; i < NBIAS; i += 256)
        bias_sm[i] = bias_table[i * HH + h];

    const unsigned* kbh = (const unsigned*)g_kfh + (size_t)bh_ * NN * (HD / 2);
    const unsigned* vbh = (const unsigned*)g_vfh + (size_t)bh_ * NN * (HD / 2);
    const unsigned dyn_base = smem_u32(dynsm);

    int cp_row0 = tid >> 3, cp_c4 = tid & 7;
    int cp_row1 = cp_row0 + 32;

    // Q A-fragments (single fp16) from global plane (one-time)
    unsigned qf[4][4];
    {
        const unsigned* qhp = (const unsigned*)g_qfh + ((size_t)bh_ * NN + i0) * (HD / 2);
#pragma unroll
        for (int kf = 0; kf < 4; kf++) {
            int base = m * (HD / 2) + kf * 8 + lt;
            qf[kf][0] = qhp[base];
            qf[kf][1] = qhp[base + 8 * (HD / 2)];
            qf[kf][2] = qhp[base + 4];
            qf[kf][3] = qhp[base + 8 * (HD / 2) + 4];
        }
    }

    float o[8][4];
#pragma unroll
    for (int nf = 0; nf < 8; nf++)
#pragma unroll
        for (int zz = 0; zz < 4; zz++) o[nf][zz] = 0.0f;
    float m0 = -CUDART_INF_F, m1 = -CUDART_INF_F;
    float l0s = 0.0f, l1s = 0.0f;

    const size_t mirow0 = ((size_t)b * NN + (i0 + m)) * NN;
    const size_t mirow1 = mirow0 + 8 * (size_t)NN;

    const unsigned k_row = (lane & 7) + ((lane >> 4) << 3);
    const unsigned k_colw = ((lane >> 3) & 1) << 2;
    const unsigned v_row = lane & 15;
    const unsigned v_colw = (lane >> 4) << 2;

    auto copy_tile = [&](int stage, int j0) {
        unsigned sb = dyn_base + (unsigned)stage * STAGE_WORDS * 4;
        size_t g0 = (size_t)(j0 + cp_row0) * (HD / 2) + cp_c4 * 4;
        size_t g1 = (size_t)(j0 + cp_row1) * (HD / 2) + cp_c4 * 4;
        unsigned d0 = (cp_row0 * PW + cp_c4 * 4) * 4u;
        unsigned d1 = (cp_row1 * PW + cp_c4 * 4) * 4u;
        cp_async16(sb + d0, kbh + g0);
        cp_async16(sb + d1, kbh + g1);
        cp_async16(sb + PLANE * 4 + d0, vbh + g0);
        cp_async16(sb + PLANE * 4 + d1, vbh + g1);
    };

    copy_tile(0, 0);
    cp_async_commit();

    for (int jt = 0; jt < NN / 64; jt++) {
        int cur = jt & 1;
        cp_async_wait0();
        __syncthreads();
        if (jt + 1 < NN / 64) {
            copy_tile(cur ^ 1, (jt + 1) * 64);
            cp_async_commit();
        }

        unsigned sb = dyn_base + (unsigned)cur * STAGE_WORDS * 4;
        unsigned kh_base = sb;
        unsigned vh_base = sb + PLANE * 4;
        int j0 = jt * 64;

        // ---- QK^T: single fp16
        float s[8][4];
#pragma unroll
        for (int nf = 0; nf < 8; nf++)
            s[nf][0] = s[nf][1] = s[nf][2] = s[nf][3] = 0.0f;
#pragma unroll
        for (int kf = 0; kf < 4; kf++) {
#pragma unroll
            for (int np = 0; np < 4; np++) {
                unsigned woff = ((np * 16 + k_row) * PW + kf * 8 + k_colw) * 4u;
                unsigned h0, h1, h2, h3;
                ldsm_x4(h0, h1, h2, h3, kh_base + woff);
                mma_f16(s[2 * np],     qf[kf][0], qf[kf][1], qf[kf][2], qf[kf][3], h0, h1);
                mma_f16(s[2 * np + 1], qf[kf][0], qf[kf][1], qf[kf][2], qf[kf][3], h2, h3);
            }
        }

        // ---- bias + mask
#pragma unroll
        for (int nf = 0; nf < 8; nf++) {
            int jc = j0 + nf * 8 + lt * 2;
            uint2 w0 = *(const uint2*)&g_mi[mirow0 + jc];
            uint2 w1 = *(const uint2*)&g_mi[mirow1 + jc];
            s[nf][0] = s[nf][0] * 0.125f + mi_term(w0.x, bias_sm);
            s[nf][1] = s[nf][1] * 0.125f + mi_term(w0.y, bias_sm);
            s[nf][2] = s[nf][2] * 0.125f + mi_term(w1.x, bias_sm);
            s[nf][3] = s[nf][3] * 0.125f + mi_term(w1.y, bias_sm);
        }

        // ---- online softmax
        float t0 = s[0][0], t1 = s[0][2];
#pragma unroll
        for (int nf = 0; nf < 8; nf++) {
            t0 = fmaxf(t0, fmaxf(s[nf][0], s[nf][1]));
            t1 = fmaxf(t1, fmaxf(s[nf][2], s[nf][3]));
        }
        t0 = fmaxf(t0, __shfl_xor_sync(0xffffffffu, t0, 1));
        t0 = fmaxf(t0, __shfl_xor_sync(0xffffffffu, t0, 2));
        t1 = fmaxf(t1, __shfl_xor_sync(0xffffffffu, t1, 1));
        t1 = fmaxf(t1, __shfl_xor_sync(0xffffffffu, t1, 2));
        float nm0 = fmaxf(m0, t0), nm1 = fmaxf(m1, t1);
        float sc0 = __expf(m0 - nm0), sc1 = __expf(m1 - nm1);

        float sum0 = 0.0f, sum1 = 0.0f;
#pragma unroll
        for (int nf = 0; nf < 8; nf++) {
            s[nf][0] = __expf(s[nf][0] - nm0);
            s[nf][1] = __expf(s[nf][1] - nm0);
            s[nf][2] = __expf(s[nf][2] - nm1);
            s[nf][3] = __expf(s[nf][3] - nm1);
            sum0 += s[nf][0] + s[nf][1];
            sum1 += s[nf][2] + s[nf][3];
        }
        sum0 += __shfl_xor_sync(0xffffffffu, sum0, 1);
        sum0 += __shfl_xor_sync(0xffffffffu, sum0, 2);
        sum1 += __shfl_xor_sync(0xffffffffu, sum1, 1);
        sum1 += __shfl_xor_sync(0xffffffffu, sum1, 2);
        l0s = l0s * sc0 + sum0;
        l1s = l1s * sc1 + sum1;
        m0 = nm0; m1 = nm1;
#pragma unroll
        for (int nf = 0; nf < 8; nf++) {
            o[nf][0] *= sc0; o[nf][1] *= sc0;
            o[nf][2] *= sc1; o[nf][3] *= sc1;
        }

        // ---- PV: single fp16
#pragma unroll
        for (int kf = 0; kf < 4; kf++) {
            unsigned phf[4];
            phf[0] = pack2h(s[2 * kf][0],     s[2 * kf][1]);
            phf[1] = pack2h(s[2 * kf][2],     s[2 * kf][3]);
            phf[2] = pack2h(s[2 * kf + 1][0], s[2 * kf + 1][1]);
            phf[3] = pack2h(s[2 * kf + 1][2], s[2 * kf + 1][3]);
            unsigned vrow = kf * 16 + v_row;
#pragma unroll
            for (int nf2 = 0; nf2 < 4; nf2++) {
                unsigned woff = (vrow * PW + nf2 * 8 + v_colw) * 4u;
                unsigned h0, h1, h2, h3;
                ldsm_x4_trans(h0, h1, h2, h3, vh_base + woff);
                mma_f16(o[2 * nf2],     phf[0], phf[1], phf[2], phf[3], h0, h1);
                mma_f16(o[2 * nf2 + 1], phf[0], phf[1], phf[2], phf[3], h2, h3);
            }
        }
    }

    // Epilogue: normalize and write bf16 hi/lo planes
    float inv0 = 1.0f / l0s;
    float inv1 = 1.0f / l1s;
    int r0 = i0 + m;
#pragma unroll
    for (int nf = 0; nf < 8; nf++) {
        int cc = h * HD + nf * 8 + lt * 2;
        size_t idx0 = ((size_t)(b * NN + r0) * DD + cc) >> 1;
        size_t idx1 = ((size_t)(b * NN + r0 + 8) * DD + cc) >> 1;
        unsigned hw, lw;
        split2(o[nf][0] * inv0, o[nf][1] * inv0, hw, lw);
        g_yh[idx0] = hw; g_yl[idx0] = lw;
        split2(o[nf][2] * inv1, o[nf][3] * inv1, hw, lw);
        g_yh[idx1] = hw; g_yl[idx1] = lw;
    }
}

// ---------------------------------------------------------------------------
// Host launch
// ---------------------------------------------------------------------------
extern "C" void kernel_launch(void* const* d_in, const int* in_sizes, int n_in,
                              void* d_out, int out_size) {
    const float* query = (const float*)d_in[0];
    const float* key   = (const float*)d_in[1];
    const float* value = (const float*)d_in[2];
    const float* coords = (const float*)d_in[3];
    const float* Wq = (const float*)d_in[4];
    const float* bq = (const float*)d_in[5];
    const float* Wk = (const float*)d_in[6];
    const float* bk = (const float*)d_in[7];
    const float* Wv = (const float*)d_in[8];
    const float* bv = (const float*)d_in[9];
    const float* Wo = (const float*)d_in[10];
    const float* bo = (const float*)d_in[11];
    const float* bias_table = (const float*)d_in[12];
    float* out = (float*)d_out;

    unsigned *xh, *xl, *wh, *wl, *yh, *yl;
    void *qfh, *kfh, *vfh;
    cudaGetSymbolAddress((void**)&xh, g_xh);
    cudaGetSymbolAddress((void**)&xl, g_xl);
    cudaGetSymbolAddress((void**)&wh, g_wh);
    cudaGetSymbolAddress((void**)&wl, g_wl);
    cudaGetSymbolAddress((void**)&yh, g_yh);
    cudaGetSymbolAddress((void**)&yl, g_yl);
    cudaGetSymbolAddress(&qfh, g_qfh);
    cudaGetSymbolAddress(&kfh, g_kfh);
    cudaGetSymbolAddress(&vfh, g_vfh);

    cudaFuncSetAttribute(attn_kernel, cudaFuncAttributeMaxDynamicSharedMemorySize,
                         (int)SMEM_DYN);
    cudaFuncSetAttribute(gemm_planes_kernel, cudaFuncAttributeMaxDynamicSharedMemorySize,
                         (int)GSMEM);

    init_bins_kernel<<<1, 32>>>();

    // Pre-split activations and weights into bf16 hi/lo planes
    const int XN4 = BB * NN * DD / 4;
    const int WN4 = DD * DD / 4;
    presplit_kernel<<<XN4 / 256, 256>>>(query, xh,          xl,          XN4);
    presplit_kernel<<<XN4 / 256, 256>>>(key,   xh + XZ,     xl + XZ,     XN4);
    presplit_kernel<<<XN4 / 256, 256>>>(value, xh + 2 * XZ, xl + 2 * XZ, XN4);
    presplit_kernel<<<WN4 / 256, 256>>>(Wq, wh,          wl,          WN4);
    presplit_kernel<<<WN4 / 256, 256>>>(Wk, wh + WZ,     wl + WZ,     WN4);
    presplit_kernel<<<WN4 / 256, 256>>>(Wv, wh + 2 * WZ, wl + 2 * WZ, WN4);
    presplit_kernel<<<WN4 / 256, 256>>>(Wo, wh + 3 * WZ, wl + 3 * WZ, WN4);

    // Fused QKV projections -> single-fp16 attn planes
    GemmArgs qa;
    qa.Ah = xh; qa.Al = xl; qa.Wh = wh; qa.Wl = wl;
    qa.b0 = bq; qa.b1 = bk; qa.b2 = bv;
    qa.C16_0 = qfh; qa.C16_1 = kfh; qa.C16_2 = vfh;
    qa.C0 = nullptr;
    gemm_planes_kernel<<<dim3(DD / 128, (BB * NN) / 128, 3), 256, GSMEM>>>(qa, 1);

    precompute_kernel<<<(BB * NN * NN) / 256, 256>>>(coords);
    attn_kernel<<<dim3(NN / 128, BB * HH), 256, SMEM_DYN>>>(bias_table);

    // Output projection (y planes @ Wo planes -> fp32 out)
    GemmArgs oa;
    oa.Ah = yh; oa.Al = yl;
    oa.Wh = wh + 3 * WZ; oa.Wl = wl + 3 * WZ;
    oa.b0 = bo; oa.b1 = bo; oa.b2 = bo;
    oa.C16_0 = nullptr; oa.C16_1 = nullptr; oa.C16_2 = nullptr;
    oa.C0 = out;
    gemm_planes_kernel<<<dim3(DD / 128, (BB * NN) / 128, 1), 256, GSMEM>>>(oa, 0);
}

// round 17
// speedup vs baseline: 6.6710x; 1.1503x over previous
#include <cuda_runtime.h>
#include <cuda_bf16.h>
#include <cuda_fp16.h>
#include <math_constants.h>

// Problem constants
#define BB 4
#define NN 1024
#define DD 512
#define HH 8
#define HD 64
#define NSP 32
#define NTMP 16

#define XZ (BB * NN * DD / 2)   // u32 per fp16 activation plane (1M)
#define WZ (DD * DD / 2)        // u32 per fp16 weight plane (128K)

// Scratch (device globals; no allocations allowed)
__device__ unsigned g_xf[3 * XZ];    // fp16 inputs (query,key,value)
__device__ unsigned g_wfh[4 * WZ];   // fp16 weight hi (Wq,Wk,Wv,Wo)
__device__ unsigned g_wfl[4 * WZ];   // fp16 weight lo
__device__ unsigned g_yf[XZ];        // attention out (fp16)
__device__ unsigned short g_qfh[BB * HH * NN * HD];  // Q fp16 plane (b,h,n,d)
__device__ unsigned short g_kfh[BB * HH * NN * HD];  // K fp16 plane
__device__ unsigned short g_vfh[BB * HH * NN * HD];  // V fp16 plane
__device__ unsigned g_mi[BB * NN * NN];    // packed: fp16(mask) << 16 | idx
__device__ float g_sbins[NSP];

// ---------------------------------------------------------------------------
// mma + pack helpers
// ---------------------------------------------------------------------------
__device__ __forceinline__ void mma_f16(float* d,
                                        unsigned a0, unsigned a1, unsigned a2, unsigned a3,
                                        unsigned b0, unsigned b1) {
    asm volatile(
        "mma.sync.aligned.m16n8k16.row.col.f32.f16.f16.f32 "
        "{%0,%1,%2,%3}, {%4,%5,%6,%7}, {%8,%9}, {%0,%1,%2,%3};\n"
        : "+f"(d[0]), "+f"(d[1]), "+f"(d[2]), "+f"(d[3])
        : "r"(a0), "r"(a1), "r"(a2), "r"(a3), "r"(b0), "r"(b1));
}

__device__ __forceinline__ void split2h(float x0, float x1, unsigned& hi, unsigned& lo) {
    __half2 h = __floats2half2_rn(x0, x1);
    float2 hf = __half22float2(h);
    __half2 l = __floats2half2_rn(x0 - hf.x, x1 - hf.y);
    hi = *(unsigned*)&h;
    lo = *(unsigned*)&l;
}

__device__ __forceinline__ unsigned pack2h(float x0, float x1) {
    __half2 h = __floats2half2_rn(x0, x1);
    return *(unsigned*)&h;
}

__device__ __forceinline__ unsigned smem_u32(const void* p) {
    return (unsigned)__cvta_generic_to_shared(p);
}

__device__ __forceinline__ void cp_async16(unsigned dst, const void* src) {
    asm volatile("cp.async.cg.shared.global [%0], [%1], 16;\n"
                 :: "r"(dst), "l"(src));
}
__device__ __forceinline__ void cp_async_commit() {
    asm volatile("cp.async.commit_group;\n" ::: "memory");
}
__device__ __forceinline__ void cp_async_wait0() {
    asm volatile("cp.async.wait_group 0;\n" ::: "memory");
}

__device__ __forceinline__ void ldsm_x4(unsigned& r0, unsigned& r1,
                                        unsigned& r2, unsigned& r3, unsigned addr) {
    asm volatile(
        "ldmatrix.sync.aligned.m8n8.x4.shared.b16 {%0,%1,%2,%3}, [%4];"
        : "=r"(r0), "=r"(r1), "=r"(r2), "=r"(r3) : "r"(addr));
}

__device__ __forceinline__ void ldsm_x4_trans(unsigned& r0, unsigned& r1,
                                              unsigned& r2, unsigned& r3,
                                              unsigned addr) {
    asm volatile(
        "ldmatrix.sync.aligned.m8n8.x4.trans.shared.b16 {%0,%1,%2,%3}, [%4];"
        : "=r"(r0), "=r"(r1), "=r"(r2), "=r"(r3) : "r"(addr));
}

__device__ __forceinline__ float mi_term(unsigned wv, const float* bias_sm) {
    float mv = __half2float(__ushort_as_half((unsigned short)(wv >> 16)));
    return bias_sm[wv & 0xffffu] + mv;
}

// ---------------------------------------------------------------------------
// init bins + elementwise conversions
// ---------------------------------------------------------------------------
__global__ void init_bins_kernel() {
    int i = threadIdx.x;
    if (i < NSP) {
        double L = log(257.0);
        g_sbins[i] = (float)exp((double)i * (L / 31.0));
    }
}

// fp32 -> single fp16 plane
__global__ void presplit_h_kernel(const float* __restrict__ src,
                                  unsigned* __restrict__ dst, int n4) {
    int i = blockIdx.x * 256 + threadIdx.x;
    if (i < n4) {
        float4 v = ((const float4*)src)[i];
        ((uint2*)dst)[i] = make_uint2(pack2h(v.x, v.y), pack2h(v.z, v.w));
    }
}

// fp32 -> fp16 hi/lo planes
__global__ void presplit_hl_kernel(const float* __restrict__ src,
                                   unsigned* __restrict__ hi,
                                   unsigned* __restrict__ lo, int n4) {
    int i = blockIdx.x * 256 + threadIdx.x;
    if (i < n4) {
        float4 v = ((const float4*)src)[i];
        unsigned h0, l0, h1, l1;
        split2h(v.x, v.y, h0, l0);
        split2h(v.z, v.w, h1, l1);
        ((uint2*)hi)[i] = make_uint2(h0, h1);
        ((uint2*)lo)[i] = make_uint2(l0, l1);
    }
}

// ---------------------------------------------------------------------------
// 2-term fp16 GEMM: C[m,o] = sum_k A[m,k]*(Wh+Wl)[o,k] + bias[o]
// A single fp16 plane; W fp16 hi/lo compensated.
// mode 0: C row-major fp32; mode 1: scatter single-fp16 attn plane
// Tile 128x128, BK=32, 256 threads (8 warps 4x2, warp tile 32x64), 2 CTAs/SM
// ---------------------------------------------------------------------------
#define PWG 20
#define GPLANE (128 * PWG)
#define GSTAGE (3 * GPLANE)              // Af, Wh, Wl
#define GSMEM (2 * GSTAGE * 4)           // 61440 bytes

struct GemmArgs {
    const unsigned* Af;
    const unsigned* Wh; const unsigned* Wl;
    const float* b0; const float* b1; const float* b2;
    void* C16_0; void* C16_1; void* C16_2;
    float* C0;
};

__global__ void __launch_bounds__(256, 2) gemm_planes_kernel(GemmArgs args, int mode) {
    extern __shared__ unsigned gsm[];

    int z = blockIdx.z;
    const unsigned* Af = args.Af + (size_t)z * XZ;
    const unsigned* Wh = args.Wh + (size_t)z * WZ;
    const unsigned* Wl = args.Wl + (size_t)z * WZ;
    const float* bias = (z == 0) ? args.b0 : (z == 1) ? args.b1 : args.b2;
    unsigned* C16 = (unsigned*)((z == 0) ? args.C16_0 : (z == 1) ? args.C16_1 : args.C16_2);

    int tid = threadIdx.x;
    int lane = tid & 31;
    int wid = tid >> 5;
    int warp_m = wid & 3;
    int warp_n = wid >> 2;
    int row0 = blockIdx.y * 128;
    int col0 = blockIdx.x * 128;
    int lg = lane >> 2;
    int lt = lane & 3;

    const unsigned gbase = smem_u32(gsm);
    const int KW = DD / 2;

    const unsigned a_row = lane & 15;
    const unsigned a_colw = (lane >> 4) << 2;
    const unsigned b_row = (lane & 7) + ((lane >> 4) << 3);
    const unsigned b_colw = ((lane >> 3) & 1) << 2;

    auto copyk = [&](int stage, int k0) {
        unsigned sb = gbase + (unsigned)stage * GSTAGE * 4u;
        int ku = k0 >> 1;
#pragma unroll
        for (int c = 0; c < 2; c++) {
            int f = tid + 256 * c;
            int r = f >> 2, c4 = f & 3;
            unsigned doff = (r * PWG + c4 * 4) * 4u;
            size_t ga = (size_t)(row0 + r) * KW + ku + c4 * 4;
            size_t gw = (size_t)(col0 + r) * KW + ku + c4 * 4;
            cp_async16(sb + doff, Af + ga);
            cp_async16(sb + GPLANE * 4 + doff, Wh + gw);
            cp_async16(sb + 2 * GPLANE * 4 + doff, Wl + gw);
        }
    };

    float acc[2][8][4];
#pragma unroll
    for (int mf = 0; mf < 2; mf++)
#pragma unroll
        for (int nf = 0; nf < 8; nf++)
#pragma unroll
            for (int zz = 0; zz < 4; zz++) acc[mf][nf][zz] = 0.0f;

    copyk(0, 0);
    cp_async_commit();

    for (int kt = 0; kt < DD / 32; kt++) {
        int cur = kt & 1;
        cp_async_wait0();
        __syncthreads();
        if (kt + 1 < DD / 32) {
            copyk(cur ^ 1, (kt + 1) * 32);
            cp_async_commit();
        }

        unsigned sb = gbase + (unsigned)cur * GSTAGE * 4u;
        unsigned afb = sb;
        unsigned whb = sb + GPLANE * 4;
        unsigned wlb = sb + 2 * GPLANE * 4;

#pragma unroll
        for (int kf = 0; kf < 2; kf++) {
            unsigned bh[8][2], bl[8][2];
#pragma unroll
            for (int np = 0; np < 4; np++) {
                unsigned woff = ((warp_n * 64 + np * 16 + b_row) * PWG + kf * 8 + b_colw) * 4u;
                ldsm_x4(bh[2 * np][0], bh[2 * np][1], bh[2 * np + 1][0], bh[2 * np + 1][1],
                        whb + woff);
                ldsm_x4(bl[2 * np][0], bl[2 * np][1], bl[2 * np + 1][0], bl[2 * np + 1][1],
                        wlb + woff);
            }
#pragma unroll
            for (int mf = 0; mf < 2; mf++) {
                unsigned aoff = ((warp_m * 32 + mf * 16 + a_row) * PWG + kf * 8 + a_colw) * 4u;
                unsigned af4[4];
                ldsm_x4(af4[0], af4[1], af4[2], af4[3], afb + aoff);
#pragma unroll
                for (int nf = 0; nf < 8; nf++) {
                    mma_f16(acc[mf][nf], af4[0], af4[1], af4[2], af4[3],
                            bh[nf][0], bh[nf][1]);
                    mma_f16(acc[mf][nf], af4[0], af4[1], af4[2], af4[3],
                            bl[nf][0], bl[nf][1]);
                }
            }
        }
    }

    // Epilogue
#pragma unroll
    for (int mf = 0; mf < 2; mf++) {
#pragma unroll
        for (int nf = 0; nf < 8; nf++) {
            int rr = row0 + warp_m * 32 + mf * 16 + lg;
            int cc = col0 + warp_n * 64 + nf * 8 + lt * 2;
            float b0 = bias[cc], b1 = bias[cc + 1];
#pragma unroll
            for (int half = 0; half < 2; half++) {
                int m = rr + half * 8;
                float v0 = acc[mf][nf][half * 2 + 0] + b0;
                float v1 = acc[mf][nf][half * 2 + 1] + b1;
                if (mode == 0) {
                    *(float2*)&args.C0[(size_t)m * DD + cc] = make_float2(v0, v1);
                } else {
                    int b = m >> 10, n = m & (NN - 1);
                    int h = cc >> 6, d = cc & (HD - 1);
                    size_t widx = (((((size_t)b * HH + h) * NN) + n) * HD + d) >> 1;
                    C16[widx] = pack2h(v0, v1);
                }
            }
        }
    }
}

// ---------------------------------------------------------------------------
// Precompute per-pair packed (fp16 mask | u16 idx)
// ---------------------------------------------------------------------------
__global__ void precompute_kernel(const float* __restrict__ coords) {
    int gid = blockIdx.x * 256 + threadIdx.x;
    int b = gid >> 20;
    int rem = gid & ((1 << 20) - 1);
    int i = rem >> 10;
    int j = rem & 1023;

    const float* ci = coords + ((size_t)b * NN + i) * 3;
    const float* cj = coords + ((size_t)b * NN + j) * 3;
    float ti = ci[0], yi = ci[1], xi = ci[2];
    float tj = cj[0], yj = cj[1], xj = cj[2];

    float dy = yi - yj, dx = xi - xj, dt = ti - tj;
    float sp2 = dy * dy + dx * dx;
    float sd = sqrtf(fmaxf(sp2, 0.0f));
    float fd = sqrtf(fmaxf(dt * dt + dy * dy + dx * dx, 0.0f));

    int c = 0;
#pragma unroll
    for (int s = 0; s < NSP; s++) c += (g_sbins[s] < sd) ? 1 : 0;
    int sidx = min(c, NSP - 1);

    int tc = (int)ceilf(dt + 16.0f);
    tc = max(0, min(2 * NTMP, tc));

    float maskval = (sd > 256.0f ? -1000.0f : 0.0f) + expf(-0.1f * fd);
    unsigned short hb = __half_as_ushort(__float2half_rn(maskval));
    g_mi[gid] = ((unsigned)hb << 16) | (unsigned)(sidx + tc * NSP);
}

// ---------------------------------------------------------------------------
// Flash attention: single-fp16 Q,K,V,P. cp.async double-buffered K/V,
// P in registers, packed mask+idx, smem bias. 2 CTAs/SM.
// grid: (N/128, B*H). 256 threads (8 warps); warp w owns q rows w*16..+16
// ---------------------------------------------------------------------------
#define PW 36
#define PLANE (64 * PW)
#define STAGE_WORDS (2 * PLANE)
#define SMEM_DYN (2 * STAGE_WORDS * 4)     // 36864 bytes
#define NBIAS ((2 * NTMP + 1) * NSP)       // 1056

__global__ void __launch_bounds__(256, 2) attn_kernel(const float* __restrict__ bias_table) {
    extern __shared__ unsigned dynsm[];
    __shared__ float bias_sm[NBIAS];

    int bh_ = blockIdx.y;
    int b = bh_ >> 3, h = bh_ & 7;
    int i0 = blockIdx.x * 128;
    int tid = threadIdx.x;
    int lane = tid & 31;
    int w = tid >> 5;
    int lg = lane >> 2;
    int lt = lane & 3;
    int m = w * 16 + lg;

    for (int i = tid; i < NBIAS; i += 256)
        bias_sm[i] = bias_table[i * HH + h];

    const unsigned* kbh = (const unsigned*)g_kfh + (size_t)bh_ * NN * (HD / 2);
    const unsigned* vbh = (const unsigned*)g_vfh + (size_t)bh_ * NN * (HD / 2);
    const unsigned dyn_base = smem_u32(dynsm);

    int cp_row0 = tid >> 3, cp_c4 = tid & 7;
    int cp_row1 = cp_row0 + 32;

    // Q A-fragments (single fp16) from global plane (one-time)
    unsigned qf[4][4];
    {
        const unsigned* qhp = (const unsigned*)g_qfh + ((size_t)bh_ * NN + i0) * (HD / 2);
#pragma unroll
        for (int kf = 0; kf < 4; kf++) {
            int base = m * (HD / 2) + kf * 8 + lt;
            qf[kf][0] = qhp[base];
            qf[kf][1] = qhp[base + 8 * (HD / 2)];
            qf[kf][2] = qhp[base + 4];
            qf[kf][3] = qhp[base + 8 * (HD / 2) + 4];
        }
    }

    float o[8][4];
#pragma unroll
    for (int nf = 0; nf < 8; nf++)
#pragma unroll
        for (int zz = 0; zz < 4; zz++) o[nf][zz] = 0.0f;
    float m0 = -CUDART_INF_F, m1 = -CUDART_INF_F;
    float l0s = 0.0f, l1s = 0.0f;

    const size_t mirow0 = ((size_t)b * NN + (i0 + m)) * NN;
    const size_t mirow1 = mirow0 + 8 * (size_t)NN;

    const unsigned k_row = (lane & 7) + ((lane >> 4) << 3);
    const unsigned k_colw = ((lane >> 3) & 1) << 2;
    const unsigned v_row = lane & 15;
    const unsigned v_colw = (lane >> 4) << 2;

    auto copy_tile = [&](int stage, int j0) {
        unsigned sb = dyn_base + (unsigned)stage * STAGE_WORDS * 4;
        size_t g0 = (size_t)(j0 + cp_row0) * (HD / 2) + cp_c4 * 4;
        size_t g1 = (size_t)(j0 + cp_row1) * (HD / 2) + cp_c4 * 4;
        unsigned d0 = (cp_row0 * PW + cp_c4 * 4) * 4u;
        unsigned d1 = (cp_row1 * PW + cp_c4 * 4) * 4u;
        cp_async16(sb + d0, kbh + g0);
        cp_async16(sb + d1, kbh + g1);
        cp_async16(sb + PLANE * 4 + d0, vbh + g0);
        cp_async16(sb + PLANE * 4 + d1, vbh + g1);
    };

    copy_tile(0, 0);
    cp_async_commit();

    for (int jt = 0; jt < NN / 64; jt++) {
        int cur = jt & 1;
        cp_async_wait0();
        __syncthreads();
        if (jt + 1 < NN / 64) {
            copy_tile(cur ^ 1, (jt + 1) * 64);
            cp_async_commit();
        }

        unsigned sb = dyn_base + (unsigned)cur * STAGE_WORDS * 4;
        unsigned kh_base = sb;
        unsigned vh_base = sb + PLANE * 4;
        int j0 = jt * 64;

        // ---- QK^T: single fp16
        float s[8][4];
#pragma unroll
        for (int nf = 0; nf < 8; nf++)
            s[nf][0] = s[nf][1] = s[nf][2] = s[nf][3] = 0.0f;
#pragma unroll
        for (int kf = 0; kf < 4; kf++) {
#pragma unroll
            for (int np = 0; np < 4; np++) {
                unsigned woff = ((np * 16 + k_row) * PW + kf * 8 + k_colw) * 4u;
                unsigned h0, h1, h2, h3;
                ldsm_x4(h0, h1, h2, h3, kh_base + woff);
                mma_f16(s[2 * np],     qf[kf][0], qf[kf][1], qf[kf][2], qf[kf][3], h0, h1);
                mma_f16(s[2 * np + 1], qf[kf][0], qf[kf][1], qf[kf][2], qf[kf][3], h2, h3);
            }
        }

        // ---- bias + mask
#pragma unroll
        for (int nf = 0; nf < 8; nf++) {
            int jc = j0 + nf * 8 + lt * 2;
            uint2 w0 = *(const uint2*)&g_mi[mirow0 + jc];
            uint2 w1 = *(const uint2*)&g_mi[mirow1 + jc];
            s[nf][0] = s[nf][0] * 0.125f + mi_term(w0.x, bias_sm);
            s[nf][1] = s[nf][1] * 0.125f + mi_term(w0.y, bias_sm);
            s[nf][2] = s[nf][2] * 0.125f + mi_term(w1.x, bias_sm);
            s[nf][3] = s[nf][3] * 0.125f + mi_term(w1.y, bias_sm);
        }

        // ---- online softmax
        float t0 = s[0][0], t1 = s[0][2];
#pragma unroll
        for (int nf = 0; nf < 8; nf++) {
            t0 = fmaxf(t0, fmaxf(s[nf][0], s[nf][1]));
            t1 = fmaxf(t1, fmaxf(s[nf][2], s[nf][3]));
        }
        t0 = fmaxf(t0, __shfl_xor_sync(0xffffffffu, t0, 1));
        t0 = fmaxf(t0, __shfl_xor_sync(0xffffffffu, t0, 2));
        t1 = fmaxf(t1, __shfl_xor_sync(0xffffffffu, t1, 1));
        t1 = fmaxf(t1, __shfl_xor_sync(0xffffffffu, t1, 2));
        float nm0 = fmaxf(m0, t0), nm1 = fmaxf(m1, t1);
        float sc0 = __expf(m0 - nm0), sc1 = __expf(m1 - nm1);

        float sum0 = 0.0f, sum1 = 0.0f;
#pragma unroll
        for (int nf = 0; nf < 8; nf++) {
            s[nf][0] = __expf(s[nf][0] - nm0);
            s[nf][1] = __expf(s[nf][1] - nm0);
            s[nf][2] = __expf(s[nf][2] - nm1);
            s[nf][3] = __expf(s[nf][3] - nm1);
            sum0 += s[nf][0] + s[nf][1];
            sum1 += s[nf][2] + s[nf][3];
        }
        sum0 += __shfl_xor_sync(0xffffffffu, sum0, 1);
        sum0 += __shfl_xor_sync(0xffffffffu, sum0, 2);
        sum1 += __shfl_xor_sync(0xffffffffu, sum1, 1);
        sum1 += __shfl_xor_sync(0xffffffffu, sum1, 2);
        l0s = l0s * sc0 + sum0;
        l1s = l1s * sc1 + sum1;
        m0 = nm0; m1 = nm1;
#pragma unroll
        for (int nf = 0; nf < 8; nf++) {
            o[nf][0] *= sc0; o[nf][1] *= sc0;
            o[nf][2] *= sc1; o[nf][3] *= sc1;
        }

        // ---- PV: single fp16
#pragma unroll
        for (int kf = 0; kf < 4; kf++) {
            unsigned phf[4];
            phf[0] = pack2h(s[2 * kf][0],     s[2 * kf][1]);
            phf[1] = pack2h(s[2 * kf][2],     s[2 * kf][3]);
            phf[2] = pack2h(s[2 * kf + 1][0], s[2 * kf + 1][1]);
            phf[3] = pack2h(s[2 * kf + 1][2], s[2 * kf + 1][3]);
            unsigned vrow = kf * 16 + v_row;
#pragma unroll
            for (int nf2 = 0; nf2 < 4; nf2++) {
                unsigned woff = (vrow * PW + nf2 * 8 + v_colw) * 4u;
                unsigned h0, h1, h2, h3;
                ldsm_x4_trans(h0, h1, h2, h3, vh_base + woff);
                mma_f16(o[2 * nf2],     phf[0], phf[1], phf[2], phf[3], h0, h1);
                mma_f16(o[2 * nf2 + 1], phf[0], phf[1], phf[2], phf[3], h2, h3);
            }
        }
    }

    // Epilogue: normalize and write single fp16 plane
    float inv0 = 1.0f / l0s;
    float inv1 = 1.0f / l1s;
    int r0 = i0 + m;
#pragma unroll
    for (int nf = 0; nf < 8; nf++) {
        int cc = h * HD + nf * 8 + lt * 2;
        size_t idx0 = ((size_t)(b * NN + r0) * DD + cc) >> 1;
        size_t idx1 = ((size_t)(b * NN + r0 + 8) * DD + cc) >> 1;
        g_yf[idx0] = pack2h(o[nf][0] * inv0, o[nf][1] * inv0);
        g_yf[idx1] = pack2h(o[nf][2] * inv1, o[nf][3] * inv1);
    }
}

// ---------------------------------------------------------------------------
// Host launch
// ---------------------------------------------------------------------------
extern "C" void kernel_launch(void* const* d_in, const int* in_sizes, int n_in,
                              void* d_out, int out_size) {
    const float* query = (const float*)d_in[0];
    const float* key   = (const float*)d_in[1];
    const float* value = (const float*)d_in[2];
    const float* coords = (const float*)d_in[3];
    const float* Wq = (const float*)d_in[4];
    const float* bq = (const float*)d_in[5];
    const float* Wk = (const float*)d_in[6];
    const float* bk = (const float*)d_in[7];
    const float* Wv = (const float*)d_in[8];
    const float* bv = (const float*)d_in[9];
    const float* Wo = (const float*)d_in[10];
    const float* bo = (const float*)d_in[11];
    const float* bias_table = (const float*)d_in[12];
    float* out = (float*)d_out;

    unsigned *xf, *wfh, *wfl, *yf;
    void *qfh, *kfh, *vfh;
    cudaGetSymbolAddress((void**)&xf, g_xf);
    cudaGetSymbolAddress((void**)&wfh, g_wfh);
    cudaGetSymbolAddress((void**)&wfl, g_wfl);
    cudaGetSymbolAddress((void**)&yf, g_yf);
    cudaGetSymbolAddress(&qfh, g_qfh);
    cudaGetSymbolAddress(&kfh, g_kfh);
    cudaGetSymbolAddress(&vfh, g_vfh);

    cudaFuncSetAttribute(attn_kernel, cudaFuncAttributeMaxDynamicSharedMemorySize,
                         (int)SMEM_DYN);
    cudaFuncSetAttribute(gemm_planes_kernel, cudaFuncAttributeMaxDynamicSharedMemorySize,
                         (int)GSMEM);

    init_bins_kernel<<<1, 32>>>();

    // Convert activations -> single fp16; weights -> fp16 hi/lo
    const int XN4 = BB * NN * DD / 4;
    const int WN4 = DD * DD / 4;
    presplit_h_kernel<<<XN4 / 256, 256>>>(query, xf,          XN4);
    presplit_h_kernel<<<XN4 / 256, 256>>>(key,   xf + XZ,     XN4);
    presplit_h_kernel<<<XN4 / 256, 256>>>(value, xf + 2 * XZ, XN4);
    presplit_hl_kernel<<<WN4 / 256, 256>>>(Wq, wfh,          wfl,          WN4);
    presplit_hl_kernel<<<WN4 / 256, 256>>>(Wk, wfh + WZ,     wfl + WZ,     WN4);
    presplit_hl_kernel<<<WN4 / 256, 256>>>(Wv, wfh + 2 * WZ, wfl + 2 * WZ, WN4);
    presplit_hl_kernel<<<WN4 / 256, 256>>>(Wo, wfh + 3 * WZ, wfl + 3 * WZ, WN4);

    // Fused QKV projections -> single-fp16 attn planes
    GemmArgs qa;
    qa.Af = xf; qa.Wh = wfh; qa.Wl = wfl;
    qa.b0 = bq; qa.b1 = bk; qa.b2 = bv;
    qa.C16_0 = qfh; qa.C16_1 = kfh; qa.C16_2 = vfh;
    qa.C0 = nullptr;
    gemm_planes_kernel<<<dim3(DD / 128, (BB * NN) / 128, 3), 256, GSMEM>>>(qa, 1);

    precompute_kernel<<<(BB * NN * NN) / 256, 256>>>(coords);
    attn_kernel<<<dim3(NN / 128, BB * HH), 256, SMEM_DYN>>>(bias_table);

    // Output projection (y fp16 @ Wo hi/lo -> fp32 out)
    GemmArgs oa;
    oa.Af = yf;
    oa.Wh = wfh + 3 * WZ; oa.Wl = wfl + 3 * WZ;
    oa.b0 = bo; oa.b1 = bo; oa.b2 = bo;
    oa.C16_0 = nullptr; oa.C16_1 = nullptr; oa.C16_2 = nullptr;
    oa.C0 = out;
    gemm_planes_kernel<<<dim3(DD / 128, (BB * NN) / 128, 1), 256, GSMEM>>>(oa, 0);
}